// round 2
// baseline (speedup 1.0000x reference)
#include <cuda_runtime.h>
#include <math.h>

#define BB 4
#define TT 2048
#define DD 768
#define NH 12
#define HD 64
#define WIN 64
#define TD3 (3*DD)

// scratch (device globals: allocation-free rule)
__device__ float g_qkv[(size_t)BB*TT*TD3];   // [B,T,3D]  ~75.5 MB
__device__ float g_attn[(size_t)BB*TT*DD];   // [B,T,D]   ~25 MB

typedef unsigned long long u64;

__device__ __forceinline__ u64 pk2(float lo, float hi){
    u64 r; asm("mov.b64 %0,{%1,%2};" : "=l"(r) : "f"(lo), "f"(hi)); return r;
}
__device__ __forceinline__ u64 fma2(u64 a, u64 b, u64 c){
    u64 d; asm("fma.rn.f32x2 %0,%1,%2,%3;" : "=l"(d) : "l"(a), "l"(b), "l"(c)); return d;
}
__device__ __forceinline__ float2 up2(u64 v){
    float2 f; asm("mov.b64 {%0,%1},%2;" : "=f"(f.x), "=f"(f.y) : "l"(v)); return f;
}

// ---------------------------------------------------------------------------
// GEMM: C[m,n] = sum_k A[m,k] * W[n,k]   (both K-major, "NT")
// M%128==0, N%128==0, K%16==0. 128x128 tile, 256 thr, 8x8/thread via f32x2.
// ---------------------------------------------------------------------------
__global__ void __launch_bounds__(256, 2)
gemm_nt(const float* __restrict__ A, const float* __restrict__ W,
        float* __restrict__ C, int M, int N, int K)
{
    __shared__ __align__(16) float As[16][132];  // [k][m]
    __shared__ __align__(16) float Bs[16][132];  // [k][n]

    const int tid = threadIdx.x;
    const int bm = blockIdx.y * 128;
    const int bn = blockIdx.x * 128;
    const int tx = tid & 15;     // 16 n-groups of 8
    const int ty = tid >> 4;     // 16 m-groups of 8

    u64 acc[8][4];
#pragma unroll
    for (int i = 0; i < 8; i++)
#pragma unroll
        for (int j = 0; j < 4; j++) acc[i][j] = 0ull;

    const int lrow = tid >> 2;          // 0..63
    const int lk4  = (tid & 3) * 4;     // 0,4,8,12
    const float* Ap = A + (size_t)(bm + lrow) * K + lk4;
    const float* Wp = W + (size_t)(bn + lrow) * K + lk4;
    const size_t rstep = (size_t)64 * K;

    for (int k0 = 0; k0 < K; k0 += 16) {
        float4 va0 = *(const float4*)(Ap + k0);
        float4 va1 = *(const float4*)(Ap + k0 + rstep);
        float4 vb0 = *(const float4*)(Wp + k0);
        float4 vb1 = *(const float4*)(Wp + k0 + rstep);

        As[lk4+0][lrow]    = va0.x; As[lk4+1][lrow]    = va0.y;
        As[lk4+2][lrow]    = va0.z; As[lk4+3][lrow]    = va0.w;
        As[lk4+0][lrow+64] = va1.x; As[lk4+1][lrow+64] = va1.y;
        As[lk4+2][lrow+64] = va1.z; As[lk4+3][lrow+64] = va1.w;
        Bs[lk4+0][lrow]    = vb0.x; Bs[lk4+1][lrow]    = vb0.y;
        Bs[lk4+2][lrow]    = vb0.z; Bs[lk4+3][lrow]    = vb0.w;
        Bs[lk4+0][lrow+64] = vb1.x; Bs[lk4+1][lrow+64] = vb1.y;
        Bs[lk4+2][lrow+64] = vb1.z; Bs[lk4+3][lrow+64] = vb1.w;
        __syncthreads();

#pragma unroll
        for (int k = 0; k < 16; k++) {
            float4 a0 = *(const float4*)&As[k][ty*8];
            float4 a1 = *(const float4*)&As[k][ty*8+4];
            ulonglong2 b01 = *(const ulonglong2*)&Bs[k][tx*8];
            ulonglong2 b23 = *(const ulonglong2*)&Bs[k][tx*8+4];
            u64 bp[4] = { b01.x, b01.y, b23.x, b23.y };
            float aa[8] = { a0.x, a0.y, a0.z, a0.w, a1.x, a1.y, a1.z, a1.w };
#pragma unroll
            for (int i = 0; i < 8; i++) {
                u64 ad = pk2(aa[i], aa[i]);
#pragma unroll
                for (int j = 0; j < 4; j++)
                    acc[i][j] = fma2(ad, bp[j], acc[i][j]);
            }
        }
        __syncthreads();
    }

#pragma unroll
    for (int i = 0; i < 8; i++) {
        float* Cp = C + (size_t)(bm + ty*8 + i) * N + bn + tx*8;
        float2 p0 = up2(acc[i][0]), p1 = up2(acc[i][1]);
        float2 p2 = up2(acc[i][2]), p3 = up2(acc[i][3]);
        *(float4*)Cp       = make_float4(p0.x, p0.y, p1.x, p1.y);
        *(float4*)(Cp + 4) = make_float4(p2.x, p2.y, p3.x, p3.y);
    }
}

// ---------------------------------------------------------------------------
// RoPE in-place on q and k parts of g_qkv. One warp per (b,t,head).
// out[2j]   = x[j]*cos - x[j+32]*sin
// out[2j+1] = x[j]*sin + x[j+32]*cos,  ang = t * 10000^(-j/32)
// ---------------------------------------------------------------------------
__global__ void rope_kernel(float* __restrict__ qkv)
{
    int gw   = (blockIdx.x * blockDim.x + threadIdx.x) >> 5;
    int lane = threadIdx.x & 31;
    if (gw >= BB * TT * NH) return;
    int h = gw % NH;
    int t = (gw / NH) % TT;
    int b = gw / (NH * TT);

    float inv = (float)pow(10000.0, -(double)lane / 32.0);
    float ang = (float)t * inv;
    float sn, cs;
    sincosf(ang, &sn, &cs);

    float* base = qkv + (size_t)(b * TT + t) * TD3 + h * HD;
    // q part (offset 0) and k part (offset DD)
    float qre = base[lane],        qim = base[lane + 32];
    float kre = base[DD + lane],   kim = base[DD + lane + 32];
    __syncwarp();
    base[2*lane]          = qre * cs - qim * sn;
    base[2*lane + 1]      = qre * sn + qim * cs;
    base[DD + 2*lane]     = kre * cs - kim * sn;
    base[DD + 2*lane + 1] = kre * sn + kim * cs;
}

// ---------------------------------------------------------------------------
// Sliding-window attention. One CTA per (64-query tile, head, batch).
// Keys in [q0-64, q0+127] (<=192). smem tiles, shuffle softmax.
// ---------------------------------------------------------------------------
#define ATTN_SMEM_FLOATS (64*68 + 64*200 + 192*68 + 64*200 + 64 + 192)
#define ATTN_SMEM_BYTES  (ATTN_SMEM_FLOATS * 4)

__global__ void __launch_bounds__(256, 1)
attn_kernel(const float* __restrict__ qkv, const int* __restrict__ amask,
            float* __restrict__ out)
{
    extern __shared__ __align__(16) float sm[];
    float* Qt = sm;                    // [64][68]  d-major: Qt[d][q]
    float* Kt = Qt + 64*68;            // [64][200] d-major: Kt[d][k]
    float* Vs = Kt + 64*200;           // [192][68] k-major: Vs[k][d]
    float* Ps = Vs + 192*68;           // [64][200] Ps[q][k] (unnormalized)
    float* Rs = Ps + 64*200;           // [64] row sums
    int*   Ms = (int*)(Rs + 64);       // [192] key pad mask

    const int tid = threadIdx.x;
    const int qb = blockIdx.x, h = blockIdx.y, b = blockIdx.z;
    const int q0 = qb * 64;
    const int ks = max(0, q0 - WIN);
    const int ke = min(TT, q0 + 64 + WIN);
    const int klen = ke - ks;
    const float* qbase = qkv + (size_t)b * TT * TD3;

    // Q transposed: Qt[d][q]
#pragma unroll
    for (int it = 0; it < 4; it++) {
        int idx = tid + it * 256;
        int d4 = idx >> 6, row = idx & 63;
        float4 v = *(const float4*)(qbase + (size_t)(q0+row)*TD3 + h*HD + d4*4);
        Qt[(d4*4+0)*68 + row] = v.x; Qt[(d4*4+1)*68 + row] = v.y;
        Qt[(d4*4+2)*68 + row] = v.z; Qt[(d4*4+3)*68 + row] = v.w;
    }
    // K transposed: Kt[d][k]
#pragma unroll
    for (int it = 0; it < 12; it++) {
        int idx = tid + it * 256;
        int d4 = idx / 192, kk = idx % 192;
        if (kk < klen) {
            float4 v = *(const float4*)(qbase + (size_t)(ks+kk)*TD3 + DD + h*HD + d4*4);
            Kt[(d4*4+0)*200 + kk] = v.x; Kt[(d4*4+1)*200 + kk] = v.y;
            Kt[(d4*4+2)*200 + kk] = v.z; Kt[(d4*4+3)*200 + kk] = v.w;
        }
    }
    // V direct: Vs[k][d]
#pragma unroll
    for (int it = 0; it < 12; it++) {
        int idx = tid + it * 256;
        int kk = idx >> 4, d4 = idx & 15;
        if (kk < klen) {
            float4 v = *(const float4*)(qbase + (size_t)(ks+kk)*TD3 + 2*DD + h*HD + d4*4);
            *(float4*)&Vs[kk*68 + d4*4] = v;
        }
    }
    if (tid < 192) Ms[tid] = (tid < klen) ? amask[b*TT + ks + tid] : 0;
    __syncthreads();

    // ---- scores: each thread 4q x 12k ----
    const int tx = tid & 15;   // k-group
    const int ty = tid >> 4;   // q-group
    float s[4][12];
#pragma unroll
    for (int qi = 0; qi < 4; qi++)
#pragma unroll
        for (int ki = 0; ki < 12; ki++) s[qi][ki] = 0.f;

    for (int d = 0; d < 64; d++) {
        float4 aq = *(const float4*)&Qt[d*68 + ty*4];
        float4 b0 = *(const float4*)&Kt[d*200 + tx*12];
        float4 b1 = *(const float4*)&Kt[d*200 + tx*12 + 4];
        float4 b2 = *(const float4*)&Kt[d*200 + tx*12 + 8];
        float aa[4] = { aq.x, aq.y, aq.z, aq.w };
        float bk[12] = { b0.x,b0.y,b0.z,b0.w, b1.x,b1.y,b1.z,b1.w, b2.x,b2.y,b2.z,b2.w };
#pragma unroll
        for (int qi = 0; qi < 4; qi++)
#pragma unroll
            for (int ki = 0; ki < 12; ki++)
                s[qi][ki] += aa[qi] * bk[ki];
    }

    // ---- mask + softmax (shuffle reduce across the 16 tx lanes) ----
    const float scale = 0.125f;  // 1/sqrt(64)
#pragma unroll
    for (int qi = 0; qi < 4; qi++) {
        int qg = q0 + ty*4 + qi;
        bool ok[12];
        float mx = -1e30f;
#pragma unroll
        for (int ki = 0; ki < 12; ki++) {
            int kk = tx*12 + ki;
            int kg = ks + kk;
            ok[ki] = (kk < klen) && (abs(qg - kg) <= WIN) && (Ms[kk] != 0);
            float sv = s[qi][ki] * scale;
            s[qi][ki] = sv;
            if (ok[ki]) mx = fmaxf(mx, sv);
        }
#pragma unroll
        for (int off = 8; off; off >>= 1)
            mx = fmaxf(mx, __shfl_xor_sync(0xffffffffu, mx, off));
        float sum = 0.f;
#pragma unroll
        for (int ki = 0; ki < 12; ki++) {
            float p = ok[ki] ? __expf(s[qi][ki] - mx) : 0.f;
            s[qi][ki] = p;
            sum += p;
        }
#pragma unroll
        for (int off = 8; off; off >>= 1)
            sum += __shfl_xor_sync(0xffffffffu, sum, off);
#pragma unroll
        for (int ki = 0; ki < 12; ki++)
            Ps[(ty*4+qi)*200 + tx*12 + ki] = s[qi][ki];
        if (tx == 0) Rs[ty*4 + qi] = sum;
    }
    __syncthreads();

    // ---- PV: each thread 4q x 4d ----
    const int tx2 = tid & 15;   // d-group of 4
    const int ty2 = tid >> 4;   // q-group of 4
    float o[4][4];
#pragma unroll
    for (int qi = 0; qi < 4; qi++)
#pragma unroll
        for (int di = 0; di < 4; di++) o[qi][di] = 0.f;

    for (int k = 0; k < klen; k++) {
        float4 vv = *(const float4*)&Vs[k*68 + tx2*4];
        float v4[4] = { vv.x, vv.y, vv.z, vv.w };
        float pq[4];
#pragma unroll
        for (int qi = 0; qi < 4; qi++) pq[qi] = Ps[(ty2*4+qi)*200 + k];
#pragma unroll
        for (int qi = 0; qi < 4; qi++)
#pragma unroll
            for (int di = 0; di < 4; di++)
                o[qi][di] += pq[qi] * v4[di];
    }
#pragma unroll
    for (int qi = 0; qi < 4; qi++) {
        float r = 1.f / fmaxf(Rs[ty2*4 + qi], 1e-30f);
        float4 ov = make_float4(o[qi][0]*r, o[qi][1]*r, o[qi][2]*r, o[qi][3]*r);
        *(float4*)&out[(size_t)(b*TT + q0 + ty2*4 + qi)*DD + h*HD + tx2*4] = ov;
    }
}

// ---------------------------------------------------------------------------
extern "C" void kernel_launch(void* const* d_in, const int* in_sizes, int n_in,
                              void* d_out, int out_size)
{
    const float* hs   = (const float*)d_in[0];
    const int*   am   = (const int*)d_in[1];
    const float* Wqkv = (const float*)d_in[2];
    const float* Wo   = (const float*)d_in[3];
    float* out = (float*)d_out;

    void* p1; cudaGetSymbolAddress(&p1, g_qkv);
    void* p2; cudaGetSymbolAddress(&p2, g_attn);
    float* qkv  = (float*)p1;
    float* attn = (float*)p2;

    cudaFuncSetAttribute(attn_kernel,
                         cudaFuncAttributeMaxDynamicSharedMemorySize,
                         ATTN_SMEM_BYTES);

    // 1) QKV projection: [8192,768] x [2304,768]^T
    dim3 g1(TD3/128, (BB*TT)/128);
    gemm_nt<<<g1, 256>>>(hs, Wqkv, qkv, BB*TT, TD3, DD);

    // 2) RoPE on q,k in place
    rope_kernel<<<(BB*TT*NH*32)/256, 256>>>(qkv);

    // 3) Sliding-window attention
    dim3 ga(TT/64, NH, BB);
    attn_kernel<<<ga, 256, ATTN_SMEM_BYTES>>>(qkv, am, attn);

    // 4) Output projection: [8192,768] x [768,768]^T
    dim3 g2(DD/128, (BB*TT)/128);
    gemm_nt<<<g2, 256>>>(attn, Wo, out, BB*TT, DD, DD);
}

// round 4
// speedup vs baseline: 1.3987x; 1.3987x over previous
#include <cuda_runtime.h>
#include <cuda_bf16.h>
#include <math.h>
#include <stdint.h>

#define BB 4
#define TT 2048
#define DD 768
#define NH 12
#define HD 64
#define WIN 64
#define TD3 (3*DD)
#define K2 (3*DD)          // expanded K (hi|lo|hi) = 2304 bf16
#define KC 32              // k per pipeline chunk
#define NC (K2/KC)         // 72 chunks
#define PS 4               // pipeline stages
#define LDT 40             // padded smem row (bf16 elems) -> 80 bytes
#define TILE_BYTES (128*LDT*2)          // 10240 per operand tile
#define STAGE_BYTES (2*TILE_BYTES)      // 20480
#define GEMM_SMEM (PS*STAGE_BYTES)      // 81920

// ---------------- scratch (device globals: allocation-free rule) -----------
__device__ float g_qkv[(size_t)BB*TT*TD3];            // [B,T,3D] fp32
__device__ float g_attn[(size_t)BB*TT*DD];            // [B,T,D]  fp32
__device__ __nv_bfloat16 g_hsx [(size_t)BB*TT*K2];    // hidden expanded
__device__ __nv_bfloat16 g_attnx[(size_t)BB*TT*K2];   // attn-out expanded
__device__ __nv_bfloat16 g_wqkvx[(size_t)TD3*K2];     // Wqkv expanded
__device__ __nv_bfloat16 g_wox [(size_t)DD*K2];       // Wo expanded

// ---------------- PTX helpers (baseline ISA only — no tcgen05) -------------
__device__ __forceinline__ uint32_t smem_u32(const void* p){
    uint32_t a;
    asm("{ .reg .u64 t; cvta.to.shared.u64 t, %1; cvt.u32.u64 %0, t; }"
        : "=r"(a) : "l"(p));
    return a;
}
__device__ __forceinline__ void cp16(uint32_t d, const void* s){
    asm volatile("cp.async.cg.shared.global [%0], [%1], 16;"
                 :: "r"(d), "l"(s) : "memory");
}
__device__ __forceinline__ void cp_commit(){
    asm volatile("cp.async.commit_group;" ::: "memory");
}
template<int N>
__device__ __forceinline__ void cp_wait(){
    asm volatile("cp.async.wait_group %0;" :: "n"(N) : "memory");
}
__device__ __forceinline__ void ldsm_x4(uint32_t &r0,uint32_t &r1,uint32_t &r2,uint32_t &r3,
                                        uint32_t addr){
    asm volatile("ldmatrix.sync.aligned.m8n8.x4.shared.b16 {%0,%1,%2,%3}, [%4];"
                 : "=r"(r0),"=r"(r1),"=r"(r2),"=r"(r3) : "r"(addr));
}
__device__ __forceinline__ void ldsm_x2(uint32_t &r0,uint32_t &r1, uint32_t addr){
    asm volatile("ldmatrix.sync.aligned.m8n8.x2.shared.b16 {%0,%1}, [%2];"
                 : "=r"(r0),"=r"(r1) : "r"(addr));
}
__device__ __forceinline__ void mma16816(float* d, const uint32_t* a, const uint32_t* b){
    asm volatile("mma.sync.aligned.m16n8k16.row.col.f32.bf16.bf16.f32 "
        "{%0,%1,%2,%3}, {%4,%5,%6,%7}, {%8,%9}, {%0,%1,%2,%3};"
        : "+f"(d[0]),"+f"(d[1]),"+f"(d[2]),"+f"(d[3])
        : "r"(a[0]),"r"(a[1]),"r"(a[2]),"r"(a[3]), "r"(b[0]),"r"(b[1]));
}

// ---------------------------------------------------------------------------
// fp32 -> bf16 split expansion.
// amode=1 (A operand): [hi | lo | hi]   amode=0 (B operand): [hi | hi | lo]
// ---------------------------------------------------------------------------
__global__ void expand_kernel(const float* __restrict__ src,
                              __nv_bfloat16* __restrict__ dst,
                              int rows, int amode)
{
    const int q = DD / 4;  // 192
    int idx = blockIdx.x * blockDim.x + threadIdx.x;
    if (idx >= rows * q) return;
    int row = idx / q;
    int c = (idx - row * q) * 4;

    float4 v = *(const float4*)(src + (size_t)row * DD + c);
    __nv_bfloat16 h0 = __float2bfloat16_rn(v.x);
    __nv_bfloat16 h1 = __float2bfloat16_rn(v.y);
    __nv_bfloat16 h2 = __float2bfloat16_rn(v.z);
    __nv_bfloat16 h3 = __float2bfloat16_rn(v.w);
    __nv_bfloat16 l0 = __float2bfloat16_rn(v.x - __bfloat162float(h0));
    __nv_bfloat16 l1 = __float2bfloat16_rn(v.y - __bfloat162float(h1));
    __nv_bfloat16 l2 = __float2bfloat16_rn(v.z - __bfloat162float(h2));
    __nv_bfloat16 l3 = __float2bfloat16_rn(v.w - __bfloat162float(h3));

    uint2 hu = make_uint2(
        (uint32_t)__bfloat16_as_ushort(h0) | ((uint32_t)__bfloat16_as_ushort(h1) << 16),
        (uint32_t)__bfloat16_as_ushort(h2) | ((uint32_t)__bfloat16_as_ushort(h3) << 16));
    uint2 lu = make_uint2(
        (uint32_t)__bfloat16_as_ushort(l0) | ((uint32_t)__bfloat16_as_ushort(l1) << 16),
        (uint32_t)__bfloat16_as_ushort(l2) | ((uint32_t)__bfloat16_as_ushort(l3) << 16));

    __nv_bfloat16* b = dst + (size_t)row * K2 + c;
    *(uint2*)(b)           = hu;
    *(uint2*)(b + DD)      = amode ? lu : hu;
    *(uint2*)(b + 2 * DD)  = amode ? hu : lu;
}

// ---------------------------------------------------------------------------
// HMMA GEMM: C[m,n] = sum_k A2[m,k]*B2[n,k]  (both K-major), K=K2.
// 128x128 CTA tile, 256 thr (8 warps, 2x4), warp tile 64x32.
// 4-stage cp.async pipeline, mma.sync.m16n8k16 bf16->fp32.
// ---------------------------------------------------------------------------
__global__ void __launch_bounds__(256, 2)
gemm_mma(const __nv_bfloat16* __restrict__ A2,
         const __nv_bfloat16* __restrict__ B2,
         float* __restrict__ C, int N)
{
    extern __shared__ __align__(16) char smem[];
    const uint32_t sb = smem_u32(smem);
    const int tid  = threadIdx.x;
    const int lane = tid & 31;
    const int warp = tid >> 5;
    const int bm = blockIdx.y * 128;
    const int bn = blockIdx.x * 128;
    const int wm = warp & 1;     // 2 m-blocks of 64
    const int wn = warp >> 1;    // 4 n-blocks of 32

    // ---------------- loader per-thread mapping ----------------------------
    // A tile: 512 x cp16 (128 rows x 4 segs of 16B); thread does idx=tid, tid+256.
    // B tile: same, offset TILE_BYTES.
    const __nv_bfloat16* asrc[2];
    const __nv_bfloat16* bsrc[2];
    uint32_t adst[2], bdst[2];
#pragma unroll
    for (int h = 0; h < 2; h++) {
        int idx = tid + h * 256;
        int row = idx >> 2, seg = idx & 3;
        asrc[h] = A2 + (size_t)(bm + row) * K2 + seg * 8;
        bsrc[h] = B2 + (size_t)(bn + row) * K2 + seg * 8;
        adst[h] = (uint32_t)(row * (LDT*2) + seg * 16);
        bdst[h] = adst[h] + TILE_BYTES;
    }

    // prologue: stages 0..PS-2
#pragma unroll
    for (int s = 0; s < PS - 1; s++) {
        uint32_t st = sb + s * STAGE_BYTES;
#pragma unroll
        for (int h = 0; h < 2; h++) {
            cp16(st + adst[h], asrc[h] + s * KC);
            cp16(st + bdst[h], bsrc[h] + s * KC);
        }
        cp_commit();
    }

    float acc[4][4][4];
#pragma unroll
    for (int mi = 0; mi < 4; mi++)
#pragma unroll
        for (int ni = 0; ni < 4; ni++)
#pragma unroll
            for (int r = 0; r < 4; r++) acc[mi][ni][r] = 0.f;

    // fragment smem addresses (stage-relative)
    const uint32_t a_row = (uint32_t)(wm * 64 + (lane & 15));
    const uint32_t a_colb = (uint32_t)((lane >> 4) * 16);          // bytes
    const uint32_t b_row = (uint32_t)(wn * 32 + (lane & 7));
    const uint32_t b_colb = (uint32_t)(((lane >> 3) & 1) * 16);    // bytes

    for (int i = 0; i < NC; i++) {
        cp_wait<PS - 2>();
        __syncthreads();

        int nc = i + PS - 1;
        if (nc < NC) {
            uint32_t st = sb + (nc & (PS - 1)) * STAGE_BYTES;
#pragma unroll
            for (int h = 0; h < 2; h++) {
                cp16(st + adst[h], asrc[h] + nc * KC);
                cp16(st + bdst[h], bsrc[h] + nc * KC);
            }
        }
        cp_commit();

        uint32_t st = sb + (i & (PS - 1)) * STAGE_BYTES;
#pragma unroll
        for (int ks = 0; ks < 2; ks++) {
            uint32_t a[4][4], b[4][2];
#pragma unroll
            for (int mi = 0; mi < 4; mi++) {
                uint32_t addr = st + (a_row + mi * 16) * (LDT*2) + ks * 32 + a_colb;
                ldsm_x4(a[mi][0], a[mi][1], a[mi][2], a[mi][3], addr);
            }
#pragma unroll
            for (int ni = 0; ni < 4; ni++) {
                uint32_t addr = st + TILE_BYTES + (b_row + ni * 8) * (LDT*2)
                              + ks * 32 + b_colb;
                ldsm_x2(b[ni][0], b[ni][1], addr);
            }
#pragma unroll
            for (int mi = 0; mi < 4; mi++)
#pragma unroll
                for (int ni = 0; ni < 4; ni++)
                    mma16816(acc[mi][ni], a[mi], b[ni]);
        }
    }

    // ---------------- epilogue --------------------------------------------
    const int g = lane >> 2, t = lane & 3;
#pragma unroll
    for (int mi = 0; mi < 4; mi++) {
        int m0 = bm + wm * 64 + mi * 16 + g;
#pragma unroll
        for (int ni = 0; ni < 4; ni++) {
            int n0 = bn + wn * 32 + ni * 8 + 2 * t;
            *(float2*)&C[(size_t)m0 * N + n0] =
                make_float2(acc[mi][ni][0], acc[mi][ni][1]);
            *(float2*)&C[(size_t)(m0 + 8) * N + n0] =
                make_float2(acc[mi][ni][2], acc[mi][ni][3]);
        }
    }
}

// ---------------------------------------------------------------------------
// RoPE in-place on q and k parts of g_qkv. One warp per (b,t,head).
// ---------------------------------------------------------------------------
__global__ void rope_kernel(float* __restrict__ qkv)
{
    int gw   = (blockIdx.x * blockDim.x + threadIdx.x) >> 5;
    int lane = threadIdx.x & 31;
    if (gw >= BB * TT * NH) return;
    int h = gw % NH;
    int t = (gw / NH) % TT;
    int b = gw / (NH * TT);

    float inv = (float)pow(10000.0, -(double)lane / 32.0);
    float ang = (float)t * inv;
    float sn, cs;
    sincosf(ang, &sn, &cs);

    float* base = qkv + (size_t)(b * TT + t) * TD3 + h * HD;
    float qre = base[lane],        qim = base[lane + 32];
    float kre = base[DD + lane],   kim = base[DD + lane + 32];
    __syncwarp();
    base[2*lane]          = qre * cs - qim * sn;
    base[2*lane + 1]      = qre * sn + qim * cs;
    base[DD + 2*lane]     = kre * cs - kim * sn;
    base[DD + 2*lane + 1] = kre * sn + kim * cs;
}

// ---------------------------------------------------------------------------
// Sliding-window attention (unchanged).
// ---------------------------------------------------------------------------
#define ATTN_SMEM_FLOATS (64*68 + 64*200 + 192*68 + 64*200 + 64 + 192)
#define ATTN_SMEM_BYTES  (ATTN_SMEM_FLOATS * 4)

__global__ void __launch_bounds__(256, 1)
attn_kernel(const float* __restrict__ qkv, const int* __restrict__ amask,
            float* __restrict__ out)
{
    extern __shared__ __align__(16) float sm[];
    float* Qt = sm;                    // [64][68]
    float* Kt = Qt + 64*68;            // [64][200]
    float* Vs = Kt + 64*200;           // [192][68]
    float* Ps = Vs + 192*68;           // [64][200]
    float* Rs = Ps + 64*200;           // [64]
    int*   Ms = (int*)(Rs + 64);       // [192]

    const int tid = threadIdx.x;
    const int qb = blockIdx.x, h = blockIdx.y, b = blockIdx.z;
    const int q0 = qb * 64;
    const int ks = max(0, q0 - WIN);
    const int ke = min(TT, q0 + 64 + WIN);
    const int klen = ke - ks;
    const float* qbase = qkv + (size_t)b * TT * TD3;

#pragma unroll
    for (int it = 0; it < 4; it++) {
        int idx = tid + it * 256;
        int d4 = idx >> 6, row = idx & 63;
        float4 v = *(const float4*)(qbase + (size_t)(q0+row)*TD3 + h*HD + d4*4);
        Qt[(d4*4+0)*68 + row] = v.x; Qt[(d4*4+1)*68 + row] = v.y;
        Qt[(d4*4+2)*68 + row] = v.z; Qt[(d4*4+3)*68 + row] = v.w;
    }
#pragma unroll
    for (int it = 0; it < 12; it++) {
        int idx = tid + it * 256;
        int d4 = idx / 192, kk = idx % 192;
        if (kk < klen) {
            float4 v = *(const float4*)(qbase + (size_t)(ks+kk)*TD3 + DD + h*HD + d4*4);
            Kt[(d4*4+0)*200 + kk] = v.x; Kt[(d4*4+1)*200 + kk] = v.y;
            Kt[(d4*4+2)*200 + kk] = v.z; Kt[(d4*4+3)*200 + kk] = v.w;
        }
    }
#pragma unroll
    for (int it = 0; it < 12; it++) {
        int idx = tid + it * 256;
        int kk = idx >> 4, d4 = idx & 15;
        if (kk < klen) {
            float4 v = *(const float4*)(qbase + (size_t)(ks+kk)*TD3 + 2*DD + h*HD + d4*4);
            *(float4*)&Vs[kk*68 + d4*4] = v;
        }
    }
    if (tid < 192) Ms[tid] = (tid < klen) ? amask[b*TT + ks + tid] : 0;
    __syncthreads();

    const int tx = tid & 15;
    const int ty = tid >> 4;
    float s[4][12];
#pragma unroll
    for (int qi = 0; qi < 4; qi++)
#pragma unroll
        for (int ki = 0; ki < 12; ki++) s[qi][ki] = 0.f;

    for (int d = 0; d < 64; d++) {
        float4 aq = *(const float4*)&Qt[d*68 + ty*4];
        float4 b0 = *(const float4*)&Kt[d*200 + tx*12];
        float4 b1 = *(const float4*)&Kt[d*200 + tx*12 + 4];
        float4 b2 = *(const float4*)&Kt[d*200 + tx*12 + 8];
        float aa[4] = { aq.x, aq.y, aq.z, aq.w };
        float bk[12] = { b0.x,b0.y,b0.z,b0.w, b1.x,b1.y,b1.z,b1.w, b2.x,b2.y,b2.z,b2.w };
#pragma unroll
        for (int qi = 0; qi < 4; qi++)
#pragma unroll
            for (int ki = 0; ki < 12; ki++)
                s[qi][ki] += aa[qi] * bk[ki];
    }

    const float scale = 0.125f;
#pragma unroll
    for (int qi = 0; qi < 4; qi++) {
        int qg = q0 + ty*4 + qi;
        bool ok[12];
        float mx = -1e30f;
#pragma unroll
        for (int ki = 0; ki < 12; ki++) {
            int kk = tx*12 + ki;
            int kg = ks + kk;
            ok[ki] = (kk < klen) && (abs(qg - kg) <= WIN) && (Ms[kk] != 0);
            float sv = s[qi][ki] * scale;
            s[qi][ki] = sv;
            if (ok[ki]) mx = fmaxf(mx, sv);
        }
#pragma unroll
        for (int off = 8; off; off >>= 1)
            mx = fmaxf(mx, __shfl_xor_sync(0xffffffffu, mx, off));
        float sum = 0.f;
#pragma unroll
        for (int ki = 0; ki < 12; ki++) {
            float p = ok[ki] ? __expf(s[qi][ki] - mx) : 0.f;
            s[qi][ki] = p;
            sum += p;
        }
#pragma unroll
        for (int off = 8; off; off >>= 1)
            sum += __shfl_xor_sync(0xffffffffu, sum, off);
#pragma unroll
        for (int ki = 0; ki < 12; ki++)
            Ps[(ty*4+qi)*200 + tx*12 + ki] = s[qi][ki];
        if (tx == 0) Rs[ty*4 + qi] = sum;
    }
    __syncthreads();

    const int tx2 = tid & 15;
    const int ty2 = tid >> 4;
    float o[4][4];
#pragma unroll
    for (int qi = 0; qi < 4; qi++)
#pragma unroll
        for (int di = 0; di < 4; di++) o[qi][di] = 0.f;

    for (int k = 0; k < klen; k++) {
        float4 vv = *(const float4*)&Vs[k*68 + tx2*4];
        float v4[4] = { vv.x, vv.y, vv.z, vv.w };
        float pq[4];
#pragma unroll
        for (int qi = 0; qi < 4; qi++) pq[qi] = Ps[(ty2*4+qi)*200 + k];
#pragma unroll
        for (int qi = 0; qi < 4; qi++)
#pragma unroll
            for (int di = 0; di < 4; di++)
                o[qi][di] += pq[qi] * v4[di];
    }
#pragma unroll
    for (int qi = 0; qi < 4; qi++) {
        float r = 1.f / fmaxf(Rs[ty2*4 + qi], 1e-30f);
        float4 ov = make_float4(o[qi][0]*r, o[qi][1]*r, o[qi][2]*r, o[qi][3]*r);
        *(float4*)&out[(size_t)(b*TT + q0 + ty2*4 + qi)*DD + h*HD + tx2*4] = ov;
    }
}

// ---------------------------------------------------------------------------
extern "C" void kernel_launch(void* const* d_in, const int* in_sizes, int n_in,
                              void* d_out, int out_size)
{
    const float* hs   = (const float*)d_in[0];
    const int*   am   = (const int*)d_in[1];
    const float* Wqkv = (const float*)d_in[2];
    const float* Wo   = (const float*)d_in[3];
    float* out = (float*)d_out;

    void* p;
    cudaGetSymbolAddress(&p, g_qkv);   float* qkv  = (float*)p;
    cudaGetSymbolAddress(&p, g_attn);  float* attn = (float*)p;
    cudaGetSymbolAddress(&p, g_hsx);   __nv_bfloat16* hsx   = (__nv_bfloat16*)p;
    cudaGetSymbolAddress(&p, g_attnx); __nv_bfloat16* attnx = (__nv_bfloat16*)p;
    cudaGetSymbolAddress(&p, g_wqkvx); __nv_bfloat16* wqkvx = (__nv_bfloat16*)p;
    cudaGetSymbolAddress(&p, g_wox);   __nv_bfloat16* wox   = (__nv_bfloat16*)p;

    cudaFuncSetAttribute(attn_kernel,
                         cudaFuncAttributeMaxDynamicSharedMemorySize,
                         ATTN_SMEM_BYTES);
    cudaFuncSetAttribute(gemm_mma,
                         cudaFuncAttributeMaxDynamicSharedMemorySize,
                         GEMM_SMEM);

    const int M = BB * TT;                 // 8192
    const int q = DD / 4;                  // 192

    // 1) expand operands for QKV GEMM
    expand_kernel<<<(M*q + 255)/256, 256>>>(hs, hsx, M, 1);
    expand_kernel<<<(TD3*q + 255)/256, 256>>>(Wqkv, wqkvx, TD3, 0);

    // 2) QKV projection on HMMA tensor cores
    gemm_mma<<<dim3(TD3/128, M/128), 256, GEMM_SMEM>>>(hsx, wqkvx, qkv, TD3);

    // 3) RoPE in place
    rope_kernel<<<(BB*TT*NH*32)/256, 256>>>(qkv);

    // 4) sliding-window attention
    dim3 ga(TT/64, NH, BB);
    attn_kernel<<<ga, 256, ATTN_SMEM_BYTES>>>(qkv, am, attn);

    // 5) expand operands for output GEMM
    expand_kernel<<<(M*q + 255)/256, 256>>>(attn, attnx, M, 1);
    expand_kernel<<<(DD*q + 255)/256, 256>>>(Wo, wox, DD, 0);

    // 6) output projection on HMMA tensor cores
    gemm_mma<<<dim3(DD/128, M/128), 256, GEMM_SMEM>>>(attnx, wox, out, DD);
}

// round 5
// speedup vs baseline: 2.5558x; 1.8272x over previous
#include <cuda_runtime.h>
#include <cuda_bf16.h>
#include <math.h>
#include <stdint.h>

#define BB 4
#define TT 2048
#define DD 768
#define NH 12
#define HD 64
#define WIN 64
#define TD3 (3*DD)
#define K2 (3*DD)          // expanded K (hi|lo|hi) = 2304 bf16
#define KC 32              // k per pipeline chunk
#define NC (K2/KC)         // 72 chunks
#define PS 4               // pipeline stages
#define LDT 40             // padded smem row (bf16 elems) -> 80 bytes
#define TILE_BYTES (128*LDT*2)          // 10240 per operand tile
#define STAGE_BYTES (2*TILE_BYTES)      // 20480
#define GEMM_SMEM (PS*STAGE_BYTES)      // 81920

// ---------------- scratch (device globals: allocation-free rule) -----------
__device__ float g_qkv[(size_t)BB*TT*TD3];            // [B,T,3D] fp32
__device__ float g_attn[(size_t)BB*TT*DD];            // [B,T,D]  fp32
__device__ __nv_bfloat16 g_hsx [(size_t)BB*TT*K2];    // hidden expanded
__device__ __nv_bfloat16 g_attnx[(size_t)BB*TT*K2];   // attn-out expanded
__device__ __nv_bfloat16 g_wqkvx[(size_t)TD3*K2];     // Wqkv expanded
__device__ __nv_bfloat16 g_wox [(size_t)DD*K2];       // Wo expanded

// ---------------- PTX helpers (baseline ISA only — no tcgen05) -------------
__device__ __forceinline__ uint32_t smem_u32(const void* p){
    uint32_t a;
    asm("{ .reg .u64 t; cvta.to.shared.u64 t, %1; cvt.u32.u64 %0, t; }"
        : "=r"(a) : "l"(p));
    return a;
}
__device__ __forceinline__ void cp16(uint32_t d, const void* s){
    asm volatile("cp.async.cg.shared.global [%0], [%1], 16;"
                 :: "r"(d), "l"(s) : "memory");
}
__device__ __forceinline__ void cp_commit(){
    asm volatile("cp.async.commit_group;" ::: "memory");
}
template<int N>
__device__ __forceinline__ void cp_wait(){
    asm volatile("cp.async.wait_group %0;" :: "n"(N) : "memory");
}
__device__ __forceinline__ void ldsm_x4(uint32_t &r0,uint32_t &r1,uint32_t &r2,uint32_t &r3,
                                        uint32_t addr){
    asm volatile("ldmatrix.sync.aligned.m8n8.x4.shared.b16 {%0,%1,%2,%3}, [%4];"
                 : "=r"(r0),"=r"(r1),"=r"(r2),"=r"(r3) : "r"(addr));
}
__device__ __forceinline__ void ldsm_x2(uint32_t &r0,uint32_t &r1, uint32_t addr){
    asm volatile("ldmatrix.sync.aligned.m8n8.x2.shared.b16 {%0,%1}, [%2];"
                 : "=r"(r0),"=r"(r1) : "r"(addr));
}
__device__ __forceinline__ void mma16816(float* d, const uint32_t* a, const uint32_t* b){
    asm volatile("mma.sync.aligned.m16n8k16.row.col.f32.bf16.bf16.f32 "
        "{%0,%1,%2,%3}, {%4,%5,%6,%7}, {%8,%9}, {%0,%1,%2,%3};"
        : "+f"(d[0]),"+f"(d[1]),"+f"(d[2]),"+f"(d[3])
        : "r"(a[0]),"r"(a[1]),"r"(a[2]),"r"(a[3]), "r"(b[0]),"r"(b[1]));
}

// ---------------------------------------------------------------------------
// fp32 -> bf16 split expansion.
// amode=1 (A operand): [hi | lo | hi]   amode=0 (B operand): [hi | hi | lo]
// ---------------------------------------------------------------------------
__global__ void expand_kernel(const float* __restrict__ src,
                              __nv_bfloat16* __restrict__ dst,
                              int rows, int amode)
{
    const int q = DD / 4;  // 192
    int idx = blockIdx.x * blockDim.x + threadIdx.x;
    if (idx >= rows * q) return;
    int row = idx / q;
    int c = (idx - row * q) * 4;

    float4 v = *(const float4*)(src + (size_t)row * DD + c);
    __nv_bfloat16 h0 = __float2bfloat16_rn(v.x);
    __nv_bfloat16 h1 = __float2bfloat16_rn(v.y);
    __nv_bfloat16 h2 = __float2bfloat16_rn(v.z);
    __nv_bfloat16 h3 = __float2bfloat16_rn(v.w);
    __nv_bfloat16 l0 = __float2bfloat16_rn(v.x - __bfloat162float(h0));
    __nv_bfloat16 l1 = __float2bfloat16_rn(v.y - __bfloat162float(h1));
    __nv_bfloat16 l2 = __float2bfloat16_rn(v.z - __bfloat162float(h2));
    __nv_bfloat16 l3 = __float2bfloat16_rn(v.w - __bfloat162float(h3));

    uint2 hu = make_uint2(
        (uint32_t)__bfloat16_as_ushort(h0) | ((uint32_t)__bfloat16_as_ushort(h1) << 16),
        (uint32_t)__bfloat16_as_ushort(h2) | ((uint32_t)__bfloat16_as_ushort(h3) << 16));
    uint2 lu = make_uint2(
        (uint32_t)__bfloat16_as_ushort(l0) | ((uint32_t)__bfloat16_as_ushort(l1) << 16),
        (uint32_t)__bfloat16_as_ushort(l2) | ((uint32_t)__bfloat16_as_ushort(l3) << 16));

    __nv_bfloat16* b = dst + (size_t)row * K2 + c;
    *(uint2*)(b)           = hu;
    *(uint2*)(b + DD)      = amode ? lu : hu;
    *(uint2*)(b + 2 * DD)  = amode ? hu : lu;
}

// ---------------------------------------------------------------------------
// HMMA GEMM: C[m,n] = sum_k A2[m,k]*B2[n,k]  (both K-major), K=K2.
// 128x128 CTA tile, 256 thr (8 warps, 2x4), warp tile 64x32.
// 4-stage cp.async pipeline, mma.sync.m16n8k16 bf16->fp32.
// ---------------------------------------------------------------------------
__global__ void __launch_bounds__(256, 2)
gemm_mma(const __nv_bfloat16* __restrict__ A2,
         const __nv_bfloat16* __restrict__ B2,
         float* __restrict__ C, int N)
{
    extern __shared__ __align__(16) char smem[];
    const uint32_t sb = smem_u32(smem);
    const int tid  = threadIdx.x;
    const int lane = tid & 31;
    const int warp = tid >> 5;
    const int bm = blockIdx.y * 128;
    const int bn = blockIdx.x * 128;
    const int wm = warp & 1;     // 2 m-blocks of 64
    const int wn = warp >> 1;    // 4 n-blocks of 32

    const __nv_bfloat16* asrc[2];
    const __nv_bfloat16* bsrc[2];
    uint32_t adst[2], bdst[2];
#pragma unroll
    for (int h = 0; h < 2; h++) {
        int idx = tid + h * 256;
        int row = idx >> 2, seg = idx & 3;
        asrc[h] = A2 + (size_t)(bm + row) * K2 + seg * 8;
        bsrc[h] = B2 + (size_t)(bn + row) * K2 + seg * 8;
        adst[h] = (uint32_t)(row * (LDT*2) + seg * 16);
        bdst[h] = adst[h] + TILE_BYTES;
    }

#pragma unroll
    for (int s = 0; s < PS - 1; s++) {
        uint32_t st = sb + s * STAGE_BYTES;
#pragma unroll
        for (int h = 0; h < 2; h++) {
            cp16(st + adst[h], asrc[h] + s * KC);
            cp16(st + bdst[h], bsrc[h] + s * KC);
        }
        cp_commit();
    }

    float acc[4][4][4];
#pragma unroll
    for (int mi = 0; mi < 4; mi++)
#pragma unroll
        for (int ni = 0; ni < 4; ni++)
#pragma unroll
            for (int r = 0; r < 4; r++) acc[mi][ni][r] = 0.f;

    const uint32_t a_row = (uint32_t)(wm * 64 + (lane & 15));
    const uint32_t a_colb = (uint32_t)((lane >> 4) * 16);
    const uint32_t b_row = (uint32_t)(wn * 32 + (lane & 7));
    const uint32_t b_colb = (uint32_t)(((lane >> 3) & 1) * 16);

    for (int i = 0; i < NC; i++) {
        cp_wait<PS - 2>();
        __syncthreads();

        int nc = i + PS - 1;
        if (nc < NC) {
            uint32_t st = sb + (nc & (PS - 1)) * STAGE_BYTES;
#pragma unroll
            for (int h = 0; h < 2; h++) {
                cp16(st + adst[h], asrc[h] + nc * KC);
                cp16(st + bdst[h], bsrc[h] + nc * KC);
            }
        }
        cp_commit();

        uint32_t st = sb + (i & (PS - 1)) * STAGE_BYTES;
#pragma unroll
        for (int ks = 0; ks < 2; ks++) {
            uint32_t a[4][4], b[4][2];
#pragma unroll
            for (int mi = 0; mi < 4; mi++) {
                uint32_t addr = st + (a_row + mi * 16) * (LDT*2) + ks * 32 + a_colb;
                ldsm_x4(a[mi][0], a[mi][1], a[mi][2], a[mi][3], addr);
            }
#pragma unroll
            for (int ni = 0; ni < 4; ni++) {
                uint32_t addr = st + TILE_BYTES + (b_row + ni * 8) * (LDT*2)
                              + ks * 32 + b_colb;
                ldsm_x2(b[ni][0], b[ni][1], addr);
            }
#pragma unroll
            for (int mi = 0; mi < 4; mi++)
#pragma unroll
                for (int ni = 0; ni < 4; ni++)
                    mma16816(acc[mi][ni], a[mi], b[ni]);
        }
    }

    const int g = lane >> 2, t = lane & 3;
#pragma unroll
    for (int mi = 0; mi < 4; mi++) {
        int m0 = bm + wm * 64 + mi * 16 + g;
#pragma unroll
        for (int ni = 0; ni < 4; ni++) {
            int n0 = bn + wn * 32 + ni * 8 + 2 * t;
            *(float2*)&C[(size_t)m0 * N + n0] =
                make_float2(acc[mi][ni][0], acc[mi][ni][1]);
            *(float2*)&C[(size_t)(m0 + 8) * N + n0] =
                make_float2(acc[mi][ni][2], acc[mi][ni][3]);
        }
    }
}

// ---------------------------------------------------------------------------
// RoPE in-place on q and k parts of g_qkv. One warp per (b,t,head).
// FP32 only — no double pow (R4: that single call was 500us of FP64).
// ---------------------------------------------------------------------------
__global__ void rope_kernel(float* __restrict__ qkv)
{
    int gw   = (blockIdx.x * blockDim.x + threadIdx.x) >> 5;
    int lane = threadIdx.x & 31;
    if (gw >= BB * TT * NH) return;
    int h = gw % NH;
    int t = (gw / NH) % TT;
    int b = gw / (NH * TT);

    // 10000^(-lane/32) = 2^(-lane * log2(10000)/32)
    const float c0 = 0.41524101186092029f;  // log2(10000)/32
    float inv = exp2f(-c0 * (float)lane);
    float ang = (float)t * inv;
    float sn, cs;
    sincosf(ang, &sn, &cs);

    float* base = qkv + (size_t)(b * TT + t) * TD3 + h * HD;
    float qre = base[lane],        qim = base[lane + 32];
    float kre = base[DD + lane],   kim = base[DD + lane + 32];
    __syncwarp();
    base[2*lane]          = qre * cs - qim * sn;
    base[2*lane + 1]      = qre * sn + qim * cs;
    base[DD + 2*lane]     = kre * cs - kim * sn;
    base[DD + 2*lane + 1] = kre * sn + kim * cs;
}

// ---------------------------------------------------------------------------
// Sliding-window attention (unchanged).
// ---------------------------------------------------------------------------
#define ATTN_SMEM_FLOATS (64*68 + 64*200 + 192*68 + 64*200 + 64 + 192)
#define ATTN_SMEM_BYTES  (ATTN_SMEM_FLOATS * 4)

__global__ void __launch_bounds__(256, 1)
attn_kernel(const float* __restrict__ qkv, const int* __restrict__ amask,
            float* __restrict__ out)
{
    extern __shared__ __align__(16) float sm[];
    float* Qt = sm;                    // [64][68]
    float* Kt = Qt + 64*68;            // [64][200]
    float* Vs = Kt + 64*200;           // [192][68]
    float* Ps = Vs + 192*68;           // [64][200]
    float* Rs = Ps + 64*200;           // [64]
    int*   Ms = (int*)(Rs + 64);       // [192]

    const int tid = threadIdx.x;
    const int qb = blockIdx.x, h = blockIdx.y, b = blockIdx.z;
    const int q0 = qb * 64;
    const int ks = max(0, q0 - WIN);
    const int ke = min(TT, q0 + 64 + WIN);
    const int klen = ke - ks;
    const float* qbase = qkv + (size_t)b * TT * TD3;

#pragma unroll
    for (int it = 0; it < 4; it++) {
        int idx = tid + it * 256;
        int d4 = idx >> 6, row = idx & 63;
        float4 v = *(const float4*)(qbase + (size_t)(q0+row)*TD3 + h*HD + d4*4);
        Qt[(d4*4+0)*68 + row] = v.x; Qt[(d4*4+1)*68 + row] = v.y;
        Qt[(d4*4+2)*68 + row] = v.z; Qt[(d4*4+3)*68 + row] = v.w;
    }
#pragma unroll
    for (int it = 0; it < 12; it++) {
        int idx = tid + it * 256;
        int d4 = idx / 192, kk = idx % 192;
        if (kk < klen) {
            float4 v = *(const float4*)(qbase + (size_t)(ks+kk)*TD3 + DD + h*HD + d4*4);
            Kt[(d4*4+0)*200 + kk] = v.x; Kt[(d4*4+1)*200 + kk] = v.y;
            Kt[(d4*4+2)*200 + kk] = v.z; Kt[(d4*4+3)*200 + kk] = v.w;
        }
    }
#pragma unroll
    for (int it = 0; it < 12; it++) {
        int idx = tid + it * 256;
        int kk = idx >> 4, d4 = idx & 15;
        if (kk < klen) {
            float4 v = *(const float4*)(qbase + (size_t)(ks+kk)*TD3 + 2*DD + h*HD + d4*4);
            *(float4*)&Vs[kk*68 + d4*4] = v;
        }
    }
    if (tid < 192) Ms[tid] = (tid < klen) ? amask[b*TT + ks + tid] : 0;
    __syncthreads();

    const int tx = tid & 15;
    const int ty = tid >> 4;
    float s[4][12];
#pragma unroll
    for (int qi = 0; qi < 4; qi++)
#pragma unroll
        for (int ki = 0; ki < 12; ki++) s[qi][ki] = 0.f;

    for (int d = 0; d < 64; d++) {
        float4 aq = *(const float4*)&Qt[d*68 + ty*4];
        float4 b0 = *(const float4*)&Kt[d*200 + tx*12];
        float4 b1 = *(const float4*)&Kt[d*200 + tx*12 + 4];
        float4 b2 = *(const float4*)&Kt[d*200 + tx*12 + 8];
        float aa[4] = { aq.x, aq.y, aq.z, aq.w };
        float bk[12] = { b0.x,b0.y,b0.z,b0.w, b1.x,b1.y,b1.z,b1.w, b2.x,b2.y,b2.z,b2.w };
#pragma unroll
        for (int qi = 0; qi < 4; qi++)
#pragma unroll
            for (int ki = 0; ki < 12; ki++)
                s[qi][ki] += aa[qi] * bk[ki];
    }

    const float scale = 0.125f;
#pragma unroll
    for (int qi = 0; qi < 4; qi++) {
        int qg = q0 + ty*4 + qi;
        bool ok[12];
        float mx = -1e30f;
#pragma unroll
        for (int ki = 0; ki < 12; ki++) {
            int kk = tx*12 + ki;
            int kg = ks + kk;
            ok[ki] = (kk < klen) && (abs(qg - kg) <= WIN) && (Ms[kk] != 0);
            float sv = s[qi][ki] * scale;
            s[qi][ki] = sv;
            if (ok[ki]) mx = fmaxf(mx, sv);
        }
#pragma unroll
        for (int off = 8; off; off >>= 1)
            mx = fmaxf(mx, __shfl_xor_sync(0xffffffffu, mx, off));
        float sum = 0.f;
#pragma unroll
        for (int ki = 0; ki < 12; ki++) {
            float p = ok[ki] ? __expf(s[qi][ki] - mx) : 0.f;
            s[qi][ki] = p;
            sum += p;
        }
#pragma unroll
        for (int off = 8; off; off >>= 1)
            sum += __shfl_xor_sync(0xffffffffu, sum, off);
#pragma unroll
        for (int ki = 0; ki < 12; ki++)
            Ps[(ty*4+qi)*200 + tx*12 + ki] = s[qi][ki];
        if (tx == 0) Rs[ty*4 + qi] = sum;
    }
    __syncthreads();

    const int tx2 = tid & 15;
    const int ty2 = tid >> 4;
    float o[4][4];
#pragma unroll
    for (int qi = 0; qi < 4; qi++)
#pragma unroll
        for (int di = 0; di < 4; di++) o[qi][di] = 0.f;

    for (int k = 0; k < klen; k++) {
        float4 vv = *(const float4*)&Vs[k*68 + tx2*4];
        float v4[4] = { vv.x, vv.y, vv.z, vv.w };
        float pq[4];
#pragma unroll
        for (int qi = 0; qi < 4; qi++) pq[qi] = Ps[(ty2*4+qi)*200 + k];
#pragma unroll
        for (int qi = 0; qi < 4; qi++)
#pragma unroll
            for (int di = 0; di < 4; di++)
                o[qi][di] += pq[qi] * v4[di];
    }
#pragma unroll
    for (int qi = 0; qi < 4; qi++) {
        float r = 1.f / fmaxf(Rs[ty2*4 + qi], 1e-30f);
        float4 ov = make_float4(o[qi][0]*r, o[qi][1]*r, o[qi][2]*r, o[qi][3]*r);
        *(float4*)&out[(size_t)(b*TT + q0 + ty2*4 + qi)*DD + h*HD + tx2*4] = ov;
    }
}

// ---------------------------------------------------------------------------
extern "C" void kernel_launch(void* const* d_in, const int* in_sizes, int n_in,
                              void* d_out, int out_size)
{
    const float* hs   = (const float*)d_in[0];
    const int*   am   = (const int*)d_in[1];
    const float* Wqkv = (const float*)d_in[2];
    const float* Wo   = (const float*)d_in[3];
    float* out = (float*)d_out;

    void* p;
    cudaGetSymbolAddress(&p, g_qkv);   float* qkv  = (float*)p;
    cudaGetSymbolAddress(&p, g_attn);  float* attn = (float*)p;
    cudaGetSymbolAddress(&p, g_hsx);   __nv_bfloat16* hsx   = (__nv_bfloat16*)p;
    cudaGetSymbolAddress(&p, g_attnx); __nv_bfloat16* attnx = (__nv_bfloat16*)p;
    cudaGetSymbolAddress(&p, g_wqkvx); __nv_bfloat16* wqkvx = (__nv_bfloat16*)p;
    cudaGetSymbolAddress(&p, g_wox);   __nv_bfloat16* wox   = (__nv_bfloat16*)p;

    cudaFuncSetAttribute(attn_kernel,
                         cudaFuncAttributeMaxDynamicSharedMemorySize,
                         ATTN_SMEM_BYTES);
    cudaFuncSetAttribute(gemm_mma,
                         cudaFuncAttributeMaxDynamicSharedMemorySize,
                         GEMM_SMEM);

    const int M = BB * TT;                 // 8192
    const int q = DD / 4;                  // 192

    // 1) expand operands for QKV GEMM
    expand_kernel<<<(M*q + 255)/256, 256>>>(hs, hsx, M, 1);
    expand_kernel<<<(TD3*q + 255)/256, 256>>>(Wqkv, wqkvx, TD3, 0);

    // 2) QKV projection on HMMA tensor cores
    gemm_mma<<<dim3(TD3/128, M/128), 256, GEMM_SMEM>>>(hsx, wqkvx, qkv, TD3);

    // 3) RoPE in place
    rope_kernel<<<(BB*TT*NH*32)/256, 256>>>(qkv);

    // 4) sliding-window attention
    dim3 ga(TT/64, NH, BB);
    attn_kernel<<<ga, 256, ATTN_SMEM_BYTES>>>(qkv, am, attn);

    // 5) expand operands for output GEMM
    expand_kernel<<<(M*q + 255)/256, 256>>>(attn, attnx, M, 1);
    expand_kernel<<<(DD*q + 255)/256, 256>>>(Wo, wox, DD, 0);

    // 6) output projection on HMMA tensor cores
    gemm_mma<<<dim3(DD/128, M/128), 256, GEMM_SMEM>>>(attnx, wox, out, DD);
}

// round 6
// speedup vs baseline: 3.2316x; 1.2644x over previous
#include <cuda_runtime.h>
#include <cuda_fp16.h>
#include <math.h>
#include <stdint.h>

#define BB 4
#define TT 2048
#define DD 768
#define NH 12
#define HD 64
#define WIN 64
#define TD3 (3*DD)
#define KA 1536            // A operand K ([hi|lo] fp16)
#define KB 768             // B operand K (plain fp16, read twice)
#define KC 32              // k per pipeline chunk
#define NC (KA/KC)         // 48 chunks
#define PS 4               // pipeline stages
#define LDT 40             // padded smem row (fp16 elems) -> 80 bytes
#define TILE_BYTES (128*LDT*2)          // 10240 per operand tile
#define STAGE_BYTES (2*TILE_BYTES)      // 20480
#define GEMM_SMEM (PS*STAGE_BYTES)      // 81920

// ---------------- scratch (device globals: allocation-free rule) -----------
__device__ float  g_qkv[(size_t)BB*TT*TD3];          // [B,T,3D] fp32 (pre-rope)
__device__ __half g_ah  [(size_t)BB*TT*KA];          // hidden [hi|lo] fp16
__device__ __half g_attnx[(size_t)BB*TT*KA];         // attn out [hi|lo] fp16
__device__ __half g_wqkvh[(size_t)TD3*KB];           // Wqkv fp16
__device__ __half g_woh [(size_t)DD*KB];             // Wo fp16
__device__ float  g_tab [(size_t)TT*64];             // rope (cos,sin) pairs [t][j]

// ---------------- PTX helpers (baseline ISA only) ---------------------------
__device__ __forceinline__ uint32_t smem_u32(const void* p){
    uint32_t a;
    asm("{ .reg .u64 t; cvta.to.shared.u64 t, %1; cvt.u32.u64 %0, t; }"
        : "=r"(a) : "l"(p));
    return a;
}
__device__ __forceinline__ void cp16(uint32_t d, const void* s){
    asm volatile("cp.async.cg.shared.global [%0], [%1], 16;"
                 :: "r"(d), "l"(s) : "memory");
}
__device__ __forceinline__ void cp_commit(){
    asm volatile("cp.async.commit_group;" ::: "memory");
}
template<int N>
__device__ __forceinline__ void cp_wait(){
    asm volatile("cp.async.wait_group %0;" :: "n"(N) : "memory");
}
__device__ __forceinline__ void ldsm_x4(uint32_t &r0,uint32_t &r1,uint32_t &r2,uint32_t &r3,
                                        uint32_t addr){
    asm volatile("ldmatrix.sync.aligned.m8n8.x4.shared.b16 {%0,%1,%2,%3}, [%4];"
                 : "=r"(r0),"=r"(r1),"=r"(r2),"=r"(r3) : "r"(addr));
}
__device__ __forceinline__ void ldsm_x2(uint32_t &r0,uint32_t &r1, uint32_t addr){
    asm volatile("ldmatrix.sync.aligned.m8n8.x2.shared.b16 {%0,%1}, [%2];"
                 : "=r"(r0),"=r"(r1) : "r"(addr));
}
__device__ __forceinline__ void mma16816(float* d, const uint32_t* a, const uint32_t* b){
    asm volatile("mma.sync.aligned.m16n8k16.row.col.f32.f16.f16.f32 "
        "{%0,%1,%2,%3}, {%4,%5,%6,%7}, {%8,%9}, {%0,%1,%2,%3};"
        : "+f"(d[0]),"+f"(d[1]),"+f"(d[2]),"+f"(d[3])
        : "r"(a[0]),"r"(a[1]),"r"(a[2]),"r"(a[3]), "r"(b[0]),"r"(b[1]));
}

// ---------------------------------------------------------------------------
// Weight conversion: fp32 -> fp16, both Wqkv and Wo in one launch.
// ---------------------------------------------------------------------------
__global__ void conv_w(const float* __restrict__ wqkv, const float* __restrict__ wo,
                       __half* __restrict__ wqkvh, __half* __restrict__ woh)
{
    const int n1 = TD3*DD/4;             // 442368 float4s
    const int n2 = DD*DD/4;              // 147456
    int idx = blockIdx.x * blockDim.x + threadIdx.x;
    if (idx >= n1 + n2) return;
    const float* src; __half* dst; int i;
    if (idx < n1) { src = wqkv; dst = wqkvh; i = idx; }
    else          { src = wo;   dst = woh;   i = idx - n1; }
    float4 v = *(const float4*)(src + (size_t)i*4);
    ushort4 u;
    u.x = __half_as_ushort(__float2half_rn(v.x));
    u.y = __half_as_ushort(__float2half_rn(v.y));
    u.z = __half_as_ushort(__float2half_rn(v.z));
    u.w = __half_as_ushort(__float2half_rn(v.w));
    uint2 o = make_uint2((uint32_t)u.x | ((uint32_t)u.y << 16),
                         (uint32_t)u.z | ((uint32_t)u.w << 16));
    *(uint2*)(dst + (size_t)i*4) = o;
}

// ---------------------------------------------------------------------------
// RoPE table: g_tab[t*64 + 2j] = cos(t * 10000^(-j/32)), [.. +1] = sin.
// ---------------------------------------------------------------------------
__global__ void tab_kernel(float* __restrict__ tab)
{
    int idx = blockIdx.x * blockDim.x + threadIdx.x;   // TT*32
    int t = idx >> 5, j = idx & 31;
    const float c0 = 0.41524101186092029f;             // log2(10000)/32
    float inv = exp2f(-c0 * (float)j);
    float sn, cs;
    sincosf((float)t * inv, &sn, &cs);
    tab[t*64 + 2*j]     = cs;
    tab[t*64 + 2*j + 1] = sn;
}

// ---------------------------------------------------------------------------
// fp32 [rows x 768] -> fp16 [rows x 1536] as [hi | lo].
// ---------------------------------------------------------------------------
__global__ void expand_a(const float* __restrict__ src, __half* __restrict__ dst,
                         int rows)
{
    const int q = DD / 4;  // 192
    int idx = blockIdx.x * blockDim.x + threadIdx.x;
    if (idx >= rows * q) return;
    int row = idx / q;
    int c = (idx - row * q) * 4;
    float4 v = *(const float4*)(src + (size_t)row * DD + c);
    __half h0 = __float2half_rn(v.x), h1 = __float2half_rn(v.y);
    __half h2 = __float2half_rn(v.z), h3 = __float2half_rn(v.w);
    __half l0 = __float2half_rn(v.x - __half2float(h0));
    __half l1 = __float2half_rn(v.y - __half2float(h1));
    __half l2 = __float2half_rn(v.z - __half2float(h2));
    __half l3 = __float2half_rn(v.w - __half2float(h3));
    uint2 hu = make_uint2(
        (uint32_t)__half_as_ushort(h0) | ((uint32_t)__half_as_ushort(h1) << 16),
        (uint32_t)__half_as_ushort(h2) | ((uint32_t)__half_as_ushort(h3) << 16));
    uint2 lu = make_uint2(
        (uint32_t)__half_as_ushort(l0) | ((uint32_t)__half_as_ushort(l1) << 16),
        (uint32_t)__half_as_ushort(l2) | ((uint32_t)__half_as_ushort(l3) << 16));
    __half* b = dst + (size_t)row * KA + c;
    *(uint2*)(b)      = hu;
    *(uint2*)(b + KB) = lu;
}

// ---------------------------------------------------------------------------
// HMMA GEMM: C[m,n] = sum_{k<KA} A2[m,k] * Bh[n, k%768]   (fp16 -> fp32)
// A2 = [hi|lo] split (K=1536), Bh plain fp16 (K=768, consumed twice).
// 128x128 CTA tile, 8 warps (2x4), warp tile 64x32, 4-stage cp.async.
// ---------------------------------------------------------------------------
__global__ void __launch_bounds__(256, 2)
gemm_mma(const __half* __restrict__ A2, const __half* __restrict__ Bh,
         float* __restrict__ C, int N)
{
    extern __shared__ __align__(16) char smem[];
    const uint32_t sb = smem_u32(smem);
    const int tid  = threadIdx.x;
    const int lane = tid & 31;
    const int warp = tid >> 5;
    const int bm = blockIdx.y * 128;
    const int bn = blockIdx.x * 128;
    const int wm = warp & 1;
    const int wn = warp >> 1;

    const __half* asrc[2];
    const __half* bsrc[2];
    uint32_t adst[2], bdst[2];
#pragma unroll
    for (int h = 0; h < 2; h++) {
        int idx = tid + h * 256;
        int row = idx >> 2, seg = idx & 3;
        asrc[h] = A2 + (size_t)(bm + row) * KA + seg * 8;
        bsrc[h] = Bh + (size_t)(bn + row) * KB + seg * 8;
        adst[h] = (uint32_t)(row * (LDT*2) + seg * 16);
        bdst[h] = adst[h] + TILE_BYTES;
    }

#pragma unroll
    for (int s = 0; s < PS - 1; s++) {
        uint32_t st = sb + s * STAGE_BYTES;
        int bko = (s % 24) * KC;
#pragma unroll
        for (int h = 0; h < 2; h++) {
            cp16(st + adst[h], asrc[h] + s * KC);
            cp16(st + bdst[h], bsrc[h] + bko);
        }
        cp_commit();
    }

    float acc[4][4][4];
#pragma unroll
    for (int mi = 0; mi < 4; mi++)
#pragma unroll
        for (int ni = 0; ni < 4; ni++)
#pragma unroll
            for (int r = 0; r < 4; r++) acc[mi][ni][r] = 0.f;

    const uint32_t a_row = (uint32_t)(wm * 64 + (lane & 15));
    const uint32_t a_colb = (uint32_t)((lane >> 4) * 16);
    const uint32_t b_row = (uint32_t)(wn * 32 + (lane & 7));
    const uint32_t b_colb = (uint32_t)(((lane >> 3) & 1) * 16);

    for (int i = 0; i < NC; i++) {
        cp_wait<PS - 2>();
        __syncthreads();

        int nc = i + PS - 1;
        if (nc < NC) {
            uint32_t st = sb + (nc & (PS - 1)) * STAGE_BYTES;
            int bko = (nc % 24) * KC;
#pragma unroll
            for (int h = 0; h < 2; h++) {
                cp16(st + adst[h], asrc[h] + nc * KC);
                cp16(st + bdst[h], bsrc[h] + bko);
            }
        }
        cp_commit();

        uint32_t st = sb + (i & (PS - 1)) * STAGE_BYTES;
#pragma unroll
        for (int ks = 0; ks < 2; ks++) {
            uint32_t a[4][4], b[4][2];
#pragma unroll
            for (int mi = 0; mi < 4; mi++) {
                uint32_t addr = st + (a_row + mi * 16) * (LDT*2) + ks * 32 + a_colb;
                ldsm_x4(a[mi][0], a[mi][1], a[mi][2], a[mi][3], addr);
            }
#pragma unroll
            for (int ni = 0; ni < 4; ni++) {
                uint32_t addr = st + TILE_BYTES + (b_row + ni * 8) * (LDT*2)
                              + ks * 32 + b_colb;
                ldsm_x2(b[ni][0], b[ni][1], addr);
            }
#pragma unroll
            for (int mi = 0; mi < 4; mi++)
#pragma unroll
                for (int ni = 0; ni < 4; ni++)
                    mma16816(acc[mi][ni], a[mi], b[ni]);
        }
    }

    const int g = lane >> 2, t = lane & 3;
#pragma unroll
    for (int mi = 0; mi < 4; mi++) {
        int m0 = bm + wm * 64 + mi * 16 + g;
#pragma unroll
        for (int ni = 0; ni < 4; ni++) {
            int n0 = bn + wn * 32 + ni * 8 + 2 * t;
            *(float2*)&C[(size_t)m0 * N + n0] =
                make_float2(acc[mi][ni][0], acc[mi][ni][1]);
            *(float2*)&C[(size_t)(m0 + 8) * N + n0] =
                make_float2(acc[mi][ni][2], acc[mi][ni][3]);
        }
    }
}

// ---------------------------------------------------------------------------
// Sliding-window attention with fused RoPE (table-based) and fused
// [hi|lo] fp16 output expansion for the Wo GEMM.
// ---------------------------------------------------------------------------
#define ATTN_SMEM_FLOATS (64*68 + 64*200 + 192*68 + 64*200 + 64 + 192)
#define ATTN_SMEM_BYTES  (ATTN_SMEM_FLOATS * 4)

__global__ void __launch_bounds__(256, 1)
attn_kernel(const float* __restrict__ qkv, const int* __restrict__ amask,
            const float* __restrict__ tab, __half* __restrict__ attnx)
{
    extern __shared__ __align__(16) float sm[];
    float* Qt = sm;                    // [64][68]  d-major (post-rope)
    float* Kt = Qt + 64*68;            // [64][200] d-major (post-rope)
    float* Vs = Kt + 64*200;           // [192][68]
    float* Ps = Vs + 192*68;           // [64][200]
    float* Rs = Ps + 64*200;           // [64]
    int*   Ms = (int*)(Rs + 64);       // [192]

    const int tid = threadIdx.x;
    const int qb = blockIdx.x, h = blockIdx.y, b = blockIdx.z;
    const int q0 = qb * 64;
    const int ks = max(0, q0 - WIN);
    const int ke = min(TT, q0 + 64 + WIN);
    const int klen = ke - ks;
    const float* qbase = qkv + (size_t)b * TT * TD3;

    // ---- Q: load + rope + transpose. 512 items = (row 0..63, j4 0..7) ----
#pragma unroll
    for (int it = 0; it < 2; it++) {
        int item = tid + it * 256;
        int row = item & 63, j4 = item >> 6;
        int t = q0 + row;
        const float* src = qbase + (size_t)t * TD3 + h * HD;
        float4 x0 = *(const float4*)(src + j4 * 4);
        float4 x1 = *(const float4*)(src + j4 * 4 + 32);
        const float4* tb = (const float4*)(tab + (size_t)t * 64 + j4 * 8);
        float4 t0 = tb[0], t1 = tb[1];   // (c,s,c,s)(c,s,c,s)
        float* q = Qt + j4 * 8 * 68 + row;
        q[0*68] = x0.x*t0.x - x1.x*t0.y;  q[1*68] = x0.x*t0.y + x1.x*t0.x;
        q[2*68] = x0.y*t0.z - x1.y*t0.w;  q[3*68] = x0.y*t0.w + x1.y*t0.z;
        q[4*68] = x0.z*t1.x - x1.z*t1.y;  q[5*68] = x0.z*t1.y + x1.z*t1.x;
        q[6*68] = x0.w*t1.z - x1.w*t1.w;  q[7*68] = x0.w*t1.w + x1.w*t1.z;
    }
    // ---- K: load + rope + transpose. 1536 items = (kk 0..191, j4 0..7) ----
#pragma unroll
    for (int it = 0; it < 6; it++) {
        int item = tid + it * 256;
        int kk = item % 192, j4 = item / 192;
        if (kk < klen) {
            int t = ks + kk;
            const float* src = qbase + (size_t)t * TD3 + DD + h * HD;
            float4 x0 = *(const float4*)(src + j4 * 4);
            float4 x1 = *(const float4*)(src + j4 * 4 + 32);
            const float4* tb = (const float4*)(tab + (size_t)t * 64 + j4 * 8);
            float4 t0 = tb[0], t1 = tb[1];
            float* k = Kt + j4 * 8 * 200 + kk;
            k[0*200] = x0.x*t0.x - x1.x*t0.y;  k[1*200] = x0.x*t0.y + x1.x*t0.x;
            k[2*200] = x0.y*t0.z - x1.y*t0.w;  k[3*200] = x0.y*t0.w + x1.y*t0.z;
            k[4*200] = x0.z*t1.x - x1.z*t1.y;  k[5*200] = x0.z*t1.y + x1.z*t1.x;
            k[6*200] = x0.w*t1.z - x1.w*t1.w;  k[7*200] = x0.w*t1.w + x1.w*t1.z;
        }
    }
    // ---- V direct ----
#pragma unroll
    for (int it = 0; it < 12; it++) {
        int idx = tid + it * 256;
        int kk = idx >> 4, d4 = idx & 15;
        if (kk < klen) {
            float4 v = *(const float4*)(qbase + (size_t)(ks+kk)*TD3 + 2*DD + h*HD + d4*4);
            *(float4*)&Vs[kk*68 + d4*4] = v;
        }
    }
    if (tid < 192) Ms[tid] = (tid < klen) ? amask[b*TT + ks + tid] : 0;
    __syncthreads();

    // ---- scores: each thread 4q x 12k ----
    const int tx = tid & 15;
    const int ty = tid >> 4;
    float s[4][12];
#pragma unroll
    for (int qi = 0; qi < 4; qi++)
#pragma unroll
        for (int ki = 0; ki < 12; ki++) s[qi][ki] = 0.f;

    for (int d = 0; d < 64; d++) {
        float4 aq = *(const float4*)&Qt[d*68 + ty*4];
        float4 b0 = *(const float4*)&Kt[d*200 + tx*12];
        float4 b1 = *(const float4*)&Kt[d*200 + tx*12 + 4];
        float4 b2 = *(const float4*)&Kt[d*200 + tx*12 + 8];
        float aa[4] = { aq.x, aq.y, aq.z, aq.w };
        float bk[12] = { b0.x,b0.y,b0.z,b0.w, b1.x,b1.y,b1.z,b1.w, b2.x,b2.y,b2.z,b2.w };
#pragma unroll
        for (int qi = 0; qi < 4; qi++)
#pragma unroll
            for (int ki = 0; ki < 12; ki++)
                s[qi][ki] += aa[qi] * bk[ki];
    }

    const float scale = 0.125f;
#pragma unroll
    for (int qi = 0; qi < 4; qi++) {
        int qg = q0 + ty*4 + qi;
        bool ok[12];
        float mx = -1e30f;
#pragma unroll
        for (int ki = 0; ki < 12; ki++) {
            int kk = tx*12 + ki;
            int kg = ks + kk;
            ok[ki] = (kk < klen) && (abs(qg - kg) <= WIN) && (Ms[kk] != 0);
            float sv = s[qi][ki] * scale;
            s[qi][ki] = sv;
            if (ok[ki]) mx = fmaxf(mx, sv);
        }
#pragma unroll
        for (int off = 8; off; off >>= 1)
            mx = fmaxf(mx, __shfl_xor_sync(0xffffffffu, mx, off));
        float sum = 0.f;
#pragma unroll
        for (int ki = 0; ki < 12; ki++) {
            float p = ok[ki] ? __expf(s[qi][ki] - mx) : 0.f;
            s[qi][ki] = p;
            sum += p;
        }
#pragma unroll
        for (int off = 8; off; off >>= 1)
            sum += __shfl_xor_sync(0xffffffffu, sum, off);
#pragma unroll
        for (int ki = 0; ki < 12; ki++)
            Ps[(ty*4+qi)*200 + tx*12 + ki] = s[qi][ki];
        if (tx == 0) Rs[ty*4 + qi] = sum;
    }
    __syncthreads();

    // ---- PV: each thread 4q x 4d ----
    const int tx2 = tid & 15;
    const int ty2 = tid >> 4;
    float o[4][4];
#pragma unroll
    for (int qi = 0; qi < 4; qi++)
#pragma unroll
        for (int di = 0; di < 4; di++) o[qi][di] = 0.f;

    for (int k = 0; k < klen; k++) {
        float4 vv = *(const float4*)&Vs[k*68 + tx2*4];
        float v4[4] = { vv.x, vv.y, vv.z, vv.w };
        float pq[4];
#pragma unroll
        for (int qi = 0; qi < 4; qi++) pq[qi] = Ps[(ty2*4+qi)*200 + k];
#pragma unroll
        for (int qi = 0; qi < 4; qi++)
#pragma unroll
            for (int di = 0; di < 4; di++)
                o[qi][di] += pq[qi] * v4[di];
    }
    // ---- epilogue: normalize + write [hi|lo] fp16 operand for Wo GEMM ----
#pragma unroll
    for (int qi = 0; qi < 4; qi++) {
        float r = 1.f / fmaxf(Rs[ty2*4 + qi], 1e-30f);
        float v0 = o[qi][0]*r, v1 = o[qi][1]*r, v2 = o[qi][2]*r, v3 = o[qi][3]*r;
        __half h0 = __float2half_rn(v0), h1 = __float2half_rn(v1);
        __half h2 = __float2half_rn(v2), h3 = __float2half_rn(v3);
        __half l0 = __float2half_rn(v0 - __half2float(h0));
        __half l1 = __float2half_rn(v1 - __half2float(h1));
        __half l2 = __float2half_rn(v2 - __half2float(h2));
        __half l3 = __float2half_rn(v3 - __half2float(h3));
        uint2 hu = make_uint2(
            (uint32_t)__half_as_ushort(h0) | ((uint32_t)__half_as_ushort(h1) << 16),
            (uint32_t)__half_as_ushort(h2) | ((uint32_t)__half_as_ushort(h3) << 16));
        uint2 lu = make_uint2(
            (uint32_t)__half_as_ushort(l0) | ((uint32_t)__half_as_ushort(l1) << 16),
            (uint32_t)__half_as_ushort(l2) | ((uint32_t)__half_as_ushort(l3) << 16));
        __half* dst = attnx + (size_t)(b*TT + q0 + ty2*4 + qi) * KA + h*HD + tx2*4;
        *(uint2*)(dst)      = hu;
        *(uint2*)(dst + KB) = lu;
    }
}

// ---------------------------------------------------------------------------
extern "C" void kernel_launch(void* const* d_in, const int* in_sizes, int n_in,
                              void* d_out, int out_size)
{
    const float* hs   = (const float*)d_in[0];
    const int*   am   = (const int*)d_in[1];
    const float* Wqkv = (const float*)d_in[2];
    const float* Wo   = (const float*)d_in[3];
    float* out = (float*)d_out;

    void* p;
    cudaGetSymbolAddress(&p, g_qkv);   float*  qkv   = (float*)p;
    cudaGetSymbolAddress(&p, g_ah);    __half* ah    = (__half*)p;
    cudaGetSymbolAddress(&p, g_attnx); __half* attnx = (__half*)p;
    cudaGetSymbolAddress(&p, g_wqkvh); __half* wqkvh = (__half*)p;
    cudaGetSymbolAddress(&p, g_woh);   __half* woh   = (__half*)p;
    cudaGetSymbolAddress(&p, g_tab);   float*  tab   = (float*)p;

    cudaFuncSetAttribute(attn_kernel,
                         cudaFuncAttributeMaxDynamicSharedMemorySize,
                         ATTN_SMEM_BYTES);
    cudaFuncSetAttribute(gemm_mma,
                         cudaFuncAttributeMaxDynamicSharedMemorySize,
                         GEMM_SMEM);

    const int M = BB * TT;                 // 8192

    // 1) weights -> fp16 (both)
    conv_w<<<((TD3*DD + DD*DD)/4 + 255)/256, 256>>>(Wqkv, Wo, wqkvh, woh);

    // 2) rope table
    tab_kernel<<<(TT*32)/256, 256>>>(tab);

    // 3) hidden states -> [hi|lo] fp16
    expand_a<<<(M*(DD/4) + 255)/256, 256>>>(hs, ah, M);

    // 4) QKV projection (captured by ncu as 4th launch)
    gemm_mma<<<dim3(TD3/128, M/128), 256, GEMM_SMEM>>>(ah, wqkvh, qkv, TD3);

    // 5) attention (rope fused in, writes [hi|lo] fp16)
    dim3 ga(TT/64, NH, BB);
    attn_kernel<<<ga, 256, ATTN_SMEM_BYTES>>>(qkv, am, tab, attnx);

    // 6) output projection
    gemm_mma<<<dim3(DD/128, M/128), 256, GEMM_SMEM>>>(attnx, woh, out, DD);
}

// round 7
// speedup vs baseline: 3.4251x; 1.0599x over previous
#include <cuda_runtime.h>
#include <cuda_fp16.h>
#include <math.h>
#include <stdint.h>

#define BB 4
#define TT 2048
#define DD 768
#define NH 12
#define HD 64
#define WIN 64
#define TD3 (3*DD)
#define KA 1536            // A operand K ([hi|lo] fp16)
#define KB 768             // B operand K (plain fp16, read twice)
#define KC 64              // k per pipeline chunk
#define NC (KA/KC)         // 24 chunks
#define PS 3               // pipeline stages
#define LDT 72             // padded smem row (fp16 elems) -> 144 bytes
#define TILE_BYTES (128*LDT*2)          // 18432 per operand tile
#define STAGE_BYTES (2*TILE_BYTES)      // 36864
#define GEMM_SMEM (PS*STAGE_BYTES)      // 110592

// ---------------- scratch (device globals: allocation-free rule) -----------
__device__ float  g_qkv[(size_t)BB*TT*TD3];          // [B,T,3D] fp32 (pre-rope)
__device__ __half g_ah  [(size_t)BB*TT*KA];          // hidden [hi|lo] fp16
__device__ __half g_attnx[(size_t)BB*TT*KA];         // attn out [hi|lo] fp16
__device__ __half g_wqkvh[(size_t)TD3*KB];           // Wqkv fp16
__device__ __half g_woh [(size_t)DD*KB];             // Wo fp16
__device__ float  g_tab [(size_t)TT*64];             // rope (cos,sin) pairs [t][j]

typedef unsigned long long u64;

// ---------------- PTX helpers (baseline ISA only) ---------------------------
__device__ __forceinline__ uint32_t smem_u32(const void* p){
    uint32_t a;
    asm("{ .reg .u64 t; cvta.to.shared.u64 t, %1; cvt.u32.u64 %0, t; }"
        : "=r"(a) : "l"(p));
    return a;
}
__device__ __forceinline__ void cp16(uint32_t d, const void* s){
    asm volatile("cp.async.cg.shared.global [%0], [%1], 16;"
                 :: "r"(d), "l"(s) : "memory");
}
__device__ __forceinline__ void cp_commit(){
    asm volatile("cp.async.commit_group;" ::: "memory");
}
template<int N>
__device__ __forceinline__ void cp_wait(){
    asm volatile("cp.async.wait_group %0;" :: "n"(N) : "memory");
}
__device__ __forceinline__ void ldsm_x4(uint32_t &r0,uint32_t &r1,uint32_t &r2,uint32_t &r3,
                                        uint32_t addr){
    asm volatile("ldmatrix.sync.aligned.m8n8.x4.shared.b16 {%0,%1,%2,%3}, [%4];"
                 : "=r"(r0),"=r"(r1),"=r"(r2),"=r"(r3) : "r"(addr));
}
__device__ __forceinline__ void ldsm_x2(uint32_t &r0,uint32_t &r1, uint32_t addr){
    asm volatile("ldmatrix.sync.aligned.m8n8.x2.shared.b16 {%0,%1}, [%2];"
                 : "=r"(r0),"=r"(r1) : "r"(addr));
}
__device__ __forceinline__ void mma16816(float* d, const uint32_t* a, const uint32_t* b){
    asm volatile("mma.sync.aligned.m16n8k16.row.col.f32.f16.f16.f32 "
        "{%0,%1,%2,%3}, {%4,%5,%6,%7}, {%8,%9}, {%0,%1,%2,%3};"
        : "+f"(d[0]),"+f"(d[1]),"+f"(d[2]),"+f"(d[3])
        : "r"(a[0]),"r"(a[1]),"r"(a[2]),"r"(a[3]), "r"(b[0]),"r"(b[1]));
}
// packed fp32 pair ops (Blackwell f32x2 — exact fp32 FMA, double width)
__device__ __forceinline__ u64 pk2(float lo, float hi){
    u64 r; asm("mov.b64 %0,{%1,%2};" : "=l"(r) : "f"(lo), "f"(hi)); return r;
}
__device__ __forceinline__ u64 fma2(u64 a, u64 b, u64 c){
    u64 d; asm("fma.rn.f32x2 %0,%1,%2,%3;" : "=l"(d) : "l"(a), "l"(b), "l"(c)); return d;
}
__device__ __forceinline__ float2 up2(u64 v){
    float2 f; asm("mov.b64 {%0,%1},%2;" : "=f"(f.x), "=f"(f.y) : "l"(v)); return f;
}

// ---------------------------------------------------------------------------
// Weight conversion: fp32 -> fp16, both Wqkv and Wo in one launch.
// ---------------------------------------------------------------------------
__global__ void conv_w(const float* __restrict__ wqkv, const float* __restrict__ wo,
                       __half* __restrict__ wqkvh, __half* __restrict__ woh)
{
    const int n1 = TD3*DD/4;
    const int n2 = DD*DD/4;
    int idx = blockIdx.x * blockDim.x + threadIdx.x;
    if (idx >= n1 + n2) return;
    const float* src; __half* dst; int i;
    if (idx < n1) { src = wqkv; dst = wqkvh; i = idx; }
    else          { src = wo;   dst = woh;   i = idx - n1; }
    float4 v = *(const float4*)(src + (size_t)i*4);
    ushort4 u;
    u.x = __half_as_ushort(__float2half_rn(v.x));
    u.y = __half_as_ushort(__float2half_rn(v.y));
    u.z = __half_as_ushort(__float2half_rn(v.z));
    u.w = __half_as_ushort(__float2half_rn(v.w));
    uint2 o = make_uint2((uint32_t)u.x | ((uint32_t)u.y << 16),
                         (uint32_t)u.z | ((uint32_t)u.w << 16));
    *(uint2*)(dst + (size_t)i*4) = o;
}

// ---------------------------------------------------------------------------
// RoPE table: g_tab[t*64 + 2j] = cos(t * 10000^(-j/32)), [.. +1] = sin.
// ---------------------------------------------------------------------------
__global__ void tab_kernel(float* __restrict__ tab)
{
    int idx = blockIdx.x * blockDim.x + threadIdx.x;   // TT*32
    int t = idx >> 5, j = idx & 31;
    const float c0 = 0.41524101186092029f;             // log2(10000)/32
    float inv = exp2f(-c0 * (float)j);
    float sn, cs;
    sincosf((float)t * inv, &sn, &cs);
    tab[t*64 + 2*j]     = cs;
    tab[t*64 + 2*j + 1] = sn;
}

// ---------------------------------------------------------------------------
// fp32 [rows x 768] -> fp16 [rows x 1536] as [hi | lo].
// ---------------------------------------------------------------------------
__global__ void expand_a(const float* __restrict__ src, __half* __restrict__ dst,
                         int rows)
{
    const int q = DD / 4;  // 192
    int idx = blockIdx.x * blockDim.x + threadIdx.x;
    if (idx >= rows * q) return;
    int row = idx / q;
    int c = (idx - row * q) * 4;
    float4 v = *(const float4*)(src + (size_t)row * DD + c);
    __half h0 = __float2half_rn(v.x), h1 = __float2half_rn(v.y);
    __half h2 = __float2half_rn(v.z), h3 = __float2half_rn(v.w);
    __half l0 = __float2half_rn(v.x - __half2float(h0));
    __half l1 = __float2half_rn(v.y - __half2float(h1));
    __half l2 = __float2half_rn(v.z - __half2float(h2));
    __half l3 = __float2half_rn(v.w - __half2float(h3));
    uint2 hu = make_uint2(
        (uint32_t)__half_as_ushort(h0) | ((uint32_t)__half_as_ushort(h1) << 16),
        (uint32_t)__half_as_ushort(h2) | ((uint32_t)__half_as_ushort(h3) << 16));
    uint2 lu = make_uint2(
        (uint32_t)__half_as_ushort(l0) | ((uint32_t)__half_as_ushort(l1) << 16),
        (uint32_t)__half_as_ushort(l2) | ((uint32_t)__half_as_ushort(l3) << 16));
    __half* b = dst + (size_t)row * KA + c;
    *(uint2*)(b)      = hu;
    *(uint2*)(b + KB) = lu;
}

// ---------------------------------------------------------------------------
// HMMA GEMM: C[m,n] = sum_{k<KA} A2[m,k] * Bh[n, k%768]   (fp16 -> fp32)
// 128x128 CTA tile, 8 warps (2x4), warp tile 64x32.
// KC=64 per stage, 3-stage cp.async pipeline (24 iters, 64 MMA per barrier).
// ---------------------------------------------------------------------------
__global__ void __launch_bounds__(256, 2)
gemm_mma(const __half* __restrict__ A2, const __half* __restrict__ Bh,
         float* __restrict__ C, int N)
{
    extern __shared__ __align__(16) char smem[];
    const uint32_t sb = smem_u32(smem);
    const int tid  = threadIdx.x;
    const int lane = tid & 31;
    const int warp = tid >> 5;
    const int bm = blockIdx.y * 128;
    const int bn = blockIdx.x * 128;
    const int wm = warp & 1;
    const int wn = warp >> 1;

    // loader mapping: per stage 2048 cp16 (A 1024 + B 1024), 8 per thread.
    const __half* asp[4]; uint32_t adf[4];
    const __half* bsp[4]; uint32_t bdf[4];
#pragma unroll
    for (int h = 0; h < 4; h++) {
        int idx = tid + h * 256;       // 0..1023
        int row = idx >> 3, seg = idx & 7;
        asp[h] = A2 + (size_t)(bm + row) * KA + seg * 8;
        bsp[h] = Bh + (size_t)(bn + row) * KB + seg * 8;
        adf[h] = (uint32_t)(row * (LDT*2) + seg * 16);
        bdf[h] = adf[h] + TILE_BYTES;
    }

    // prologue: stages 0..PS-2
#pragma unroll
    for (int s = 0; s < PS - 1; s++) {
        uint32_t st = sb + s * STAGE_BYTES;
        int ao = s * KC, bo = (s % 12) * KC;
#pragma unroll
        for (int h = 0; h < 4; h++) {
            cp16(st + adf[h], asp[h] + ao);
            cp16(st + bdf[h], bsp[h] + bo);
        }
        cp_commit();
    }

    float acc[4][4][4];
#pragma unroll
    for (int mi = 0; mi < 4; mi++)
#pragma unroll
        for (int ni = 0; ni < 4; ni++)
#pragma unroll
            for (int r = 0; r < 4; r++) acc[mi][ni][r] = 0.f;

    const uint32_t a_row = (uint32_t)(wm * 64 + (lane & 15));
    const uint32_t a_colb = (uint32_t)((lane >> 4) * 16);
    const uint32_t b_row = (uint32_t)(wn * 32 + (lane & 7));
    const uint32_t b_colb = (uint32_t)(((lane >> 3) & 1) * 16);

    for (int i = 0; i < NC; i++) {
        cp_wait<PS - 2>();
        __syncthreads();

        int nc = i + PS - 1;
        if (nc < NC) {
            uint32_t st = sb + (nc % PS) * STAGE_BYTES;
            int ao = nc * KC, bo = (nc % 12) * KC;
#pragma unroll
            for (int h = 0; h < 4; h++) {
                cp16(st + adf[h], asp[h] + ao);
                cp16(st + bdf[h], bsp[h] + bo);
            }
        }
        cp_commit();

        uint32_t st = sb + (i % PS) * STAGE_BYTES;
#pragma unroll
        for (int ks = 0; ks < 4; ks++) {
            uint32_t a[4][4], b[4][2];
#pragma unroll
            for (int mi = 0; mi < 4; mi++) {
                uint32_t addr = st + (a_row + mi * 16) * (LDT*2) + ks * 32 + a_colb;
                ldsm_x4(a[mi][0], a[mi][1], a[mi][2], a[mi][3], addr);
            }
#pragma unroll
            for (int ni = 0; ni < 4; ni++) {
                uint32_t addr = st + TILE_BYTES + (b_row + ni * 8) * (LDT*2)
                              + ks * 32 + b_colb;
                ldsm_x2(b[ni][0], b[ni][1], addr);
            }
#pragma unroll
            for (int mi = 0; mi < 4; mi++)
#pragma unroll
                for (int ni = 0; ni < 4; ni++)
                    mma16816(acc[mi][ni], a[mi], b[ni]);
        }
    }

    const int g = lane >> 2, t = lane & 3;
#pragma unroll
    for (int mi = 0; mi < 4; mi++) {
        int m0 = bm + wm * 64 + mi * 16 + g;
#pragma unroll
        for (int ni = 0; ni < 4; ni++) {
            int n0 = bn + wn * 32 + ni * 8 + 2 * t;
            *(float2*)&C[(size_t)m0 * N + n0] =
                make_float2(acc[mi][ni][0], acc[mi][ni][1]);
            *(float2*)&C[(size_t)(m0 + 8) * N + n0] =
                make_float2(acc[mi][ni][2], acc[mi][ni][3]);
        }
    }
}

// ---------------------------------------------------------------------------
// Sliding-window attention with fused RoPE and fused [hi|lo] fp16 output.
// Inner products on packed fp32 (fma.rn.f32x2) — numerically exact fp32.
// ---------------------------------------------------------------------------
#define ATTN_SMEM_FLOATS (64*68 + 64*200 + 192*68 + 64*200 + 64 + 192)
#define ATTN_SMEM_BYTES  (ATTN_SMEM_FLOATS * 4)

__global__ void __launch_bounds__(256, 1)
attn_kernel(const float* __restrict__ qkv, const int* __restrict__ amask,
            const float* __restrict__ tab, __half* __restrict__ attnx)
{
    extern __shared__ __align__(16) float sm[];
    float* Qt = sm;                    // [64][68]  d-major (post-rope)
    float* Kt = Qt + 64*68;            // [64][200] d-major (post-rope)
    float* Vs = Kt + 64*200;           // [192][68]
    float* Ps = Vs + 192*68;           // [64][200]
    float* Rs = Ps + 64*200;           // [64]
    int*   Ms = (int*)(Rs + 64);       // [192]

    const int tid = threadIdx.x;
    const int qb = blockIdx.x, h = blockIdx.y, b = blockIdx.z;
    const int q0 = qb * 64;
    const int ks = max(0, q0 - WIN);
    const int ke = min(TT, q0 + 64 + WIN);
    const int klen = ke - ks;
    const float* qbase = qkv + (size_t)b * TT * TD3;

    // ---- Q: load + rope + transpose ----
#pragma unroll
    for (int it = 0; it < 2; it++) {
        int item = tid + it * 256;
        int row = item & 63, j4 = item >> 6;
        int t = q0 + row;
        const float* src = qbase + (size_t)t * TD3 + h * HD;
        float4 x0 = *(const float4*)(src + j4 * 4);
        float4 x1 = *(const float4*)(src + j4 * 4 + 32);
        const float4* tb = (const float4*)(tab + (size_t)t * 64 + j4 * 8);
        float4 t0 = tb[0], t1 = tb[1];
        float* q = Qt + j4 * 8 * 68 + row;
        q[0*68] = x0.x*t0.x - x1.x*t0.y;  q[1*68] = x0.x*t0.y + x1.x*t0.x;
        q[2*68] = x0.y*t0.z - x1.y*t0.w;  q[3*68] = x0.y*t0.w + x1.y*t0.z;
        q[4*68] = x0.z*t1.x - x1.z*t1.y;  q[5*68] = x0.z*t1.y + x1.z*t1.x;
        q[6*68] = x0.w*t1.z - x1.w*t1.w;  q[7*68] = x0.w*t1.w + x1.w*t1.z;
    }
    // ---- K: load + rope + transpose ----
#pragma unroll
    for (int it = 0; it < 6; it++) {
        int item = tid + it * 256;
        int kk = item % 192, j4 = item / 192;
        if (kk < klen) {
            int t = ks + kk;
            const float* src = qbase + (size_t)t * TD3 + DD + h * HD;
            float4 x0 = *(const float4*)(src + j4 * 4);
            float4 x1 = *(const float4*)(src + j4 * 4 + 32);
            const float4* tb = (const float4*)(tab + (size_t)t * 64 + j4 * 8);
            float4 t0 = tb[0], t1 = tb[1];
            float* k = Kt + j4 * 8 * 200 + kk;
            k[0*200] = x0.x*t0.x - x1.x*t0.y;  k[1*200] = x0.x*t0.y + x1.x*t0.x;
            k[2*200] = x0.y*t0.z - x1.y*t0.w;  k[3*200] = x0.y*t0.w + x1.y*t0.z;
            k[4*200] = x0.z*t1.x - x1.z*t1.y;  k[5*200] = x0.z*t1.y + x1.z*t1.x;
            k[6*200] = x0.w*t1.z - x1.w*t1.w;  k[7*200] = x0.w*t1.w + x1.w*t1.z;
        }
    }
    // ---- V direct ----
#pragma unroll
    for (int it = 0; it < 12; it++) {
        int idx = tid + it * 256;
        int kk = idx >> 4, d4 = idx & 15;
        if (kk < klen) {
            float4 v = *(const float4*)(qbase + (size_t)(ks+kk)*TD3 + 2*DD + h*HD + d4*4);
            *(float4*)&Vs[kk*68 + d4*4] = v;
        }
    }
    if (tid < 192) Ms[tid] = (tid < klen) ? amask[b*TT + ks + tid] : 0;
    __syncthreads();

    // ---- scores: each thread 4q x 12k via f32x2 (6 packed k-pairs) ----
    const int tx = tid & 15;
    const int ty = tid >> 4;
    u64 s2[4][6];
#pragma unroll
    for (int qi = 0; qi < 4; qi++)
#pragma unroll
        for (int p = 0; p < 6; p++) s2[qi][p] = 0ull;

    for (int d = 0; d < 64; d++) {
        float4 aq = *(const float4*)&Qt[d*68 + ty*4];
        // Kt row base 16B-aligned: tx*12 floats = 48B; load 3 x ulonglong2
        const ulonglong2* kb = (const ulonglong2*)&Kt[d*200 + tx*12];
        ulonglong2 p01 = kb[0], p23 = kb[1], p45 = kb[2];
        u64 bp[6] = { p01.x, p01.y, p23.x, p23.y, p45.x, p45.y };
        u64 ad[4] = { pk2(aq.x,aq.x), pk2(aq.y,aq.y), pk2(aq.z,aq.z), pk2(aq.w,aq.w) };
#pragma unroll
        for (int qi = 0; qi < 4; qi++)
#pragma unroll
            for (int p = 0; p < 6; p++)
                s2[qi][p] = fma2(ad[qi], bp[p], s2[qi][p]);
    }
    float s[4][12];
#pragma unroll
    for (int qi = 0; qi < 4; qi++)
#pragma unroll
        for (int p = 0; p < 6; p++) {
            float2 f = up2(s2[qi][p]);
            s[qi][2*p] = f.x; s[qi][2*p+1] = f.y;
        }

    const float scale = 0.125f;
#pragma unroll
    for (int qi = 0; qi < 4; qi++) {
        int qg = q0 + ty*4 + qi;
        bool ok[12];
        float mx = -1e30f;
#pragma unroll
        for (int ki = 0; ki < 12; ki++) {
            int kk = tx*12 + ki;
            int kg = ks + kk;
            ok[ki] = (kk < klen) && (abs(qg - kg) <= WIN) && (Ms[kk] != 0);
            float sv = s[qi][ki] * scale;
            s[qi][ki] = sv;
            if (ok[ki]) mx = fmaxf(mx, sv);
        }
#pragma unroll
        for (int off = 8; off; off >>= 1)
            mx = fmaxf(mx, __shfl_xor_sync(0xffffffffu, mx, off));
        float sum = 0.f;
#pragma unroll
        for (int ki = 0; ki < 12; ki++) {
            float p = ok[ki] ? __expf(s[qi][ki] - mx) : 0.f;
            s[qi][ki] = p;
            sum += p;
        }
#pragma unroll
        for (int off = 8; off; off >>= 1)
            sum += __shfl_xor_sync(0xffffffffu, sum, off);
#pragma unroll
        for (int ki = 0; ki < 12; ki++)
            Ps[(ty*4+qi)*200 + tx*12 + ki] = s[qi][ki];
        if (tx == 0) Rs[ty*4 + qi] = sum;
    }
    __syncthreads();

    // ---- PV: each thread 4q x 4d via f32x2 (2 packed d-pairs) ----
    const int tx2 = tid & 15;
    const int ty2 = tid >> 4;
    u64 o2[4][2];
#pragma unroll
    for (int qi = 0; qi < 4; qi++) { o2[qi][0] = 0ull; o2[qi][1] = 0ull; }

    for (int k = 0; k < klen; k++) {
        // Vs row base 16B-aligned: k*68 floats = 272B, tx2*4 floats = 16B
        ulonglong2 vp = *(const ulonglong2*)&Vs[k*68 + tx2*4];
        u64 pd[4];
#pragma unroll
        for (int qi = 0; qi < 4; qi++) {
            float pq = Ps[(ty2*4+qi)*200 + k];
            pd[qi] = pk2(pq, pq);
        }
#pragma unroll
        for (int qi = 0; qi < 4; qi++) {
            o2[qi][0] = fma2(pd[qi], vp.x, o2[qi][0]);
            o2[qi][1] = fma2(pd[qi], vp.y, o2[qi][1]);
        }
    }
    // ---- epilogue: normalize + write [hi|lo] fp16 operand for Wo GEMM ----
#pragma unroll
    for (int qi = 0; qi < 4; qi++) {
        float r = 1.f / fmaxf(Rs[ty2*4 + qi], 1e-30f);
        float2 f0 = up2(o2[qi][0]), f1 = up2(o2[qi][1]);
        float v0 = f0.x*r, v1 = f0.y*r, v2 = f1.x*r, v3 = f1.y*r;
        __half h0 = __float2half_rn(v0), h1 = __float2half_rn(v1);
        __half h2 = __float2half_rn(v2), h3 = __float2half_rn(v3);
        __half l0 = __float2half_rn(v0 - __half2float(h0));
        __half l1 = __float2half_rn(v1 - __half2float(h1));
        __half l2 = __float2half_rn(v2 - __half2float(h2));
        __half l3 = __float2half_rn(v3 - __half2float(h3));
        uint2 hu = make_uint2(
            (uint32_t)__half_as_ushort(h0) | ((uint32_t)__half_as_ushort(h1) << 16),
            (uint32_t)__half_as_ushort(h2) | ((uint32_t)__half_as_ushort(h3) << 16));
        uint2 lu = make_uint2(
            (uint32_t)__half_as_ushort(l0) | ((uint32_t)__half_as_ushort(l1) << 16),
            (uint32_t)__half_as_ushort(l2) | ((uint32_t)__half_as_ushort(l3) << 16));
        __half* dst = attnx + (size_t)(b*TT + q0 + ty2*4 + qi) * KA + h*HD + tx2*4;
        *(uint2*)(dst)      = hu;
        *(uint2*)(dst + KB) = lu;
    }
}

// ---------------------------------------------------------------------------
extern "C" void kernel_launch(void* const* d_in, const int* in_sizes, int n_in,
                              void* d_out, int out_size)
{
    const float* hs   = (const float*)d_in[0];
    const int*   am   = (const int*)d_in[1];
    const float* Wqkv = (const float*)d_in[2];
    const float* Wo   = (const float*)d_in[3];
    float* out = (float*)d_out;

    void* p;
    cudaGetSymbolAddress(&p, g_qkv);   float*  qkv   = (float*)p;
    cudaGetSymbolAddress(&p, g_ah);    __half* ah    = (__half*)p;
    cudaGetSymbolAddress(&p, g_attnx); __half* attnx = (__half*)p;
    cudaGetSymbolAddress(&p, g_wqkvh); __half* wqkvh = (__half*)p;
    cudaGetSymbolAddress(&p, g_woh);   __half* woh   = (__half*)p;
    cudaGetSymbolAddress(&p, g_tab);   float*  tab   = (float*)p;

    cudaFuncSetAttribute(attn_kernel,
                         cudaFuncAttributeMaxDynamicSharedMemorySize,
                         ATTN_SMEM_BYTES);
    cudaFuncSetAttribute(gemm_mma,
                         cudaFuncAttributeMaxDynamicSharedMemorySize,
                         GEMM_SMEM);

    const int M = BB * TT;                 // 8192

    // 1) weights -> fp16 (both)
    conv_w<<<((TD3*DD + DD*DD)/4 + 255)/256, 256>>>(Wqkv, Wo, wqkvh, woh);

    // 2) rope table
    tab_kernel<<<(TT*32)/256, 256>>>(tab);

    // 3) hidden states -> [hi|lo] fp16
    expand_a<<<(M*(DD/4) + 255)/256, 256>>>(hs, ah, M);

    // 4) QKV projection
    gemm_mma<<<dim3(TD3/128, M/128), 256, GEMM_SMEM>>>(ah, wqkvh, qkv, TD3);

    // 5) attention (rope fused, f32x2 math, writes [hi|lo] fp16)
    dim3 ga(TT/64, NH, BB);
    attn_kernel<<<ga, 256, ATTN_SMEM_BYTES>>>(qkv, am, tab, attnx);

    // 6) output projection
    gemm_mma<<<dim3(DD/128, M/128), 256, GEMM_SMEM>>>(attnx, woh, out, DD);
}

// round 8
// speedup vs baseline: 4.6145x; 1.3473x over previous
#include <cuda_runtime.h>
#include <cuda_fp16.h>
#include <math.h>
#include <stdint.h>

#define BB 4
#define TT 2048
#define DD 768
#define NH 12
#define HD 64
#define WIN 64
#define TD3 (3*DD)
#define KK 768             // GEMM K (plain fp16 both operands)
#define KC 64              // k per pipeline chunk
#define NC (KK/KC)         // 12 chunks
#define PS 3               // pipeline stages
#define LDT 72             // padded smem row (fp16 elems) -> 144 bytes
#define TILE_BYTES (128*LDT*2)          // 18432 per operand tile
#define STAGE_BYTES (2*TILE_BYTES)      // 36864
#define GEMM_SMEM (PS*STAGE_BYTES)      // 110592

// ---------------- scratch (device globals: allocation-free rule) -----------
__device__ float  g_qkv[(size_t)BB*TT*TD3];          // [B,T,3D] fp32 (pre-rope)
__device__ __half g_ah  [(size_t)BB*TT*KK];          // hidden fp16
__device__ __half g_attnx[(size_t)BB*TT*KK];         // attn out fp16
__device__ __half g_wqkvh[(size_t)TD3*KK];           // Wqkv fp16
__device__ __half g_woh [(size_t)DD*KK];             // Wo fp16
__device__ float  g_tab [(size_t)TT*64];             // rope (cos,sin) pairs [t][j]

typedef unsigned long long u64;

// ---------------- PTX helpers (baseline ISA only) ---------------------------
__device__ __forceinline__ uint32_t smem_u32(const void* p){
    uint32_t a;
    asm("{ .reg .u64 t; cvta.to.shared.u64 t, %1; cvt.u32.u64 %0, t; }"
        : "=r"(a) : "l"(p));
    return a;
}
__device__ __forceinline__ void cp16(uint32_t d, const void* s){
    asm volatile("cp.async.cg.shared.global [%0], [%1], 16;"
                 :: "r"(d), "l"(s) : "memory");
}
__device__ __forceinline__ void cp_commit(){
    asm volatile("cp.async.commit_group;" ::: "memory");
}
template<int N>
__device__ __forceinline__ void cp_wait(){
    asm volatile("cp.async.wait_group %0;" :: "n"(N) : "memory");
}
__device__ __forceinline__ void ldsm_x4(uint32_t &r0,uint32_t &r1,uint32_t &r2,uint32_t &r3,
                                        uint32_t addr){
    asm volatile("ldmatrix.sync.aligned.m8n8.x4.shared.b16 {%0,%1,%2,%3}, [%4];"
                 : "=r"(r0),"=r"(r1),"=r"(r2),"=r"(r3) : "r"(addr));
}
__device__ __forceinline__ void ldsm_x2(uint32_t &r0,uint32_t &r1, uint32_t addr){
    asm volatile("ldmatrix.sync.aligned.m8n8.x2.shared.b16 {%0,%1}, [%2];"
                 : "=r"(r0),"=r"(r1) : "r"(addr));
}
__device__ __forceinline__ void mma16816(float* d, const uint32_t* a, const uint32_t* b){
    asm volatile("mma.sync.aligned.m16n8k16.row.col.f32.f16.f16.f32 "
        "{%0,%1,%2,%3}, {%4,%5,%6,%7}, {%8,%9}, {%0,%1,%2,%3};"
        : "+f"(d[0]),"+f"(d[1]),"+f"(d[2]),"+f"(d[3])
        : "r"(a[0]),"r"(a[1]),"r"(a[2]),"r"(a[3]), "r"(b[0]),"r"(b[1]));
}
// packed fp32 pair ops (Blackwell f32x2 — exact fp32 FMA, double width)
__device__ __forceinline__ u64 pk2(float lo, float hi){
    u64 r; asm("mov.b64 %0,{%1,%2};" : "=l"(r) : "f"(lo), "f"(hi)); return r;
}
__device__ __forceinline__ u64 fma2(u64 a, u64 b, u64 c){
    u64 d; asm("fma.rn.f32x2 %0,%1,%2,%3;" : "=l"(d) : "l"(a), "l"(b), "l"(c)); return d;
}
__device__ __forceinline__ float2 up2(u64 v){
    float2 f; asm("mov.b64 {%0,%1},%2;" : "=f"(f.x), "=f"(f.y) : "l"(v)); return f;
}

// ---------------------------------------------------------------------------
// fp32 -> fp16 conversion (weights + hidden states, one launch each region).
// ---------------------------------------------------------------------------
__global__ void conv_all(const float* __restrict__ wqkv, const float* __restrict__ wo,
                         const float* __restrict__ hs,
                         __half* __restrict__ wqkvh, __half* __restrict__ woh,
                         __half* __restrict__ ah)
{
    const int n1 = TD3*DD/4;
    const int n2 = DD*DD/4;
    const int n3 = BB*TT*DD/4;
    int idx = blockIdx.x * blockDim.x + threadIdx.x;
    if (idx >= n1 + n2 + n3) return;
    const float* src; __half* dst; int i;
    if (idx < n1)            { src = wqkv; dst = wqkvh; i = idx; }
    else if (idx < n1 + n2)  { src = wo;   dst = woh;   i = idx - n1; }
    else                     { src = hs;   dst = ah;    i = idx - n1 - n2; }
    float4 v = *(const float4*)(src + (size_t)i*4);
    ushort4 u;
    u.x = __half_as_ushort(__float2half_rn(v.x));
    u.y = __half_as_ushort(__float2half_rn(v.y));
    u.z = __half_as_ushort(__float2half_rn(v.z));
    u.w = __half_as_ushort(__float2half_rn(v.w));
    uint2 o = make_uint2((uint32_t)u.x | ((uint32_t)u.y << 16),
                         (uint32_t)u.z | ((uint32_t)u.w << 16));
    *(uint2*)(dst + (size_t)i*4) = o;
}

// ---------------------------------------------------------------------------
// RoPE table: g_tab[t*64 + 2j] = cos(t * 10000^(-j/32)), [.. +1] = sin.
// ---------------------------------------------------------------------------
__global__ void tab_kernel(float* __restrict__ tab)
{
    int idx = blockIdx.x * blockDim.x + threadIdx.x;   // TT*32
    int t = idx >> 5, j = idx & 31;
    const float c0 = 0.41524101186092029f;             // log2(10000)/32
    float inv = exp2f(-c0 * (float)j);
    float sn, cs;
    sincosf((float)t * inv, &sn, &cs);
    tab[t*64 + 2*j]     = cs;
    tab[t*64 + 2*j + 1] = sn;
}

// ---------------------------------------------------------------------------
// HMMA GEMM: C[m,n] = sum_{k<768} A[m,k] * B[n,k]   (fp16 -> fp32)
// 128x128 CTA tile, 8 warps (2x4), warp tile 64x32.
// KC=64 per stage, 3-stage cp.async pipeline (12 iters).
// ---------------------------------------------------------------------------
__global__ void __launch_bounds__(256, 2)
gemm_mma(const __half* __restrict__ A, const __half* __restrict__ B,
         float* __restrict__ C, int N)
{
    extern __shared__ __align__(16) char smem[];
    const uint32_t sb = smem_u32(smem);
    const int tid  = threadIdx.x;
    const int lane = tid & 31;
    const int warp = tid >> 5;
    const int bm = blockIdx.y * 128;
    const int bn = blockIdx.x * 128;
    const int wm = warp & 1;
    const int wn = warp >> 1;

    const __half* asp[4]; uint32_t adf[4];
    const __half* bsp[4]; uint32_t bdf[4];
#pragma unroll
    for (int h = 0; h < 4; h++) {
        int idx = tid + h * 256;       // 0..1023
        int row = idx >> 3, seg = idx & 7;
        asp[h] = A + (size_t)(bm + row) * KK + seg * 8;
        bsp[h] = B + (size_t)(bn + row) * KK + seg * 8;
        adf[h] = (uint32_t)(row * (LDT*2) + seg * 16);
        bdf[h] = adf[h] + TILE_BYTES;
    }

#pragma unroll
    for (int s = 0; s < PS - 1; s++) {
        uint32_t st = sb + s * STAGE_BYTES;
#pragma unroll
        for (int h = 0; h < 4; h++) {
            cp16(st + adf[h], asp[h] + s * KC);
            cp16(st + bdf[h], bsp[h] + s * KC);
        }
        cp_commit();
    }

    float acc[4][4][4];
#pragma unroll
    for (int mi = 0; mi < 4; mi++)
#pragma unroll
        for (int ni = 0; ni < 4; ni++)
#pragma unroll
            for (int r = 0; r < 4; r++) acc[mi][ni][r] = 0.f;

    const uint32_t a_row = (uint32_t)(wm * 64 + (lane & 15));
    const uint32_t a_colb = (uint32_t)((lane >> 4) * 16);
    const uint32_t b_row = (uint32_t)(wn * 32 + (lane & 7));
    const uint32_t b_colb = (uint32_t)(((lane >> 3) & 1) * 16);

    for (int i = 0; i < NC; i++) {
        cp_wait<PS - 2>();
        __syncthreads();

        int nc = i + PS - 1;
        if (nc < NC) {
            uint32_t st = sb + (nc % PS) * STAGE_BYTES;
#pragma unroll
            for (int h = 0; h < 4; h++) {
                cp16(st + adf[h], asp[h] + nc * KC);
                cp16(st + bdf[h], bsp[h] + nc * KC);
            }
        }
        cp_commit();

        uint32_t st = sb + (i % PS) * STAGE_BYTES;
#pragma unroll
        for (int ks = 0; ks < 4; ks++) {
            uint32_t a[4][4], b[4][2];
#pragma unroll
            for (int mi = 0; mi < 4; mi++) {
                uint32_t addr = st + (a_row + mi * 16) * (LDT*2) + ks * 32 + a_colb;
                ldsm_x4(a[mi][0], a[mi][1], a[mi][2], a[mi][3], addr);
            }
#pragma unroll
            for (int ni = 0; ni < 4; ni++) {
                uint32_t addr = st + TILE_BYTES + (b_row + ni * 8) * (LDT*2)
                              + ks * 32 + b_colb;
                ldsm_x2(b[ni][0], b[ni][1], addr);
            }
#pragma unroll
            for (int mi = 0; mi < 4; mi++)
#pragma unroll
                for (int ni = 0; ni < 4; ni++)
                    mma16816(acc[mi][ni], a[mi], b[ni]);
        }
    }

    const int g = lane >> 2, t = lane & 3;
#pragma unroll
    for (int mi = 0; mi < 4; mi++) {
        int m0 = bm + wm * 64 + mi * 16 + g;
#pragma unroll
        for (int ni = 0; ni < 4; ni++) {
            int n0 = bn + wn * 32 + ni * 8 + 2 * t;
            *(float2*)&C[(size_t)m0 * N + n0] =
                make_float2(acc[mi][ni][0], acc[mi][ni][1]);
            *(float2*)&C[(size_t)(m0 + 8) * N + n0] =
                make_float2(acc[mi][ni][2], acc[mi][ni][3]);
        }
    }
}

// ---------------------------------------------------------------------------
// Sliding-window attention with fused RoPE and fp16 output for Wo GEMM.
// Inner products on packed fp32 (fma.rn.f32x2).
// ---------------------------------------------------------------------------
#define ATTN_SMEM_FLOATS (64*68 + 64*200 + 192*68 + 64*200 + 64 + 192)
#define ATTN_SMEM_BYTES  (ATTN_SMEM_FLOATS * 4)

__global__ void __launch_bounds__(256, 1)
attn_kernel(const float* __restrict__ qkv, const int* __restrict__ amask,
            const float* __restrict__ tab, __half* __restrict__ attnx)
{
    extern __shared__ __align__(16) float sm[];
    float* Qt = sm;                    // [64][68]  d-major (post-rope)
    float* Kt = Qt + 64*68;            // [64][200] d-major (post-rope)
    float* Vs = Kt + 64*200;           // [192][68]
    float* Ps = Vs + 192*68;           // [64][200]
    float* Rs = Ps + 64*200;           // [64]
    int*   Ms = (int*)(Rs + 64);       // [192]

    const int tid = threadIdx.x;
    const int qb = blockIdx.x, h = blockIdx.y, b = blockIdx.z;
    const int q0 = qb * 64;
    const int ks = max(0, q0 - WIN);
    const int ke = min(TT, q0 + 64 + WIN);
    const int klen = ke - ks;
    const float* qbase = qkv + (size_t)b * TT * TD3;

    // ---- Q: load + rope + transpose ----
#pragma unroll
    for (int it = 0; it < 2; it++) {
        int item = tid + it * 256;
        int row = item & 63, j4 = item >> 6;
        int t = q0 + row;
        const float* src = qbase + (size_t)t * TD3 + h * HD;
        float4 x0 = *(const float4*)(src + j4 * 4);
        float4 x1 = *(const float4*)(src + j4 * 4 + 32);
        const float4* tb = (const float4*)(tab + (size_t)t * 64 + j4 * 8);
        float4 t0 = tb[0], t1 = tb[1];
        float* q = Qt + j4 * 8 * 68 + row;
        q[0*68] = x0.x*t0.x - x1.x*t0.y;  q[1*68] = x0.x*t0.y + x1.x*t0.x;
        q[2*68] = x0.y*t0.z - x1.y*t0.w;  q[3*68] = x0.y*t0.w + x1.y*t0.z;
        q[4*68] = x0.z*t1.x - x1.z*t1.y;  q[5*68] = x0.z*t1.y + x1.z*t1.x;
        q[6*68] = x0.w*t1.z - x1.w*t1.w;  q[7*68] = x0.w*t1.w + x1.w*t1.z;
    }
    // ---- K: load + rope + transpose ----
#pragma unroll
    for (int it = 0; it < 6; it++) {
        int item = tid + it * 256;
        int kk = item % 192, j4 = item / 192;
        if (kk < klen) {
            int t = ks + kk;
            const float* src = qbase + (size_t)t * TD3 + DD + h * HD;
            float4 x0 = *(const float4*)(src + j4 * 4);
            float4 x1 = *(const float4*)(src + j4 * 4 + 32);
            const float4* tb = (const float4*)(tab + (size_t)t * 64 + j4 * 8);
            float4 t0 = tb[0], t1 = tb[1];
            float* k = Kt + j4 * 8 * 200 + kk;
            k[0*200] = x0.x*t0.x - x1.x*t0.y;  k[1*200] = x0.x*t0.y + x1.x*t0.x;
            k[2*200] = x0.y*t0.z - x1.y*t0.w;  k[3*200] = x0.y*t0.w + x1.y*t0.z;
            k[4*200] = x0.z*t1.x - x1.z*t1.y;  k[5*200] = x0.z*t1.y + x1.z*t1.x;
            k[6*200] = x0.w*t1.z - x1.w*t1.w;  k[7*200] = x0.w*t1.w + x1.w*t1.z;
        }
    }
    // ---- V direct ----
#pragma unroll
    for (int it = 0; it < 12; it++) {
        int idx = tid + it * 256;
        int kk = idx >> 4, d4 = idx & 15;
        if (kk < klen) {
            float4 v = *(const float4*)(qbase + (size_t)(ks+kk)*TD3 + 2*DD + h*HD + d4*4);
            *(float4*)&Vs[kk*68 + d4*4] = v;
        }
    }
    if (tid < 192) Ms[tid] = (tid < klen) ? amask[b*TT + ks + tid] : 0;
    __syncthreads();

    // ---- scores: each thread 4q x 12k via f32x2 (6 packed k-pairs) ----
    const int tx = tid & 15;
    const int ty = tid >> 4;
    u64 s2[4][6];
#pragma unroll
    for (int qi = 0; qi < 4; qi++)
#pragma unroll
        for (int p = 0; p < 6; p++) s2[qi][p] = 0ull;

    for (int d = 0; d < 64; d++) {
        float4 aq = *(const float4*)&Qt[d*68 + ty*4];
        const ulonglong2* kb = (const ulonglong2*)&Kt[d*200 + tx*12];
        ulonglong2 p01 = kb[0], p23 = kb[1], p45 = kb[2];
        u64 bp[6] = { p01.x, p01.y, p23.x, p23.y, p45.x, p45.y };
        u64 ad[4] = { pk2(aq.x,aq.x), pk2(aq.y,aq.y), pk2(aq.z,aq.z), pk2(aq.w,aq.w) };
#pragma unroll
        for (int qi = 0; qi < 4; qi++)
#pragma unroll
            for (int p = 0; p < 6; p++)
                s2[qi][p] = fma2(ad[qi], bp[p], s2[qi][p]);
    }
    float s[4][12];
#pragma unroll
    for (int qi = 0; qi < 4; qi++)
#pragma unroll
        for (int p = 0; p < 6; p++) {
            float2 f = up2(s2[qi][p]);
            s[qi][2*p] = f.x; s[qi][2*p+1] = f.y;
        }

    const float scale = 0.125f;
#pragma unroll
    for (int qi = 0; qi < 4; qi++) {
        int qg = q0 + ty*4 + qi;
        bool ok[12];
        float mx = -1e30f;
#pragma unroll
        for (int ki = 0; ki < 12; ki++) {
            int kk = tx*12 + ki;
            int kg = ks + kk;
            ok[ki] = (kk < klen) && (abs(qg - kg) <= WIN) && (Ms[kk] != 0);
            float sv = s[qi][ki] * scale;
            s[qi][ki] = sv;
            if (ok[ki]) mx = fmaxf(mx, sv);
        }
#pragma unroll
        for (int off = 8; off; off >>= 1)
            mx = fmaxf(mx, __shfl_xor_sync(0xffffffffu, mx, off));
        float sum = 0.f;
#pragma unroll
        for (int ki = 0; ki < 12; ki++) {
            float p = ok[ki] ? __expf(s[qi][ki] - mx) : 0.f;
            s[qi][ki] = p;
            sum += p;
        }
#pragma unroll
        for (int off = 8; off; off >>= 1)
            sum += __shfl_xor_sync(0xffffffffu, sum, off);
#pragma unroll
        for (int ki = 0; ki < 12; ki++)
            Ps[(ty*4+qi)*200 + tx*12 + ki] = s[qi][ki];
        if (tx == 0) Rs[ty*4 + qi] = sum;
    }
    __syncthreads();

    // ---- PV: each thread 4q x 4d via f32x2 (2 packed d-pairs) ----
    const int tx2 = tid & 15;
    const int ty2 = tid >> 4;
    u64 o2[4][2];
#pragma unroll
    for (int qi = 0; qi < 4; qi++) { o2[qi][0] = 0ull; o2[qi][1] = 0ull; }

    for (int k = 0; k < klen; k++) {
        ulonglong2 vp = *(const ulonglong2*)&Vs[k*68 + tx2*4];
        u64 pd[4];
#pragma unroll
        for (int qi = 0; qi < 4; qi++) {
            float pq = Ps[(ty2*4+qi)*200 + k];
            pd[qi] = pk2(pq, pq);
        }
#pragma unroll
        for (int qi = 0; qi < 4; qi++) {
            o2[qi][0] = fma2(pd[qi], vp.x, o2[qi][0]);
            o2[qi][1] = fma2(pd[qi], vp.y, o2[qi][1]);
        }
    }
    // ---- epilogue: normalize + write fp16 operand for Wo GEMM ----
#pragma unroll
    for (int qi = 0; qi < 4; qi++) {
        float r = 1.f / fmaxf(Rs[ty2*4 + qi], 1e-30f);
        float2 f0 = up2(o2[qi][0]), f1 = up2(o2[qi][1]);
        __half h0 = __float2half_rn(f0.x*r), h1 = __float2half_rn(f0.y*r);
        __half h2 = __float2half_rn(f1.x*r), h3 = __float2half_rn(f1.y*r);
        uint2 hu = make_uint2(
            (uint32_t)__half_as_ushort(h0) | ((uint32_t)__half_as_ushort(h1) << 16),
            (uint32_t)__half_as_ushort(h2) | ((uint32_t)__half_as_ushort(h3) << 16));
        __half* dst = attnx + (size_t)(b*TT + q0 + ty2*4 + qi) * KK + h*HD + tx2*4;
        *(uint2*)(dst) = hu;
    }
}

// ---------------------------------------------------------------------------
extern "C" void kernel_launch(void* const* d_in, const int* in_sizes, int n_in,
                              void* d_out, int out_size)
{
    const float* hs   = (const float*)d_in[0];
    const int*   am   = (const int*)d_in[1];
    const float* Wqkv = (const float*)d_in[2];
    const float* Wo   = (const float*)d_in[3];
    float* out = (float*)d_out;

    void* p;
    cudaGetSymbolAddress(&p, g_qkv);   float*  qkv   = (float*)p;
    cudaGetSymbolAddress(&p, g_ah);    __half* ah    = (__half*)p;
    cudaGetSymbolAddress(&p, g_attnx); __half* attnx = (__half*)p;
    cudaGetSymbolAddress(&p, g_wqkvh); __half* wqkvh = (__half*)p;
    cudaGetSymbolAddress(&p, g_woh);   __half* woh   = (__half*)p;
    cudaGetSymbolAddress(&p, g_tab);   float*  tab   = (float*)p;

    cudaFuncSetAttribute(attn_kernel,
                         cudaFuncAttributeMaxDynamicSharedMemorySize,
                         ATTN_SMEM_BYTES);
    cudaFuncSetAttribute(gemm_mma,
                         cudaFuncAttributeMaxDynamicSharedMemorySize,
                         GEMM_SMEM);

    const int M = BB * TT;                 // 8192

    // 1) fp32 -> fp16: weights + hidden states
    conv_all<<<((TD3*DD + DD*DD + M*DD)/4 + 255)/256, 256>>>(
        Wqkv, Wo, hs, wqkvh, woh, ah);

    // 2) rope table
    tab_kernel<<<(TT*32)/256, 256>>>(tab);

    // 3) QKV projection
    gemm_mma<<<dim3(TD3/128, M/128), 256, GEMM_SMEM>>>(ah, wqkvh, qkv, TD3);

    // 4) attention (rope fused, f32x2 math, writes fp16)
    dim3 ga(TT/64, NH, BB);
    attn_kernel<<<ga, 256, ATTN_SMEM_BYTES>>>(qkv, am, tab, attnx);

    // 5) output projection
    gemm_mma<<<dim3(DD/128, M/128), 256, GEMM_SMEM>>>(attnx, woh, out, DD);
}

// round 9
// speedup vs baseline: 5.1475x; 1.1155x over previous
#include <cuda_runtime.h>
#include <cuda_fp16.h>
#include <math.h>
#include <stdint.h>

#define BB 4
#define TT 2048
#define DD 768
#define NH 12
#define HD 64
#define WIN 64
#define TD3 (3*DD)
#define KK 768             // GEMM K (plain fp16 both operands)
#define KC 64              // k per pipeline chunk
#define NC (KK/KC)         // 12 chunks
#define PS 3               // pipeline stages
#define LDT 72             // padded smem row (fp16 elems) -> 144 bytes
#define TILE_BYTES (128*LDT*2)          // 18432 per operand tile
#define STAGE_BYTES (2*TILE_BYTES)      // 36864
#define GEMM_SMEM (PS*STAGE_BYTES)      // 110592

// attention smem layout (bytes)
#define PS_OFF   0                       // Ps fp32 [64][200]
#define VS_OFF   51200                   // Vs fp32 [192][68]
#define QH_OFF   103424                  // Qh fp16 [64][136]  ([hi|lo]+pad)
#define KH_OFF   120832                  // Kh fp16 [192][72]
#define PMAX_OFF 148480                  // fp32 [4][64]
#define PSUM_OFF 149504                  // fp32 [4][64]
#define MS_OFF   150528                  // int  [192]
#define ATTN_SMEM_BYTES 151296

// ---------------- scratch (device globals: allocation-free rule) -----------
__device__ float  g_qkv[(size_t)BB*TT*TD3];          // [B,T,3D] fp32 (pre-rope)
__device__ __half g_ah  [(size_t)BB*TT*KK];          // hidden fp16
__device__ __half g_attnx[(size_t)BB*TT*KK];         // attn out fp16
__device__ __half g_wqkvh[(size_t)TD3*KK];           // Wqkv fp16
__device__ __half g_woh [(size_t)DD*KK];             // Wo fp16
__device__ float  g_tab [(size_t)TT*64];             // rope (cos,sin) pairs [t][j]

typedef unsigned long long u64;

// ---------------- PTX helpers (baseline ISA only) ---------------------------
__device__ __forceinline__ uint32_t smem_u32(const void* p){
    uint32_t a;
    asm("{ .reg .u64 t; cvta.to.shared.u64 t, %1; cvt.u32.u64 %0, t; }"
        : "=r"(a) : "l"(p));
    return a;
}
__device__ __forceinline__ void cp16(uint32_t d, const void* s){
    asm volatile("cp.async.cg.shared.global [%0], [%1], 16;"
                 :: "r"(d), "l"(s) : "memory");
}
__device__ __forceinline__ void cp_commit(){
    asm volatile("cp.async.commit_group;" ::: "memory");
}
template<int N>
__device__ __forceinline__ void cp_wait(){
    asm volatile("cp.async.wait_group %0;" :: "n"(N) : "memory");
}
__device__ __forceinline__ void ldsm_x4(uint32_t &r0,uint32_t &r1,uint32_t &r2,uint32_t &r3,
                                        uint32_t addr){
    asm volatile("ldmatrix.sync.aligned.m8n8.x4.shared.b16 {%0,%1,%2,%3}, [%4];"
                 : "=r"(r0),"=r"(r1),"=r"(r2),"=r"(r3) : "r"(addr));
}
__device__ __forceinline__ void ldsm_x2(uint32_t &r0,uint32_t &r1, uint32_t addr){
    asm volatile("ldmatrix.sync.aligned.m8n8.x2.shared.b16 {%0,%1}, [%2];"
                 : "=r"(r0),"=r"(r1) : "r"(addr));
}
__device__ __forceinline__ void mma16816(float* d, const uint32_t* a, const uint32_t* b){
    asm volatile("mma.sync.aligned.m16n8k16.row.col.f32.f16.f16.f32 "
        "{%0,%1,%2,%3}, {%4,%5,%6,%7}, {%8,%9}, {%0,%1,%2,%3};"
        : "+f"(d[0]),"+f"(d[1]),"+f"(d[2]),"+f"(d[3])
        : "r"(a[0]),"r"(a[1]),"r"(a[2]),"r"(a[3]), "r"(b[0]),"r"(b[1]));
}
// packed fp32 pair ops (Blackwell f32x2 — exact fp32 FMA, double width)
__device__ __forceinline__ u64 pk2(float lo, float hi){
    u64 r; asm("mov.b64 %0,{%1,%2};" : "=l"(r) : "f"(lo), "f"(hi)); return r;
}
__device__ __forceinline__ u64 fma2(u64 a, u64 b, u64 c){
    u64 d; asm("fma.rn.f32x2 %0,%1,%2,%3;" : "=l"(d) : "l"(a), "l"(b), "l"(c)); return d;
}
__device__ __forceinline__ float2 up2(u64 v){
    float2 f; asm("mov.b64 {%0,%1},%2;" : "=f"(f.x), "=f"(f.y) : "l"(v)); return f;
}
__device__ __forceinline__ uint32_t packh2(__half a, __half b){
    return (uint32_t)__half_as_ushort(a) | ((uint32_t)__half_as_ushort(b) << 16);
}

// ---------------------------------------------------------------------------
// fp32 -> fp16 conversion (weights + hidden states).
// ---------------------------------------------------------------------------
__global__ void conv_all(const float* __restrict__ wqkv, const float* __restrict__ wo,
                         const float* __restrict__ hs,
                         __half* __restrict__ wqkvh, __half* __restrict__ woh,
                         __half* __restrict__ ah)
{
    const int n1 = TD3*DD/4;
    const int n2 = DD*DD/4;
    const int n3 = BB*TT*DD/4;
    int idx = blockIdx.x * blockDim.x + threadIdx.x;
    if (idx >= n1 + n2 + n3) return;
    const float* src; __half* dst; int i;
    if (idx < n1)            { src = wqkv; dst = wqkvh; i = idx; }
    else if (idx < n1 + n2)  { src = wo;   dst = woh;   i = idx - n1; }
    else                     { src = hs;   dst = ah;    i = idx - n1 - n2; }
    float4 v = *(const float4*)(src + (size_t)i*4);
    uint2 o = make_uint2(packh2(__float2half_rn(v.x), __float2half_rn(v.y)),
                         packh2(__float2half_rn(v.z), __float2half_rn(v.w)));
    *(uint2*)(dst + (size_t)i*4) = o;
}

// ---------------------------------------------------------------------------
// RoPE table: g_tab[t*64 + 2j] = cos(t * 10000^(-j/32)), [.. +1] = sin.
// ---------------------------------------------------------------------------
__global__ void tab_kernel(float* __restrict__ tab)
{
    int idx = blockIdx.x * blockDim.x + threadIdx.x;   // TT*32
    int t = idx >> 5, j = idx & 31;
    const float c0 = 0.41524101186092029f;             // log2(10000)/32
    float inv = exp2f(-c0 * (float)j);
    float sn, cs;
    sincosf((float)t * inv, &sn, &cs);
    tab[t*64 + 2*j]     = cs;
    tab[t*64 + 2*j + 1] = sn;
}

// ---------------------------------------------------------------------------
// HMMA GEMM: C[m,n] = sum_{k<768} A[m,k] * B[n,k]   (fp16 -> fp32)
// ---------------------------------------------------------------------------
__global__ void __launch_bounds__(256, 2)
gemm_mma(const __half* __restrict__ A, const __half* __restrict__ B,
         float* __restrict__ C, int N)
{
    extern __shared__ __align__(16) char smem[];
    const uint32_t sb = smem_u32(smem);
    const int tid  = threadIdx.x;
    const int lane = tid & 31;
    const int warp = tid >> 5;
    const int bm = blockIdx.y * 128;
    const int bn = blockIdx.x * 128;
    const int wm = warp & 1;
    const int wn = warp >> 1;

    const __half* asp[4]; uint32_t adf[4];
    const __half* bsp[4]; uint32_t bdf[4];
#pragma unroll
    for (int h = 0; h < 4; h++) {
        int idx = tid + h * 256;
        int row = idx >> 3, seg = idx & 7;
        asp[h] = A + (size_t)(bm + row) * KK + seg * 8;
        bsp[h] = B + (size_t)(bn + row) * KK + seg * 8;
        adf[h] = (uint32_t)(row * (LDT*2) + seg * 16);
        bdf[h] = adf[h] + TILE_BYTES;
    }

#pragma unroll
    for (int s = 0; s < PS - 1; s++) {
        uint32_t st = sb + s * STAGE_BYTES;
#pragma unroll
        for (int h = 0; h < 4; h++) {
            cp16(st + adf[h], asp[h] + s * KC);
            cp16(st + bdf[h], bsp[h] + s * KC);
        }
        cp_commit();
    }

    float acc[4][4][4];
#pragma unroll
    for (int mi = 0; mi < 4; mi++)
#pragma unroll
        for (int ni = 0; ni < 4; ni++)
#pragma unroll
            for (int r = 0; r < 4; r++) acc[mi][ni][r] = 0.f;

    const uint32_t a_row = (uint32_t)(wm * 64 + (lane & 15));
    const uint32_t a_colb = (uint32_t)((lane >> 4) * 16);
    const uint32_t b_row = (uint32_t)(wn * 32 + (lane & 7));
    const uint32_t b_colb = (uint32_t)(((lane >> 3) & 1) * 16);

    for (int i = 0; i < NC; i++) {
        cp_wait<PS - 2>();
        __syncthreads();

        int nc = i + PS - 1;
        if (nc < NC) {
            uint32_t st = sb + (nc % PS) * STAGE_BYTES;
#pragma unroll
            for (int h = 0; h < 4; h++) {
                cp16(st + adf[h], asp[h] + nc * KC);
                cp16(st + bdf[h], bsp[h] + nc * KC);
            }
        }
        cp_commit();

        uint32_t st = sb + (i % PS) * STAGE_BYTES;
#pragma unroll
        for (int ks = 0; ks < 4; ks++) {
            uint32_t a[4][4], b[4][2];
#pragma unroll
            for (int mi = 0; mi < 4; mi++) {
                uint32_t addr = st + (a_row + mi * 16) * (LDT*2) + ks * 32 + a_colb;
                ldsm_x4(a[mi][0], a[mi][1], a[mi][2], a[mi][3], addr);
            }
#pragma unroll
            for (int ni = 0; ni < 4; ni++) {
                uint32_t addr = st + TILE_BYTES + (b_row + ni * 8) * (LDT*2)
                              + ks * 32 + b_colb;
                ldsm_x2(b[ni][0], b[ni][1], addr);
            }
#pragma unroll
            for (int mi = 0; mi < 4; mi++)
#pragma unroll
                for (int ni = 0; ni < 4; ni++)
                    mma16816(acc[mi][ni], a[mi], b[ni]);
        }
    }

    const int g = lane >> 2, t = lane & 3;
#pragma unroll
    for (int mi = 0; mi < 4; mi++) {
        int m0 = bm + wm * 64 + mi * 16 + g;
#pragma unroll
        for (int ni = 0; ni < 4; ni++) {
            int n0 = bn + wn * 32 + ni * 8 + 2 * t;
            *(float2*)&C[(size_t)m0 * N + n0] =
                make_float2(acc[mi][ni][0], acc[mi][ni][1]);
            *(float2*)&C[(size_t)(m0 + 8) * N + n0] =
                make_float2(acc[mi][ni][2], acc[mi][ni][3]);
        }
    }
}

// ---------------------------------------------------------------------------
// Sliding-window attention:
//   QK^T on HMMA (Q = [hi|lo] fp16 split -> only K-rounding error),
//   softmax on fragments (shuffle + smem cross-warp reduce),
//   PV in exact fp32 (f32x2 SIMT), fused RoPE + fp16 output.
// ---------------------------------------------------------------------------
__global__ void __launch_bounds__(256, 1)
attn_kernel(const float* __restrict__ qkv, const int* __restrict__ amask,
            const float* __restrict__ tab, __half* __restrict__ attnx)
{
    extern __shared__ __align__(16) char sm[];
    float*  Psm  = (float*)(sm + PS_OFF);     // [64][200] exp scores
    float*  Vs   = (float*)(sm + VS_OFF);     // [192][68]
    __half* Qh   = (__half*)(sm + QH_OFF);    // [64][136] = [hi(64)|lo(64)|pad]
    __half* Kh   = (__half*)(sm + KH_OFF);    // [192][72]
    float*  pmax = (float*)(sm + PMAX_OFF);   // [4][64]
    float*  psum = (float*)(sm + PSUM_OFF);   // [4][64]
    int*    Ms   = (int*)(sm + MS_OFF);       // [192]

    const int tid = threadIdx.x;
    const int qb = blockIdx.x, h = blockIdx.y, b = blockIdx.z;
    const int q0 = qb * 64;
    const int ks = max(0, q0 - WIN);
    const int ke = min(TT, q0 + 64 + WIN);
    const int klen = ke - ks;
    const float* qbase = qkv + (size_t)b * TT * TD3;

    // ---- Q: load + rope -> fp16 [hi|lo], row-major [q][d] ----
#pragma unroll
    for (int it = 0; it < 2; it++) {
        int item = tid + it * 256;
        int row = item & 63, j4 = item >> 6;
        int t = q0 + row;
        const float* src = qbase + (size_t)t * TD3 + h * HD;
        float4 x0 = *(const float4*)(src + j4 * 4);
        float4 x1 = *(const float4*)(src + j4 * 4 + 32);
        const float4* tb = (const float4*)(tab + (size_t)t * 64 + j4 * 8);
        float4 t0 = tb[0], t1 = tb[1];
        float o[8];
        o[0]=x0.x*t0.x - x1.x*t0.y;  o[1]=x0.x*t0.y + x1.x*t0.x;
        o[2]=x0.y*t0.z - x1.y*t0.w;  o[3]=x0.y*t0.w + x1.y*t0.z;
        o[4]=x0.z*t1.x - x1.z*t1.y;  o[5]=x0.z*t1.y + x1.z*t1.x;
        o[6]=x0.w*t1.z - x1.w*t1.w;  o[7]=x0.w*t1.w + x1.w*t1.z;
        __half hh[8], hl[8];
#pragma unroll
        for (int i = 0; i < 8; i++) {
            hh[i] = __float2half_rn(o[i]);
            hl[i] = __float2half_rn(o[i] - __half2float(hh[i]));
        }
        uint4 ph = make_uint4(packh2(hh[0],hh[1]), packh2(hh[2],hh[3]),
                              packh2(hh[4],hh[5]), packh2(hh[6],hh[7]));
        uint4 pl = make_uint4(packh2(hl[0],hl[1]), packh2(hl[2],hl[3]),
                              packh2(hl[4],hl[5]), packh2(hl[6],hl[7]));
        *(uint4*)(Qh + row * 136 + j4 * 8)      = ph;
        *(uint4*)(Qh + row * 136 + 64 + j4 * 8) = pl;
    }
    // ---- K: load + rope -> fp16 row-major [token][d] ----
#pragma unroll
    for (int it = 0; it < 6; it++) {
        int item = tid + it * 256;
        int kk = item % 192, j4 = item / 192;
        if (kk < klen) {
            int t = ks + kk;
            const float* src = qbase + (size_t)t * TD3 + DD + h * HD;
            float4 x0 = *(const float4*)(src + j4 * 4);
            float4 x1 = *(const float4*)(src + j4 * 4 + 32);
            const float4* tb = (const float4*)(tab + (size_t)t * 64 + j4 * 8);
            float4 t0 = tb[0], t1 = tb[1];
            float o[8];
            o[0]=x0.x*t0.x - x1.x*t0.y;  o[1]=x0.x*t0.y + x1.x*t0.x;
            o[2]=x0.y*t0.z - x1.y*t0.w;  o[3]=x0.y*t0.w + x1.y*t0.z;
            o[4]=x0.z*t1.x - x1.z*t1.y;  o[5]=x0.z*t1.y + x1.z*t1.x;
            o[6]=x0.w*t1.z - x1.w*t1.w;  o[7]=x0.w*t1.w + x1.w*t1.z;
            uint4 ph = make_uint4(
                packh2(__float2half_rn(o[0]),__float2half_rn(o[1])),
                packh2(__float2half_rn(o[2]),__float2half_rn(o[3])),
                packh2(__float2half_rn(o[4]),__float2half_rn(o[5])),
                packh2(__float2half_rn(o[6]),__float2half_rn(o[7])));
            *(uint4*)(Kh + kk * 72 + j4 * 8) = ph;
        }
    }
    // ---- V direct (fp32) ----
#pragma unroll
    for (int it = 0; it < 12; it++) {
        int idx = tid + it * 256;
        int kk = idx >> 4, d4 = idx & 15;
        if (kk < klen) {
            float4 v = *(const float4*)(qbase + (size_t)(ks+kk)*TD3 + 2*DD + h*HD + d4*4);
            *(float4*)&Vs[kk*68 + d4*4] = v;
        }
    }
    if (tid < 192) Ms[tid] = (tid < klen) ? amask[b*TT + ks + tid] : 0;
    __syncthreads();

    // ---- QK^T on HMMA: warp tile 32(q) x 48(k), K-dim 128 ([hi|lo]) ----
    const int lane = tid & 31;
    const int warp = tid >> 5;
    const int wm = warp & 1;       // q half
    const int wn = warp >> 1;      // k quarter (48 cols)
    const int g = lane >> 2, t = lane & 3;
    const uint32_t qh_base = smem_u32(Qh);
    const uint32_t kh_base = smem_u32(Kh);

    float c[2][6][4];
#pragma unroll
    for (int mi = 0; mi < 2; mi++)
#pragma unroll
        for (int ni = 0; ni < 6; ni++)
#pragma unroll
            for (int r = 0; r < 4; r++) c[mi][ni][r] = 0.f;

    const uint32_t a_row = (uint32_t)(wm * 32 + (lane & 15));
    const uint32_t a_colb = (uint32_t)((lane >> 4) * 16);
    const uint32_t b_row = (uint32_t)(wn * 48 + (lane & 7));
    const uint32_t b_colb = (uint32_t)(((lane >> 3) & 1) * 16);

#pragma unroll
    for (int kstep = 0; kstep < 8; kstep++) {
        uint32_t a[2][4];
#pragma unroll
        for (int mi = 0; mi < 2; mi++)
            ldsm_x4(a[mi][0], a[mi][1], a[mi][2], a[mi][3],
                    qh_base + (a_row + mi * 16) * 272 + kstep * 32 + a_colb);
        uint32_t bf[6][2];
#pragma unroll
        for (int ni = 0; ni < 6; ni++)
            ldsm_x2(bf[ni][0], bf[ni][1],
                    kh_base + (b_row + ni * 8) * 144 + (kstep & 3) * 32 + b_colb);
#pragma unroll
        for (int mi = 0; mi < 2; mi++)
#pragma unroll
            for (int ni = 0; ni < 6; ni++)
                mma16816(c[mi][ni], a[mi], bf[ni]);
    }

    // ---- mask + row max ----
    const float scale = 0.125f;
    float mx[2][2] = { {-1e30f,-1e30f}, {-1e30f,-1e30f} };
#pragma unroll
    for (int mi = 0; mi < 2; mi++)
#pragma unroll
        for (int hh = 0; hh < 2; hh++) {
            int qg = q0 + wm*32 + mi*16 + g + hh*8;
#pragma unroll
            for (int ni = 0; ni < 6; ni++)
#pragma unroll
                for (int cc = 0; cc < 2; cc++) {
                    int kk = wn*48 + ni*8 + 2*t + cc;
                    int kg = ks + kk;
                    bool ok = (Ms[kk] != 0) && (abs(qg - kg) <= WIN);
                    float v = ok ? c[mi][ni][hh*2+cc] * scale : -1e30f;
                    c[mi][ni][hh*2+cc] = v;
                    mx[mi][hh] = fmaxf(mx[mi][hh], v);
                }
        }
#pragma unroll
    for (int mi = 0; mi < 2; mi++)
#pragma unroll
        for (int hh = 0; hh < 2; hh++) {
            float m = mx[mi][hh];
            m = fmaxf(m, __shfl_xor_sync(0xffffffffu, m, 1));
            m = fmaxf(m, __shfl_xor_sync(0xffffffffu, m, 2));
            mx[mi][hh] = m;
        }
    if (t == 0) {
#pragma unroll
        for (int mi = 0; mi < 2; mi++)
#pragma unroll
            for (int hh = 0; hh < 2; hh++)
                pmax[wn*64 + wm*32 + mi*16 + g + hh*8] = mx[mi][hh];
    }
    __syncthreads();

    // ---- exp + row sum, write Ps ----
    float sum[2][2] = { {0.f,0.f}, {0.f,0.f} };
#pragma unroll
    for (int mi = 0; mi < 2; mi++)
#pragma unroll
        for (int hh = 0; hh < 2; hh++) {
            int row = wm*32 + mi*16 + g + hh*8;
            float gm = fmaxf(fmaxf(pmax[row], pmax[64+row]),
                             fmaxf(pmax[128+row], pmax[192+row]));
#pragma unroll
            for (int ni = 0; ni < 6; ni++)
#pragma unroll
                for (int cc = 0; cc < 2; cc++) {
                    float e = __expf(c[mi][ni][hh*2+cc] - gm);
                    sum[mi][hh] += e;
                    Psm[row*200 + wn*48 + ni*8 + 2*t + cc] = e;
                }
        }
#pragma unroll
    for (int mi = 0; mi < 2; mi++)
#pragma unroll
        for (int hh = 0; hh < 2; hh++) {
            float s = sum[mi][hh];
            s += __shfl_xor_sync(0xffffffffu, s, 1);
            s += __shfl_xor_sync(0xffffffffu, s, 2);
            sum[mi][hh] = s;
        }
    if (t == 0) {
#pragma unroll
        for (int mi = 0; mi < 2; mi++)
#pragma unroll
            for (int hh = 0; hh < 2; hh++)
                psum[wn*64 + wm*32 + mi*16 + g + hh*8] = sum[mi][hh];
    }
    __syncthreads();

    // ---- PV: each thread 4q x 4d via f32x2 (exact fp32) ----
    const int tx2 = tid & 15;
    const int ty2 = tid >> 4;
    u64 o2[4][2];
#pragma unroll
    for (int qi = 0; qi < 4; qi++) { o2[qi][0] = 0ull; o2[qi][1] = 0ull; }

    for (int k = 0; k < klen; k++) {
        ulonglong2 vp = *(const ulonglong2*)&Vs[k*68 + tx2*4];
        u64 pd[4];
#pragma unroll
        for (int qi = 0; qi < 4; qi++) {
            float pq = Psm[(ty2*4+qi)*200 + k];
            pd[qi] = pk2(pq, pq);
        }
#pragma unroll
        for (int qi = 0; qi < 4; qi++) {
            o2[qi][0] = fma2(pd[qi], vp.x, o2[qi][0]);
            o2[qi][1] = fma2(pd[qi], vp.y, o2[qi][1]);
        }
    }
    // ---- epilogue: normalize + write fp16 operand for Wo GEMM ----
#pragma unroll
    for (int qi = 0; qi < 4; qi++) {
        int qq = ty2*4 + qi;
        float tot = psum[qq] + psum[64+qq] + psum[128+qq] + psum[192+qq];
        float r = 1.f / fmaxf(tot, 1e-30f);
        float2 f0 = up2(o2[qi][0]), f1 = up2(o2[qi][1]);
        uint2 hu = make_uint2(
            packh2(__float2half_rn(f0.x*r), __float2half_rn(f0.y*r)),
            packh2(__float2half_rn(f1.x*r), __float2half_rn(f1.y*r)));
        __half* dst = attnx + (size_t)(b*TT + q0 + qq) * KK + h*HD + tx2*4;
        *(uint2*)(dst) = hu;
    }
}

// ---------------------------------------------------------------------------
extern "C" void kernel_launch(void* const* d_in, const int* in_sizes, int n_in,
                              void* d_out, int out_size)
{
    const float* hs   = (const float*)d_in[0];
    const int*   am   = (const int*)d_in[1];
    const float* Wqkv = (const float*)d_in[2];
    const float* Wo   = (const float*)d_in[3];
    float* out = (float*)d_out;

    void* p;
    cudaGetSymbolAddress(&p, g_qkv);   float*  qkv   = (float*)p;
    cudaGetSymbolAddress(&p, g_ah);    __half* ah    = (__half*)p;
    cudaGetSymbolAddress(&p, g_attnx); __half* attnx = (__half*)p;
    cudaGetSymbolAddress(&p, g_wqkvh); __half* wqkvh = (__half*)p;
    cudaGetSymbolAddress(&p, g_woh);   __half* woh   = (__half*)p;
    cudaGetSymbolAddress(&p, g_tab);   float*  tab   = (float*)p;

    cudaFuncSetAttribute(attn_kernel,
                         cudaFuncAttributeMaxDynamicSharedMemorySize,
                         ATTN_SMEM_BYTES);
    cudaFuncSetAttribute(gemm_mma,
                         cudaFuncAttributeMaxDynamicSharedMemorySize,
                         GEMM_SMEM);

    const int M = BB * TT;                 // 8192

    // 1) fp32 -> fp16: weights + hidden states
    conv_all<<<((TD3*DD + DD*DD + M*DD)/4 + 255)/256, 256>>>(
        Wqkv, Wo, hs, wqkvh, woh, ah);

    // 2) rope table
    tab_kernel<<<(TT*32)/256, 256>>>(tab);

    // 3) QKV projection
    gemm_mma<<<dim3(TD3/128, M/128), 256, GEMM_SMEM>>>(ah, wqkvh, qkv, TD3);

    // 4) attention (HMMA scores, fp32 PV)
    dim3 ga(TT/64, NH, BB);
    attn_kernel<<<ga, 256, ATTN_SMEM_BYTES>>>(qkv, am, tab, attnx);

    // 5) output projection
    gemm_mma<<<dim3(DD/128, M/128), 256, GEMM_SMEM>>>(attnx, woh, out, DD);
}

// round 10
// speedup vs baseline: 5.2123x; 1.0126x over previous
#include <cuda_runtime.h>
#include <cuda_fp16.h>
#include <math.h>
#include <stdint.h>

#define BB 4
#define TT 2048
#define DD 768
#define NH 12
#define HD 64
#define WIN 64
#define TD3 (3*DD)
#define KK 768             // GEMM K (plain fp16 both operands)
#define KC 64              // k per pipeline chunk
#define NC (KK/KC)         // 12 chunks
#define PS 3               // pipeline stages
#define LDT 72             // padded smem row (fp16 elems) -> 144 bytes
#define TILE_BYTES (128*LDT*2)          // 18432 per operand tile
#define STAGE_BYTES (2*TILE_BYTES)      // 36864
#define GEMM_SMEM (PS*STAGE_BYTES)      // 110592

// attention smem layout (bytes)
#define QH_OFF   0                       // Qh fp16 [64][136] ([hi|lo]+pad)
#define KH_OFF   17408                   // Kh fp16 [192][72]
#define VHI_OFF  45056                   // Vhi fp16 [192][72]
#define VLO_OFF  72704                   // Vlo fp16 [192][72]
#define PH_OFF   100352                  // Ph fp16 [64][200]
#define PMAX_OFF 125952                  // fp32 [4][64]
#define PSUM_OFF 126976                  // fp32 [4][64]
#define MS_OFF   128000                  // int [192]
#define ATTN_SMEM_BYTES 128768

// ---------------- scratch (device globals: allocation-free rule) -----------
__device__ float  g_qkv[(size_t)BB*TT*TD3];          // [B,T,3D] fp32 (pre-rope)
__device__ __half g_ah  [(size_t)BB*TT*KK];          // hidden fp16
__device__ __half g_attnx[(size_t)BB*TT*KK];         // attn out fp16
__device__ __half g_wqkvh[(size_t)TD3*KK];           // Wqkv fp16
__device__ __half g_woh [(size_t)DD*KK];             // Wo fp16
__device__ float  g_tab [(size_t)TT*64];             // rope (cos,sin) pairs [t][j]

typedef unsigned long long u64;

// ---------------- PTX helpers (baseline ISA only) ---------------------------
__device__ __forceinline__ uint32_t smem_u32(const void* p){
    uint32_t a;
    asm("{ .reg .u64 t; cvta.to.shared.u64 t, %1; cvt.u32.u64 %0, t; }"
        : "=r"(a) : "l"(p));
    return a;
}
__device__ __forceinline__ void cp16(uint32_t d, const void* s){
    asm volatile("cp.async.cg.shared.global [%0], [%1], 16;"
                 :: "r"(d), "l"(s) : "memory");
}
__device__ __forceinline__ void cp_commit(){
    asm volatile("cp.async.commit_group;" ::: "memory");
}
template<int N>
__device__ __forceinline__ void cp_wait(){
    asm volatile("cp.async.wait_group %0;" :: "n"(N) : "memory");
}
__device__ __forceinline__ void ldsm_x4(uint32_t &r0,uint32_t &r1,uint32_t &r2,uint32_t &r3,
                                        uint32_t addr){
    asm volatile("ldmatrix.sync.aligned.m8n8.x4.shared.b16 {%0,%1,%2,%3}, [%4];"
                 : "=r"(r0),"=r"(r1),"=r"(r2),"=r"(r3) : "r"(addr));
}
__device__ __forceinline__ void ldsm_x2(uint32_t &r0,uint32_t &r1, uint32_t addr){
    asm volatile("ldmatrix.sync.aligned.m8n8.x2.shared.b16 {%0,%1}, [%2];"
                 : "=r"(r0),"=r"(r1) : "r"(addr));
}
__device__ __forceinline__ void ldsm_x2t(uint32_t &r0,uint32_t &r1, uint32_t addr){
    asm volatile("ldmatrix.sync.aligned.m8n8.x2.trans.shared.b16 {%0,%1}, [%2];"
                 : "=r"(r0),"=r"(r1) : "r"(addr));
}
__device__ __forceinline__ void mma16816(float* d, const uint32_t* a, const uint32_t* b){
    asm volatile("mma.sync.aligned.m16n8k16.row.col.f32.f16.f16.f32 "
        "{%0,%1,%2,%3}, {%4,%5,%6,%7}, {%8,%9}, {%0,%1,%2,%3};"
        : "+f"(d[0]),"+f"(d[1]),"+f"(d[2]),"+f"(d[3])
        : "r"(a[0]),"r"(a[1]),"r"(a[2]),"r"(a[3]), "r"(b[0]),"r"(b[1]));
}
__device__ __forceinline__ uint32_t packh2(__half a, __half b){
    return (uint32_t)__half_as_ushort(a) | ((uint32_t)__half_as_ushort(b) << 16);
}

// ---------------------------------------------------------------------------
// fp32 -> fp16 conversion (weights + hidden states).
// ---------------------------------------------------------------------------
__global__ void conv_all(const float* __restrict__ wqkv, const float* __restrict__ wo,
                         const float* __restrict__ hs,
                         __half* __restrict__ wqkvh, __half* __restrict__ woh,
                         __half* __restrict__ ah)
{
    const int n1 = TD3*DD/4;
    const int n2 = DD*DD/4;
    const int n3 = BB*TT*DD/4;
    int idx = blockIdx.x * blockDim.x + threadIdx.x;
    if (idx >= n1 + n2 + n3) return;
    const float* src; __half* dst; int i;
    if (idx < n1)            { src = wqkv; dst = wqkvh; i = idx; }
    else if (idx < n1 + n2)  { src = wo;   dst = woh;   i = idx - n1; }
    else                     { src = hs;   dst = ah;    i = idx - n1 - n2; }
    float4 v = *(const float4*)(src + (size_t)i*4);
    uint2 o = make_uint2(packh2(__float2half_rn(v.x), __float2half_rn(v.y)),
                         packh2(__float2half_rn(v.z), __float2half_rn(v.w)));
    *(uint2*)(dst + (size_t)i*4) = o;
}

// ---------------------------------------------------------------------------
// RoPE table: g_tab[t*64 + 2j] = cos(t * 10000^(-j/32)), [.. +1] = sin.
// ---------------------------------------------------------------------------
__global__ void tab_kernel(float* __restrict__ tab)
{
    int idx = blockIdx.x * blockDim.x + threadIdx.x;   // TT*32
    int t = idx >> 5, j = idx & 31;
    const float c0 = 0.41524101186092029f;             // log2(10000)/32
    float inv = exp2f(-c0 * (float)j);
    float sn, cs;
    sincosf((float)t * inv, &sn, &cs);
    tab[t*64 + 2*j]     = cs;
    tab[t*64 + 2*j + 1] = sn;
}

// ---------------------------------------------------------------------------
// HMMA GEMM: C[m,n] = sum_{k<768} A[m,k] * B[n,k]   (fp16 -> fp32)
// ---------------------------------------------------------------------------
__global__ void __launch_bounds__(256, 2)
gemm_mma(const __half* __restrict__ A, const __half* __restrict__ B,
         float* __restrict__ C, int N)
{
    extern __shared__ __align__(16) char smem[];
    const uint32_t sb = smem_u32(smem);
    const int tid  = threadIdx.x;
    const int lane = tid & 31;
    const int warp = tid >> 5;
    const int bm = blockIdx.y * 128;
    const int bn = blockIdx.x * 128;
    const int wm = warp & 1;
    const int wn = warp >> 1;

    const __half* asp[4]; uint32_t adf[4];
    const __half* bsp[4]; uint32_t bdf[4];
#pragma unroll
    for (int h = 0; h < 4; h++) {
        int idx = tid + h * 256;
        int row = idx >> 3, seg = idx & 7;
        asp[h] = A + (size_t)(bm + row) * KK + seg * 8;
        bsp[h] = B + (size_t)(bn + row) * KK + seg * 8;
        adf[h] = (uint32_t)(row * (LDT*2) + seg * 16);
        bdf[h] = adf[h] + TILE_BYTES;
    }

#pragma unroll
    for (int s = 0; s < PS - 1; s++) {
        uint32_t st = sb + s * STAGE_BYTES;
#pragma unroll
        for (int h = 0; h < 4; h++) {
            cp16(st + adf[h], asp[h] + s * KC);
            cp16(st + bdf[h], bsp[h] + s * KC);
        }
        cp_commit();
    }

    float acc[4][4][4];
#pragma unroll
    for (int mi = 0; mi < 4; mi++)
#pragma unroll
        for (int ni = 0; ni < 4; ni++)
#pragma unroll
            for (int r = 0; r < 4; r++) acc[mi][ni][r] = 0.f;

    const uint32_t a_row = (uint32_t)(wm * 64 + (lane & 15));
    const uint32_t a_colb = (uint32_t)((lane >> 4) * 16);
    const uint32_t b_row = (uint32_t)(wn * 32 + (lane & 7));
    const uint32_t b_colb = (uint32_t)(((lane >> 3) & 1) * 16);

    for (int i = 0; i < NC; i++) {
        cp_wait<PS - 2>();
        __syncthreads();

        int nc = i + PS - 1;
        if (nc < NC) {
            uint32_t st = sb + (nc % PS) * STAGE_BYTES;
#pragma unroll
            for (int h = 0; h < 4; h++) {
                cp16(st + adf[h], asp[h] + nc * KC);
                cp16(st + bdf[h], bsp[h] + nc * KC);
            }
        }
        cp_commit();

        uint32_t st = sb + (i % PS) * STAGE_BYTES;
#pragma unroll
        for (int ks = 0; ks < 4; ks++) {
            uint32_t a[4][4], b[4][2];
#pragma unroll
            for (int mi = 0; mi < 4; mi++) {
                uint32_t addr = st + (a_row + mi * 16) * (LDT*2) + ks * 32 + a_colb;
                ldsm_x4(a[mi][0], a[mi][1], a[mi][2], a[mi][3], addr);
            }
#pragma unroll
            for (int ni = 0; ni < 4; ni++) {
                uint32_t addr = st + TILE_BYTES + (b_row + ni * 8) * (LDT*2)
                              + ks * 32 + b_colb;
                ldsm_x2(b[ni][0], b[ni][1], addr);
            }
#pragma unroll
            for (int mi = 0; mi < 4; mi++)
#pragma unroll
                for (int ni = 0; ni < 4; ni++)
                    mma16816(acc[mi][ni], a[mi], b[ni]);
        }
    }

    const int g = lane >> 2, t = lane & 3;
#pragma unroll
    for (int mi = 0; mi < 4; mi++) {
        int m0 = bm + wm * 64 + mi * 16 + g;
#pragma unroll
        for (int ni = 0; ni < 4; ni++) {
            int n0 = bn + wn * 32 + ni * 8 + 2 * t;
            *(float2*)&C[(size_t)m0 * N + n0] =
                make_float2(acc[mi][ni][0], acc[mi][ni][1]);
            *(float2*)&C[(size_t)(m0 + 8) * N + n0] =
                make_float2(acc[mi][ni][2], acc[mi][ni][3]);
        }
    }
}

// ---------------------------------------------------------------------------
// Sliding-window attention, fully on HMMA:
//   QK^T: Q=[hi|lo] fp16 split (only K-rounding error), softmax on fragments,
//   PV:   P fp16 (rounded) x V=[hi|lo] fp16 split via ldmatrix.trans.
// ---------------------------------------------------------------------------
__global__ void __launch_bounds__(256, 1)
attn_kernel(const float* __restrict__ qkv, const int* __restrict__ amask,
            const float* __restrict__ tab, __half* __restrict__ attnx)
{
    extern __shared__ __align__(16) char sm[];
    __half* Qh   = (__half*)(sm + QH_OFF);    // [64][136]
    __half* Kh   = (__half*)(sm + KH_OFF);    // [192][72]
    __half* Vhi  = (__half*)(sm + VHI_OFF);   // [192][72]
    __half* Vlo  = (__half*)(sm + VLO_OFF);   // [192][72]
    __half* Ph   = (__half*)(sm + PH_OFF);    // [64][200]
    float*  pmax = (float*)(sm + PMAX_OFF);   // [4][64]
    float*  psum = (float*)(sm + PSUM_OFF);   // [4][64]
    int*    Ms   = (int*)(sm + MS_OFF);       // [192]

    const int tid = threadIdx.x;
    const int qb = blockIdx.x, h = blockIdx.y, b = blockIdx.z;
    const int q0 = qb * 64;
    const int ks = max(0, q0 - WIN);
    const int ke = min(TT, q0 + 64 + WIN);
    const int klen = ke - ks;
    const float* qbase = qkv + (size_t)b * TT * TD3;

    // ---- Q: load + rope -> fp16 [hi|lo], row-major [q][d] ----
#pragma unroll
    for (int it = 0; it < 2; it++) {
        int item = tid + it * 256;
        int row = item & 63, j4 = item >> 6;
        int t = q0 + row;
        const float* src = qbase + (size_t)t * TD3 + h * HD;
        float4 x0 = *(const float4*)(src + j4 * 4);
        float4 x1 = *(const float4*)(src + j4 * 4 + 32);
        const float4* tb = (const float4*)(tab + (size_t)t * 64 + j4 * 8);
        float4 t0 = tb[0], t1 = tb[1];
        float o[8];
        o[0]=x0.x*t0.x - x1.x*t0.y;  o[1]=x0.x*t0.y + x1.x*t0.x;
        o[2]=x0.y*t0.z - x1.y*t0.w;  o[3]=x0.y*t0.w + x1.y*t0.z;
        o[4]=x0.z*t1.x - x1.z*t1.y;  o[5]=x0.z*t1.y + x1.z*t1.x;
        o[6]=x0.w*t1.z - x1.w*t1.w;  o[7]=x0.w*t1.w + x1.w*t1.z;
        __half hh[8], hl[8];
#pragma unroll
        for (int i = 0; i < 8; i++) {
            hh[i] = __float2half_rn(o[i]);
            hl[i] = __float2half_rn(o[i] - __half2float(hh[i]));
        }
        uint4 ph = make_uint4(packh2(hh[0],hh[1]), packh2(hh[2],hh[3]),
                              packh2(hh[4],hh[5]), packh2(hh[6],hh[7]));
        uint4 pl = make_uint4(packh2(hl[0],hl[1]), packh2(hl[2],hl[3]),
                              packh2(hl[4],hl[5]), packh2(hl[6],hl[7]));
        *(uint4*)(Qh + row * 136 + j4 * 8)      = ph;
        *(uint4*)(Qh + row * 136 + 64 + j4 * 8) = pl;
    }
    // ---- K: load + rope -> fp16 row-major [token][d] ----
#pragma unroll
    for (int it = 0; it < 6; it++) {
        int item = tid + it * 256;
        int kk = item % 192, j4 = item / 192;
        if (kk < klen) {
            int t = ks + kk;
            const float* src = qbase + (size_t)t * TD3 + DD + h * HD;
            float4 x0 = *(const float4*)(src + j4 * 4);
            float4 x1 = *(const float4*)(src + j4 * 4 + 32);
            const float4* tb = (const float4*)(tab + (size_t)t * 64 + j4 * 8);
            float4 t0 = tb[0], t1 = tb[1];
            float o[8];
            o[0]=x0.x*t0.x - x1.x*t0.y;  o[1]=x0.x*t0.y + x1.x*t0.x;
            o[2]=x0.y*t0.z - x1.y*t0.w;  o[3]=x0.y*t0.w + x1.y*t0.z;
            o[4]=x0.z*t1.x - x1.z*t1.y;  o[5]=x0.z*t1.y + x1.z*t1.x;
            o[6]=x0.w*t1.z - x1.w*t1.w;  o[7]=x0.w*t1.w + x1.w*t1.z;
            uint4 ph = make_uint4(
                packh2(__float2half_rn(o[0]),__float2half_rn(o[1])),
                packh2(__float2half_rn(o[2]),__float2half_rn(o[3])),
                packh2(__float2half_rn(o[4]),__float2half_rn(o[5])),
                packh2(__float2half_rn(o[6]),__float2half_rn(o[7])));
            *(uint4*)(Kh + kk * 72 + j4 * 8) = ph;
        }
    }
    // ---- V: load -> [hi|lo] fp16 (zero-fill beyond klen: NaN guard) ----
#pragma unroll
    for (int it = 0; it < 12; it++) {
        int idx = tid + it * 256;
        int kk = idx >> 4, d4 = idx & 15;
        uint2 vh = make_uint2(0u, 0u), vl = make_uint2(0u, 0u);
        if (kk < klen) {
            float4 v = *(const float4*)(qbase + (size_t)(ks+kk)*TD3 + 2*DD + h*HD + d4*4);
            __half h0 = __float2half_rn(v.x), h1 = __float2half_rn(v.y);
            __half h2 = __float2half_rn(v.z), h3 = __float2half_rn(v.w);
            vh = make_uint2(packh2(h0,h1), packh2(h2,h3));
            vl = make_uint2(
                packh2(__float2half_rn(v.x - __half2float(h0)),
                       __float2half_rn(v.y - __half2float(h1))),
                packh2(__float2half_rn(v.z - __half2float(h2)),
                       __float2half_rn(v.w - __half2float(h3))));
        }
        *(uint2*)(Vhi + kk*72 + d4*4) = vh;
        *(uint2*)(Vlo + kk*72 + d4*4) = vl;
    }
    if (tid < 192) Ms[tid] = (tid < klen) ? amask[b*TT + ks + tid] : 0;
    __syncthreads();

    // ---- QK^T on HMMA: warp tile 32(q) x 48(k), K-dim 128 ([hi|lo]) ----
    const int lane = tid & 31;
    const int warp = tid >> 5;
    const int wm = warp & 1;       // q half
    const int wn = warp >> 1;      // k quarter (48 cols)
    const int g = lane >> 2, t = lane & 3;
    const uint32_t qh_base = smem_u32(Qh);
    const uint32_t kh_base = smem_u32(Kh);

    float c[2][6][4];
#pragma unroll
    for (int mi = 0; mi < 2; mi++)
#pragma unroll
        for (int ni = 0; ni < 6; ni++)
#pragma unroll
            for (int r = 0; r < 4; r++) c[mi][ni][r] = 0.f;

    const uint32_t a_row = (uint32_t)(wm * 32 + (lane & 15));
    const uint32_t a_colb = (uint32_t)((lane >> 4) * 16);
    const uint32_t b_row = (uint32_t)(wn * 48 + (lane & 7));
    const uint32_t b_colb = (uint32_t)(((lane >> 3) & 1) * 16);

#pragma unroll
    for (int kstep = 0; kstep < 8; kstep++) {
        uint32_t a[2][4];
#pragma unroll
        for (int mi = 0; mi < 2; mi++)
            ldsm_x4(a[mi][0], a[mi][1], a[mi][2], a[mi][3],
                    qh_base + (a_row + mi * 16) * 272 + kstep * 32 + a_colb);
        uint32_t bf[6][2];
#pragma unroll
        for (int ni = 0; ni < 6; ni++)
            ldsm_x2(bf[ni][0], bf[ni][1],
                    kh_base + (b_row + ni * 8) * 144 + (kstep & 3) * 32 + b_colb);
#pragma unroll
        for (int mi = 0; mi < 2; mi++)
#pragma unroll
            for (int ni = 0; ni < 6; ni++)
                mma16816(c[mi][ni], a[mi], bf[ni]);
    }

    // ---- mask + row max ----
    const float scale = 0.125f;
    float mx[2][2] = { {-1e30f,-1e30f}, {-1e30f,-1e30f} };
#pragma unroll
    for (int mi = 0; mi < 2; mi++)
#pragma unroll
        for (int hh = 0; hh < 2; hh++) {
            int qg = q0 + wm*32 + mi*16 + g + hh*8;
#pragma unroll
            for (int ni = 0; ni < 6; ni++)
#pragma unroll
                for (int cc = 0; cc < 2; cc++) {
                    int kk = wn*48 + ni*8 + 2*t + cc;
                    int kg = ks + kk;
                    bool ok = (Ms[kk] != 0) && (abs(qg - kg) <= WIN);
                    float v = ok ? c[mi][ni][hh*2+cc] * scale : -1e30f;
                    c[mi][ni][hh*2+cc] = v;
                    mx[mi][hh] = fmaxf(mx[mi][hh], v);
                }
        }
#pragma unroll
    for (int mi = 0; mi < 2; mi++)
#pragma unroll
        for (int hh = 0; hh < 2; hh++) {
            float m = mx[mi][hh];
            m = fmaxf(m, __shfl_xor_sync(0xffffffffu, m, 1));
            m = fmaxf(m, __shfl_xor_sync(0xffffffffu, m, 2));
            mx[mi][hh] = m;
        }
    if (t == 0) {
#pragma unroll
        for (int mi = 0; mi < 2; mi++)
#pragma unroll
            for (int hh = 0; hh < 2; hh++)
                pmax[wn*64 + wm*32 + mi*16 + g + hh*8] = mx[mi][hh];
    }
    __syncthreads();

    // ---- exp + row sum, write Ph (fp16) ----
    float sum[2][2] = { {0.f,0.f}, {0.f,0.f} };
#pragma unroll
    for (int mi = 0; mi < 2; mi++)
#pragma unroll
        for (int hh = 0; hh < 2; hh++) {
            int row = wm*32 + mi*16 + g + hh*8;
            float gm = fmaxf(fmaxf(pmax[row], pmax[64+row]),
                             fmaxf(pmax[128+row], pmax[192+row]));
#pragma unroll
            for (int ni = 0; ni < 6; ni++) {
                float e0 = __expf(c[mi][ni][hh*2+0] - gm);
                float e1 = __expf(c[mi][ni][hh*2+1] - gm);
                sum[mi][hh] += e0 + e1;
                *(uint32_t*)(Ph + row*200 + wn*48 + ni*8 + 2*t) =
                    packh2(__float2half_rn(e0), __float2half_rn(e1));
            }
        }
#pragma unroll
    for (int mi = 0; mi < 2; mi++)
#pragma unroll
        for (int hh = 0; hh < 2; hh++) {
            float s = sum[mi][hh];
            s += __shfl_xor_sync(0xffffffffu, s, 1);
            s += __shfl_xor_sync(0xffffffffu, s, 2);
            sum[mi][hh] = s;
        }
    if (t == 0) {
#pragma unroll
        for (int mi = 0; mi < 2; mi++)
#pragma unroll
            for (int hh = 0; hh < 2; hh++)
                psum[wn*64 + wm*32 + mi*16 + g + hh*8] = sum[mi][hh];
    }
    __syncthreads();

    // ---- PV on HMMA: warp tile 32(q) x 16(d), K-dim 192, V=[hi|lo] -------
    const int wm2 = warp & 1;      // q half
    const int wn2 = warp >> 1;     // d quarter (16 cols)
    const uint32_t ph_base  = smem_u32(Ph);
    const uint32_t vhi_base = smem_u32(Vhi);
    const uint32_t vlo_base = smem_u32(Vlo);

    float o[2][2][4];
#pragma unroll
    for (int mi = 0; mi < 2; mi++)
#pragma unroll
        for (int ni = 0; ni < 2; ni++)
#pragma unroll
            for (int r = 0; r < 4; r++) o[mi][ni][r] = 0.f;

    const uint32_t pa_row  = (uint32_t)(wm2 * 32 + (lane & 15));
    const uint32_t pa_colb = (uint32_t)((lane >> 4) * 16);
    const uint32_t v_lane  = (uint32_t)(lane & 15);          // k row within 16

#pragma unroll
    for (int ks2 = 0; ks2 < 12; ks2++) {
        uint32_t a[2][4];
#pragma unroll
        for (int mi = 0; mi < 2; mi++)
            ldsm_x4(a[mi][0], a[mi][1], a[mi][2], a[mi][3],
                    ph_base + (pa_row + mi * 16) * 400 + ks2 * 32 + pa_colb);
        uint32_t bh[2][2], bl[2][2];
#pragma unroll
        for (int ni = 0; ni < 2; ni++) {
            uint32_t off = (ks2 * 16 + v_lane) * 144 + (wn2 * 16 + ni * 8) * 2;
            ldsm_x2t(bh[ni][0], bh[ni][1], vhi_base + off);
            ldsm_x2t(bl[ni][0], bl[ni][1], vlo_base + off);
        }
#pragma unroll
        for (int mi = 0; mi < 2; mi++)
#pragma unroll
            for (int ni = 0; ni < 2; ni++) {
                mma16816(o[mi][ni], a[mi], bh[ni]);
                mma16816(o[mi][ni], a[mi], bl[ni]);
            }
    }

    // ---- epilogue: normalize + write fp16 operand for Wo GEMM ----
#pragma unroll
    for (int mi = 0; mi < 2; mi++)
#pragma unroll
        for (int hh = 0; hh < 2; hh++) {
            int qq = wm2*32 + mi*16 + g + hh*8;
            float tot = psum[qq] + psum[64+qq] + psum[128+qq] + psum[192+qq];
            float r = 1.f / fmaxf(tot, 1e-30f);
#pragma unroll
            for (int ni = 0; ni < 2; ni++) {
                int d = wn2*16 + ni*8 + 2*t;
                uint32_t pair = packh2(__float2half_rn(o[mi][ni][hh*2+0] * r),
                                       __float2half_rn(o[mi][ni][hh*2+1] * r));
                *(uint32_t*)(attnx + (size_t)(b*TT + q0 + qq) * KK + h*HD + d) = pair;
            }
        }
}

// ---------------------------------------------------------------------------
extern "C" void kernel_launch(void* const* d_in, const int* in_sizes, int n_in,
                              void* d_out, int out_size)
{
    const float* hs   = (const float*)d_in[0];
    const int*   am   = (const int*)d_in[1];
    const float* Wqkv = (const float*)d_in[2];
    const float* Wo   = (const float*)d_in[3];
    float* out = (float*)d_out;

    void* p;
    cudaGetSymbolAddress(&p, g_qkv);   float*  qkv   = (float*)p;
    cudaGetSymbolAddress(&p, g_ah);    __half* ah    = (__half*)p;
    cudaGetSymbolAddress(&p, g_attnx); __half* attnx = (__half*)p;
    cudaGetSymbolAddress(&p, g_wqkvh); __half* wqkvh = (__half*)p;
    cudaGetSymbolAddress(&p, g_woh);   __half* woh   = (__half*)p;
    cudaGetSymbolAddress(&p, g_tab);   float*  tab   = (float*)p;

    cudaFuncSetAttribute(attn_kernel,
                         cudaFuncAttributeMaxDynamicSharedMemorySize,
                         ATTN_SMEM_BYTES);
    cudaFuncSetAttribute(gemm_mma,
                         cudaFuncAttributeMaxDynamicSharedMemorySize,
                         GEMM_SMEM);

    const int M = BB * TT;                 // 8192

    // 1) fp32 -> fp16: weights + hidden states
    conv_all<<<((TD3*DD + DD*DD + M*DD)/4 + 255)/256, 256>>>(
        Wqkv, Wo, hs, wqkvh, woh, ah);

    // 2) rope table
    tab_kernel<<<(TT*32)/256, 256>>>(tab);

    // 3) QKV projection
    gemm_mma<<<dim3(TD3/128, M/128), 256, GEMM_SMEM>>>(ah, wqkvh, qkv, TD3);

    // 4) attention (HMMA scores + HMMA PV)
    dim3 ga(TT/64, NH, BB);
    attn_kernel<<<ga, 256, ATTN_SMEM_BYTES>>>(qkv, am, tab, attnx);

    // 5) output projection
    gemm_mma<<<dim3(DD/128, M/128), 256, GEMM_SMEM>>>(attnx, woh, out, DD);
}

// round 11
// speedup vs baseline: 5.5970x; 1.0738x over previous
#include <cuda_runtime.h>
#include <cuda_fp16.h>
#include <math.h>
#include <stdint.h>

#define BB 4
#define TT 2048
#define DD 768
#define NH 12
#define HD 64
#define WIN 64
#define TD3 (3*DD)
#define KK 768             // GEMM K (plain fp16 both operands)
#define KC 64              // k per pipeline chunk
#define NC (KK/KC)         // 12 chunks
#define PS 3               // pipeline stages
#define LDT 72             // padded smem row (fp16 elems) -> 144 bytes
#define TILE_BYTES (128*LDT*2)          // 18432 per operand tile
#define STAGE_BYTES (2*TILE_BYTES)      // 36864
#define GEMM_SMEM (PS*STAGE_BYTES)      // 110592

// attention smem layout (bytes).  Qh and Ph ALIAS (same region):
// Qh is dead after the scores MMAs; Ph is first written in the exp phase,
// and the pmax __syncthreads() separates them.  This cuts smem to 111KB
// -> 2 CTAs/SM.
#define QH_OFF   0                       // Qh fp16 [64][136] ([hi|lo]+pad) 17408B
#define PH_OFF   0                       // Ph fp16 [64][200] 25600B (alias)
#define KH_OFF   25600                   // Kh fp16 [192][72]  27648B
#define VHI_OFF  53248                   // Vhi fp16 [192][72] 27648B
#define VLO_OFF  80896                   // Vlo fp16 [192][72] 27648B
#define PMAX_OFF 108544                  // fp32 [4][64] 1024B
#define PSUM_OFF 109568                  // fp32 [4][64] 1024B
#define MS_OFF   110592                  // int [192] 768B
#define ATTN_SMEM_BYTES 111360

// ---------------- scratch (device globals: allocation-free rule) -----------
__device__ float  g_qkv[(size_t)BB*TT*TD3];          // [B,T,3D] fp32 (pre-rope)
__device__ __half g_ah  [(size_t)BB*TT*KK];          // hidden fp16
__device__ __half g_attnx[(size_t)BB*TT*KK];         // attn out fp16
__device__ __half g_wqkvh[(size_t)TD3*KK];           // Wqkv fp16
__device__ __half g_woh [(size_t)DD*KK];             // Wo fp16
__device__ float  g_tab [(size_t)TT*64];             // rope (cos,sin) pairs [t][j]

typedef unsigned long long u64;

// ---------------- PTX helpers (baseline ISA only) ---------------------------
__device__ __forceinline__ uint32_t smem_u32(const void* p){
    uint32_t a;
    asm("{ .reg .u64 t; cvta.to.shared.u64 t, %1; cvt.u32.u64 %0, t; }"
        : "=r"(a) : "l"(p));
    return a;
}
__device__ __forceinline__ void cp16(uint32_t d, const void* s){
    asm volatile("cp.async.cg.shared.global [%0], [%1], 16;"
                 :: "r"(d), "l"(s) : "memory");
}
__device__ __forceinline__ void cp_commit(){
    asm volatile("cp.async.commit_group;" ::: "memory");
}
template<int N>
__device__ __forceinline__ void cp_wait(){
    asm volatile("cp.async.wait_group %0;" :: "n"(N) : "memory");
}
__device__ __forceinline__ void ldsm_x4(uint32_t &r0,uint32_t &r1,uint32_t &r2,uint32_t &r3,
                                        uint32_t addr){
    asm volatile("ldmatrix.sync.aligned.m8n8.x4.shared.b16 {%0,%1,%2,%3}, [%4];"
                 : "=r"(r0),"=r"(r1),"=r"(r2),"=r"(r3) : "r"(addr));
}
__device__ __forceinline__ void ldsm_x2(uint32_t &r0,uint32_t &r1, uint32_t addr){
    asm volatile("ldmatrix.sync.aligned.m8n8.x2.shared.b16 {%0,%1}, [%2];"
                 : "=r"(r0),"=r"(r1) : "r"(addr));
}
__device__ __forceinline__ void ldsm_x2t(uint32_t &r0,uint32_t &r1, uint32_t addr){
    asm volatile("ldmatrix.sync.aligned.m8n8.x2.trans.shared.b16 {%0,%1}, [%2];"
                 : "=r"(r0),"=r"(r1) : "r"(addr));
}
__device__ __forceinline__ void mma16816(float* d, const uint32_t* a, const uint32_t* b){
    asm volatile("mma.sync.aligned.m16n8k16.row.col.f32.f16.f16.f32 "
        "{%0,%1,%2,%3}, {%4,%5,%6,%7}, {%8,%9}, {%0,%1,%2,%3};"
        : "+f"(d[0]),"+f"(d[1]),"+f"(d[2]),"+f"(d[3])
        : "r"(a[0]),"r"(a[1]),"r"(a[2]),"r"(a[3]), "r"(b[0]),"r"(b[1]));
}
__device__ __forceinline__ uint32_t packh2(__half a, __half b){
    return (uint32_t)__half_as_ushort(a) | ((uint32_t)__half_as_ushort(b) << 16);
}

// ---------------------------------------------------------------------------
// fp32 -> fp16 conversion (weights + hidden states).
// ---------------------------------------------------------------------------
__global__ void conv_all(const float* __restrict__ wqkv, const float* __restrict__ wo,
                         const float* __restrict__ hs,
                         __half* __restrict__ wqkvh, __half* __restrict__ woh,
                         __half* __restrict__ ah)
{
    const int n1 = TD3*DD/4;
    const int n2 = DD*DD/4;
    const int n3 = BB*TT*DD/4;
    int idx = blockIdx.x * blockDim.x + threadIdx.x;
    if (idx >= n1 + n2 + n3) return;
    const float* src; __half* dst; int i;
    if (idx < n1)            { src = wqkv; dst = wqkvh; i = idx; }
    else if (idx < n1 + n2)  { src = wo;   dst = woh;   i = idx - n1; }
    else                     { src = hs;   dst = ah;    i = idx - n1 - n2; }
    float4 v = *(const float4*)(src + (size_t)i*4);
    uint2 o = make_uint2(packh2(__float2half_rn(v.x), __float2half_rn(v.y)),
                         packh2(__float2half_rn(v.z), __float2half_rn(v.w)));
    *(uint2*)(dst + (size_t)i*4) = o;
}

// ---------------------------------------------------------------------------
// RoPE table: g_tab[t*64 + 2j] = cos(t * 10000^(-j/32)), [.. +1] = sin.
// ---------------------------------------------------------------------------
__global__ void tab_kernel(float* __restrict__ tab)
{
    int idx = blockIdx.x * blockDim.x + threadIdx.x;   // TT*32
    int t = idx >> 5, j = idx & 31;
    const float c0 = 0.41524101186092029f;             // log2(10000)/32
    float inv = exp2f(-c0 * (float)j);
    float sn, cs;
    sincosf((float)t * inv, &sn, &cs);
    tab[t*64 + 2*j]     = cs;
    tab[t*64 + 2*j + 1] = sn;
}

// ---------------------------------------------------------------------------
// HMMA GEMM: C[m,n] = sum_{k<768} A[m,k] * B[n,k]   (fp16 -> fp32)
// ---------------------------------------------------------------------------
__global__ void __launch_bounds__(256, 2)
gemm_mma(const __half* __restrict__ A, const __half* __restrict__ B,
         float* __restrict__ C, int N)
{
    extern __shared__ __align__(16) char smem[];
    const uint32_t sb = smem_u32(smem);
    const int tid  = threadIdx.x;
    const int lane = tid & 31;
    const int warp = tid >> 5;
    const int bm = blockIdx.y * 128;
    const int bn = blockIdx.x * 128;
    const int wm = warp & 1;
    const int wn = warp >> 1;

    const __half* asp[4]; uint32_t adf[4];
    const __half* bsp[4]; uint32_t bdf[4];
#pragma unroll
    for (int h = 0; h < 4; h++) {
        int idx = tid + h * 256;
        int row = idx >> 3, seg = idx & 7;
        asp[h] = A + (size_t)(bm + row) * KK + seg * 8;
        bsp[h] = B + (size_t)(bn + row) * KK + seg * 8;
        adf[h] = (uint32_t)(row * (LDT*2) + seg * 16);
        bdf[h] = adf[h] + TILE_BYTES;
    }

#pragma unroll
    for (int s = 0; s < PS - 1; s++) {
        uint32_t st = sb + s * STAGE_BYTES;
#pragma unroll
        for (int h = 0; h < 4; h++) {
            cp16(st + adf[h], asp[h] + s * KC);
            cp16(st + bdf[h], bsp[h] + s * KC);
        }
        cp_commit();
    }

    float acc[4][4][4];
#pragma unroll
    for (int mi = 0; mi < 4; mi++)
#pragma unroll
        for (int ni = 0; ni < 4; ni++)
#pragma unroll
            for (int r = 0; r < 4; r++) acc[mi][ni][r] = 0.f;

    const uint32_t a_row = (uint32_t)(wm * 64 + (lane & 15));
    const uint32_t a_colb = (uint32_t)((lane >> 4) * 16);
    const uint32_t b_row = (uint32_t)(wn * 32 + (lane & 7));
    const uint32_t b_colb = (uint32_t)(((lane >> 3) & 1) * 16);

    for (int i = 0; i < NC; i++) {
        cp_wait<PS - 2>();
        __syncthreads();

        int nc = i + PS - 1;
        if (nc < NC) {
            uint32_t st = sb + (nc % PS) * STAGE_BYTES;
#pragma unroll
            for (int h = 0; h < 4; h++) {
                cp16(st + adf[h], asp[h] + nc * KC);
                cp16(st + bdf[h], bsp[h] + nc * KC);
            }
        }
        cp_commit();

        uint32_t st = sb + (i % PS) * STAGE_BYTES;
#pragma unroll
        for (int ks = 0; ks < 4; ks++) {
            uint32_t a[4][4], b[4][2];
#pragma unroll
            for (int mi = 0; mi < 4; mi++) {
                uint32_t addr = st + (a_row + mi * 16) * (LDT*2) + ks * 32 + a_colb;
                ldsm_x4(a[mi][0], a[mi][1], a[mi][2], a[mi][3], addr);
            }
#pragma unroll
            for (int ni = 0; ni < 4; ni++) {
                uint32_t addr = st + TILE_BYTES + (b_row + ni * 8) * (LDT*2)
                              + ks * 32 + b_colb;
                ldsm_x2(b[ni][0], b[ni][1], addr);
            }
#pragma unroll
            for (int mi = 0; mi < 4; mi++)
#pragma unroll
                for (int ni = 0; ni < 4; ni++)
                    mma16816(acc[mi][ni], a[mi], b[ni]);
        }
    }

    const int g = lane >> 2, t = lane & 3;
#pragma unroll
    for (int mi = 0; mi < 4; mi++) {
        int m0 = bm + wm * 64 + mi * 16 + g;
#pragma unroll
        for (int ni = 0; ni < 4; ni++) {
            int n0 = bn + wn * 32 + ni * 8 + 2 * t;
            *(float2*)&C[(size_t)m0 * N + n0] =
                make_float2(acc[mi][ni][0], acc[mi][ni][1]);
            *(float2*)&C[(size_t)(m0 + 8) * N + n0] =
                make_float2(acc[mi][ni][2], acc[mi][ni][3]);
        }
    }
}

// ---------------------------------------------------------------------------
// Sliding-window attention, fully on HMMA, 2 CTAs/SM (Qh/Ph smem alias):
//   QK^T: Q=[hi|lo] fp16 split, softmax on fragments,
//   PV:   P fp16 x V=[hi|lo] fp16 split via ldmatrix.trans.
// ---------------------------------------------------------------------------
__global__ void __launch_bounds__(256, 2)
attn_kernel(const float* __restrict__ qkv, const int* __restrict__ amask,
            const float* __restrict__ tab, __half* __restrict__ attnx)
{
    extern __shared__ __align__(16) char sm[];
    __half* Qh   = (__half*)(sm + QH_OFF);    // [64][136] (aliases Ph)
    __half* Ph   = (__half*)(sm + PH_OFF);    // [64][200] (aliases Qh)
    __half* Kh   = (__half*)(sm + KH_OFF);    // [192][72]
    __half* Vhi  = (__half*)(sm + VHI_OFF);   // [192][72]
    __half* Vlo  = (__half*)(sm + VLO_OFF);   // [192][72]
    float*  pmax = (float*)(sm + PMAX_OFF);   // [4][64]
    float*  psum = (float*)(sm + PSUM_OFF);   // [4][64]
    int*    Ms   = (int*)(sm + MS_OFF);       // [192]

    const int tid = threadIdx.x;
    const int qb = blockIdx.x, h = blockIdx.y, b = blockIdx.z;
    const int q0 = qb * 64;
    const int ks = max(0, q0 - WIN);
    const int ke = min(TT, q0 + 64 + WIN);
    const int klen = ke - ks;
    const float* qbase = qkv + (size_t)b * TT * TD3;

    // ---- Q: load + rope -> fp16 [hi|lo], row-major [q][d] ----
#pragma unroll
    for (int it = 0; it < 2; it++) {
        int item = tid + it * 256;
        int row = item & 63, j4 = item >> 6;
        int t = q0 + row;
        const float* src = qbase + (size_t)t * TD3 + h * HD;
        float4 x0 = *(const float4*)(src + j4 * 4);
        float4 x1 = *(const float4*)(src + j4 * 4 + 32);
        const float4* tb = (const float4*)(tab + (size_t)t * 64 + j4 * 8);
        float4 t0 = tb[0], t1 = tb[1];
        float o[8];
        o[0]=x0.x*t0.x - x1.x*t0.y;  o[1]=x0.x*t0.y + x1.x*t0.x;
        o[2]=x0.y*t0.z - x1.y*t0.w;  o[3]=x0.y*t0.w + x1.y*t0.z;
        o[4]=x0.z*t1.x - x1.z*t1.y;  o[5]=x0.z*t1.y + x1.z*t1.x;
        o[6]=x0.w*t1.z - x1.w*t1.w;  o[7]=x0.w*t1.w + x1.w*t1.z;
        __half hh[8], hl[8];
#pragma unroll
        for (int i = 0; i < 8; i++) {
            hh[i] = __float2half_rn(o[i]);
            hl[i] = __float2half_rn(o[i] - __half2float(hh[i]));
        }
        uint4 ph = make_uint4(packh2(hh[0],hh[1]), packh2(hh[2],hh[3]),
                              packh2(hh[4],hh[5]), packh2(hh[6],hh[7]));
        uint4 pl = make_uint4(packh2(hl[0],hl[1]), packh2(hl[2],hl[3]),
                              packh2(hl[4],hl[5]), packh2(hl[6],hl[7]));
        *(uint4*)(Qh + row * 136 + j4 * 8)      = ph;
        *(uint4*)(Qh + row * 136 + 64 + j4 * 8) = pl;
    }
    // ---- K: load + rope -> fp16 row-major [token][d] ----
#pragma unroll
    for (int it = 0; it < 6; it++) {
        int item = tid + it * 256;
        int kk = item % 192, j4 = item / 192;
        if (kk < klen) {
            int t = ks + kk;
            const float* src = qbase + (size_t)t * TD3 + DD + h * HD;
            float4 x0 = *(const float4*)(src + j4 * 4);
            float4 x1 = *(const float4*)(src + j4 * 4 + 32);
            const float4* tb = (const float4*)(tab + (size_t)t * 64 + j4 * 8);
            float4 t0 = tb[0], t1 = tb[1];
            float o[8];
            o[0]=x0.x*t0.x - x1.x*t0.y;  o[1]=x0.x*t0.y + x1.x*t0.x;
            o[2]=x0.y*t0.z - x1.y*t0.w;  o[3]=x0.y*t0.w + x1.y*t0.z;
            o[4]=x0.z*t1.x - x1.z*t1.y;  o[5]=x0.z*t1.y + x1.z*t1.x;
            o[6]=x0.w*t1.z - x1.w*t1.w;  o[7]=x0.w*t1.w + x1.w*t1.z;
            uint4 ph = make_uint4(
                packh2(__float2half_rn(o[0]),__float2half_rn(o[1])),
                packh2(__float2half_rn(o[2]),__float2half_rn(o[3])),
                packh2(__float2half_rn(o[4]),__float2half_rn(o[5])),
                packh2(__float2half_rn(o[6]),__float2half_rn(o[7])));
            *(uint4*)(Kh + kk * 72 + j4 * 8) = ph;
        }
    }
    // ---- V: load -> [hi|lo] fp16 (zero-fill beyond klen: NaN guard) ----
#pragma unroll
    for (int it = 0; it < 12; it++) {
        int idx = tid + it * 256;
        int kk = idx >> 4, d4 = idx & 15;
        uint2 vh = make_uint2(0u, 0u), vl = make_uint2(0u, 0u);
        if (kk < klen) {
            float4 v = *(const float4*)(qbase + (size_t)(ks+kk)*TD3 + 2*DD + h*HD + d4*4);
            __half h0 = __float2half_rn(v.x), h1 = __float2half_rn(v.y);
            __half h2 = __float2half_rn(v.z), h3 = __float2half_rn(v.w);
            vh = make_uint2(packh2(h0,h1), packh2(h2,h3));
            vl = make_uint2(
                packh2(__float2half_rn(v.x - __half2float(h0)),
                       __float2half_rn(v.y - __half2float(h1))),
                packh2(__float2half_rn(v.z - __half2float(h2)),
                       __float2half_rn(v.w - __half2float(h3))));
        }
        *(uint2*)(Vhi + kk*72 + d4*4) = vh;
        *(uint2*)(Vlo + kk*72 + d4*4) = vl;
    }
    if (tid < 192) Ms[tid] = (tid < klen) ? amask[b*TT + ks + tid] : 0;
    __syncthreads();

    // ---- QK^T on HMMA: warp tile 32(q) x 48(k), K-dim 128 ([hi|lo]) ----
    const int lane = tid & 31;
    const int warp = tid >> 5;
    const int wm = warp & 1;       // q half
    const int wn = warp >> 1;      // k quarter (48 cols)
    const int g = lane >> 2, t = lane & 3;
    const uint32_t qh_base = smem_u32(Qh);
    const uint32_t kh_base = smem_u32(Kh);

    float c[2][6][4];
#pragma unroll
    for (int mi = 0; mi < 2; mi++)
#pragma unroll
        for (int ni = 0; ni < 6; ni++)
#pragma unroll
            for (int r = 0; r < 4; r++) c[mi][ni][r] = 0.f;

    const uint32_t a_row = (uint32_t)(wm * 32 + (lane & 15));
    const uint32_t a_colb = (uint32_t)((lane >> 4) * 16);
    const uint32_t b_row = (uint32_t)(wn * 48 + (lane & 7));
    const uint32_t b_colb = (uint32_t)(((lane >> 3) & 1) * 16);

#pragma unroll
    for (int kstep = 0; kstep < 8; kstep++) {
        uint32_t a[2][4];
#pragma unroll
        for (int mi = 0; mi < 2; mi++)
            ldsm_x4(a[mi][0], a[mi][1], a[mi][2], a[mi][3],
                    qh_base + (a_row + mi * 16) * 272 + kstep * 32 + a_colb);
        uint32_t bf[6][2];
#pragma unroll
        for (int ni = 0; ni < 6; ni++)
            ldsm_x2(bf[ni][0], bf[ni][1],
                    kh_base + (b_row + ni * 8) * 144 + (kstep & 3) * 32 + b_colb);
#pragma unroll
        for (int mi = 0; mi < 2; mi++)
#pragma unroll
            for (int ni = 0; ni < 6; ni++)
                mma16816(c[mi][ni], a[mi], bf[ni]);
    }

    // ---- mask + row max ----
    const float scale = 0.125f;
    float mx[2][2] = { {-1e30f,-1e30f}, {-1e30f,-1e30f} };
#pragma unroll
    for (int mi = 0; mi < 2; mi++)
#pragma unroll
        for (int hh = 0; hh < 2; hh++) {
            int qg = q0 + wm*32 + mi*16 + g + hh*8;
#pragma unroll
            for (int ni = 0; ni < 6; ni++)
#pragma unroll
                for (int cc = 0; cc < 2; cc++) {
                    int kk = wn*48 + ni*8 + 2*t + cc;
                    int kg = ks + kk;
                    bool ok = (Ms[kk] != 0) && (abs(qg - kg) <= WIN);
                    float v = ok ? c[mi][ni][hh*2+cc] * scale : -1e30f;
                    c[mi][ni][hh*2+cc] = v;
                    mx[mi][hh] = fmaxf(mx[mi][hh], v);
                }
        }
#pragma unroll
    for (int mi = 0; mi < 2; mi++)
#pragma unroll
        for (int hh = 0; hh < 2; hh++) {
            float m = mx[mi][hh];
            m = fmaxf(m, __shfl_xor_sync(0xffffffffu, m, 1));
            m = fmaxf(m, __shfl_xor_sync(0xffffffffu, m, 2));
            mx[mi][hh] = m;
        }
    if (t == 0) {
#pragma unroll
        for (int mi = 0; mi < 2; mi++)
#pragma unroll
            for (int hh = 0; hh < 2; hh++)
                pmax[wn*64 + wm*32 + mi*16 + g + hh*8] = mx[mi][hh];
    }
    // This barrier both publishes pmax AND retires all Qh reads -> Ph may
    // now overwrite the aliased region.
    __syncthreads();

    // ---- exp + row sum, write Ph (fp16, aliases Qh) ----
    float sum[2][2] = { {0.f,0.f}, {0.f,0.f} };
#pragma unroll
    for (int mi = 0; mi < 2; mi++)
#pragma unroll
        for (int hh = 0; hh < 2; hh++) {
            int row = wm*32 + mi*16 + g + hh*8;
            float gm = fmaxf(fmaxf(pmax[row], pmax[64+row]),
                             fmaxf(pmax[128+row], pmax[192+row]));
#pragma unroll
            for (int ni = 0; ni < 6; ni++) {
                float e0 = __expf(c[mi][ni][hh*2+0] - gm);
                float e1 = __expf(c[mi][ni][hh*2+1] - gm);
                sum[mi][hh] += e0 + e1;
                *(uint32_t*)(Ph + row*200 + wn*48 + ni*8 + 2*t) =
                    packh2(__float2half_rn(e0), __float2half_rn(e1));
            }
        }
#pragma unroll
    for (int mi = 0; mi < 2; mi++)
#pragma unroll
        for (int hh = 0; hh < 2; hh++) {
            float s = sum[mi][hh];
            s += __shfl_xor_sync(0xffffffffu, s, 1);
            s += __shfl_xor_sync(0xffffffffu, s, 2);
            sum[mi][hh] = s;
        }
    if (t == 0) {
#pragma unroll
        for (int mi = 0; mi < 2; mi++)
#pragma unroll
            for (int hh = 0; hh < 2; hh++)
                psum[wn*64 + wm*32 + mi*16 + g + hh*8] = sum[mi][hh];
    }
    __syncthreads();

    // ---- PV on HMMA: warp tile 32(q) x 16(d), K-dim 192, V=[hi|lo] -------
    const int wm2 = warp & 1;      // q half
    const int wn2 = warp >> 1;     // d quarter (16 cols)
    const uint32_t ph_base  = smem_u32(Ph);
    const uint32_t vhi_base = smem_u32(Vhi);
    const uint32_t vlo_base = smem_u32(Vlo);

    float o[2][2][4];
#pragma unroll
    for (int mi = 0; mi < 2; mi++)
#pragma unroll
        for (int ni = 0; ni < 2; ni++)
#pragma unroll
            for (int r = 0; r < 4; r++) o[mi][ni][r] = 0.f;

    const uint32_t pa_row  = (uint32_t)(wm2 * 32 + (lane & 15));
    const uint32_t pa_colb = (uint32_t)((lane >> 4) * 16);
    const uint32_t v_lane  = (uint32_t)(lane & 15);          // k row within 16

#pragma unroll
    for (int ks2 = 0; ks2 < 12; ks2++) {
        uint32_t a[2][4];
#pragma unroll
        for (int mi = 0; mi < 2; mi++)
            ldsm_x4(a[mi][0], a[mi][1], a[mi][2], a[mi][3],
                    ph_base + (pa_row + mi * 16) * 400 + ks2 * 32 + pa_colb);
        uint32_t bh[2][2], bl[2][2];
#pragma unroll
        for (int ni = 0; ni < 2; ni++) {
            uint32_t off = (ks2 * 16 + v_lane) * 144 + (wn2 * 16 + ni * 8) * 2;
            ldsm_x2t(bh[ni][0], bh[ni][1], vhi_base + off);
            ldsm_x2t(bl[ni][0], bl[ni][1], vlo_base + off);
        }
#pragma unroll
        for (int mi = 0; mi < 2; mi++)
#pragma unroll
            for (int ni = 0; ni < 2; ni++) {
                mma16816(o[mi][ni], a[mi], bh[ni]);
                mma16816(o[mi][ni], a[mi], bl[ni]);
            }
    }

    // ---- epilogue: normalize + write fp16 operand for Wo GEMM ----
#pragma unroll
    for (int mi = 0; mi < 2; mi++)
#pragma unroll
        for (int hh = 0; hh < 2; hh++) {
            int qq = wm2*32 + mi*16 + g + hh*8;
            float tot = psum[qq] + psum[64+qq] + psum[128+qq] + psum[192+qq];
            float r = 1.f / fmaxf(tot, 1e-30f);
#pragma unroll
            for (int ni = 0; ni < 2; ni++) {
                int d = wn2*16 + ni*8 + 2*t;
                uint32_t pair = packh2(__float2half_rn(o[mi][ni][hh*2+0] * r),
                                       __float2half_rn(o[mi][ni][hh*2+1] * r));
                *(uint32_t*)(attnx + (size_t)(b*TT + q0 + qq) * KK + h*HD + d) = pair;
            }
        }
}

// ---------------------------------------------------------------------------
extern "C" void kernel_launch(void* const* d_in, const int* in_sizes, int n_in,
                              void* d_out, int out_size)
{
    const float* hs   = (const float*)d_in[0];
    const int*   am   = (const int*)d_in[1];
    const float* Wqkv = (const float*)d_in[2];
    const float* Wo   = (const float*)d_in[3];
    float* out = (float*)d_out;

    void* p;
    cudaGetSymbolAddress(&p, g_qkv);   float*  qkv   = (float*)p;
    cudaGetSymbolAddress(&p, g_ah);    __half* ah    = (__half*)p;
    cudaGetSymbolAddress(&p, g_attnx); __half* attnx = (__half*)p;
    cudaGetSymbolAddress(&p, g_wqkvh); __half* wqkvh = (__half*)p;
    cudaGetSymbolAddress(&p, g_woh);   __half* woh   = (__half*)p;
    cudaGetSymbolAddress(&p, g_tab);   float*  tab   = (float*)p;

    cudaFuncSetAttribute(attn_kernel,
                         cudaFuncAttributeMaxDynamicSharedMemorySize,
                         ATTN_SMEM_BYTES);
    cudaFuncSetAttribute(gemm_mma,
                         cudaFuncAttributeMaxDynamicSharedMemorySize,
                         GEMM_SMEM);

    const int M = BB * TT;                 // 8192

    // 1) fp32 -> fp16: weights + hidden states
    conv_all<<<((TD3*DD + DD*DD + M*DD)/4 + 255)/256, 256>>>(
        Wqkv, Wo, hs, wqkvh, woh, ah);

    // 2) rope table
    tab_kernel<<<(TT*32)/256, 256>>>(tab);

    // 3) QKV projection
    gemm_mma<<<dim3(TD3/128, M/128), 256, GEMM_SMEM>>>(ah, wqkvh, qkv, TD3);

    // 4) attention (HMMA scores + HMMA PV, 2 CTAs/SM)
    dim3 ga(TT/64, NH, BB);
    attn_kernel<<<ga, 256, ATTN_SMEM_BYTES>>>(qkv, am, tab, attnx);

    // 5) output projection
    gemm_mma<<<dim3(DD/128, M/128), 256, GEMM_SMEM>>>(attnx, woh, out, DD);
}

// round 12
// speedup vs baseline: 6.7674x; 1.2091x over previous
#include <cuda_runtime.h>
#include <cuda_fp16.h>
#include <math.h>
#include <stdint.h>

#define BB 4
#define TT 2048
#define DD 768
#define NH 12
#define HD 64
#define WIN 64
#define TD3 (3*DD)
#define KK 768             // GEMM K (plain fp16 both operands)
#define KC 64              // k per pipeline chunk
#define NC (KK/KC)         // 12 chunks
#define PS 3               // pipeline stages
#define LDT 72             // padded smem row (fp16 elems) -> 144 bytes
#define TILE_BYTES (128*LDT*2)          // 18432 per operand tile
#define STAGE_BYTES (2*TILE_BYTES)      // 36864
#define GEMM_SMEM (PS*STAGE_BYTES)      // 110592

// attention smem layout (bytes).  Qh and Ph ALIAS (same region):
// Qh dead after scores MMAs; Ph first written after the pmax barrier.
#define QH_OFF   0                       // Qh fp16 [64][72]  9216B (alias w/ Ph)
#define PH_OFF   0                       // Ph fp16 [64][200] 25600B
#define KH_OFF   25600                   // Kh fp16 [192][72] 27648B
#define VHI_OFF  53248                   // Vhi fp16 [192][72] 27648B
#define PMAX_OFF 80896                   // fp32 [4][64] 1024B
#define PSUM_OFF 81920                   // fp32 [4][64] 1024B
#define MS_OFF   82944                   // int [192] 768B
#define ATTN_SMEM_BYTES 83712

// ---------------- scratch (device globals: allocation-free rule) -----------
__device__ float  g_qkv[(size_t)BB*TT*TD3];          // [B,T,3D] fp32 (pre-rope)
__device__ __half g_ah  [(size_t)BB*TT*KK];          // hidden fp16
__device__ __half g_attnx[(size_t)BB*TT*KK];         // attn out fp16
__device__ __half g_wqkvh[(size_t)TD3*KK];           // Wqkv fp16
__device__ __half g_woh [(size_t)DD*KK];             // Wo fp16
__device__ float  g_tab [(size_t)TT*64];             // rope (cos,sin) pairs [t][j]

typedef unsigned long long u64;

// ---------------- PTX helpers (baseline ISA only) ---------------------------
__device__ __forceinline__ uint32_t smem_u32(const void* p){
    uint32_t a;
    asm("{ .reg .u64 t; cvta.to.shared.u64 t, %1; cvt.u32.u64 %0, t; }"
        : "=r"(a) : "l"(p));
    return a;
}
__device__ __forceinline__ void cp16(uint32_t d, const void* s){
    asm volatile("cp.async.cg.shared.global [%0], [%1], 16;"
                 :: "r"(d), "l"(s) : "memory");
}
__device__ __forceinline__ void cp_commit(){
    asm volatile("cp.async.commit_group;" ::: "memory");
}
template<int N>
__device__ __forceinline__ void cp_wait(){
    asm volatile("cp.async.wait_group %0;" :: "n"(N) : "memory");
}
__device__ __forceinline__ void ldsm_x4(uint32_t &r0,uint32_t &r1,uint32_t &r2,uint32_t &r3,
                                        uint32_t addr){
    asm volatile("ldmatrix.sync.aligned.m8n8.x4.shared.b16 {%0,%1,%2,%3}, [%4];"
                 : "=r"(r0),"=r"(r1),"=r"(r2),"=r"(r3) : "r"(addr));
}
__device__ __forceinline__ void ldsm_x2(uint32_t &r0,uint32_t &r1, uint32_t addr){
    asm volatile("ldmatrix.sync.aligned.m8n8.x2.shared.b16 {%0,%1}, [%2];"
                 : "=r"(r0),"=r"(r1) : "r"(addr));
}
__device__ __forceinline__ void ldsm_x2t(uint32_t &r0,uint32_t &r1, uint32_t addr){
    asm volatile("ldmatrix.sync.aligned.m8n8.x2.trans.shared.b16 {%0,%1}, [%2];"
                 : "=r"(r0),"=r"(r1) : "r"(addr));
}
__device__ __forceinline__ void mma16816(float* d, const uint32_t* a, const uint32_t* b){
    asm volatile("mma.sync.aligned.m16n8k16.row.col.f32.f16.f16.f32 "
        "{%0,%1,%2,%3}, {%4,%5,%6,%7}, {%8,%9}, {%0,%1,%2,%3};"
        : "+f"(d[0]),"+f"(d[1]),"+f"(d[2]),"+f"(d[3])
        : "r"(a[0]),"r"(a[1]),"r"(a[2]),"r"(a[3]), "r"(b[0]),"r"(b[1]));
}
__device__ __forceinline__ uint32_t packh2(__half a, __half b){
    return (uint32_t)__half_as_ushort(a) | ((uint32_t)__half_as_ushort(b) << 16);
}

// ---------------------------------------------------------------------------
// fp32 -> fp16 conversion (weights + hidden states).
// ---------------------------------------------------------------------------
__global__ void conv_all(const float* __restrict__ wqkv, const float* __restrict__ wo,
                         const float* __restrict__ hs,
                         __half* __restrict__ wqkvh, __half* __restrict__ woh,
                         __half* __restrict__ ah)
{
    const int n1 = TD3*DD/4;
    const int n2 = DD*DD/4;
    const int n3 = BB*TT*DD/4;
    int idx = blockIdx.x * blockDim.x + threadIdx.x;
    if (idx >= n1 + n2 + n3) return;
    const float* src; __half* dst; int i;
    if (idx < n1)            { src = wqkv; dst = wqkvh; i = idx; }
    else if (idx < n1 + n2)  { src = wo;   dst = woh;   i = idx - n1; }
    else                     { src = hs;   dst = ah;    i = idx - n1 - n2; }
    float4 v = *(const float4*)(src + (size_t)i*4);
    uint2 o = make_uint2(packh2(__float2half_rn(v.x), __float2half_rn(v.y)),
                         packh2(__float2half_rn(v.z), __float2half_rn(v.w)));
    *(uint2*)(dst + (size_t)i*4) = o;
}

// ---------------------------------------------------------------------------
// RoPE table: g_tab[t*64 + 2j] = cos(t * 10000^(-j/32)), [.. +1] = sin.
// ---------------------------------------------------------------------------
__global__ void tab_kernel(float* __restrict__ tab)
{
    int idx = blockIdx.x * blockDim.x + threadIdx.x;   // TT*32
    int t = idx >> 5, j = idx & 31;
    const float c0 = 0.41524101186092029f;             // log2(10000)/32
    float inv = exp2f(-c0 * (float)j);
    float sn, cs;
    sincosf((float)t * inv, &sn, &cs);
    tab[t*64 + 2*j]     = cs;
    tab[t*64 + 2*j + 1] = sn;
}

// ---------------------------------------------------------------------------
// HMMA GEMM: C[m,n] = sum_{k<768} A[m,k] * B[n,k]   (fp16 -> fp32)
// ---------------------------------------------------------------------------
__global__ void __launch_bounds__(256, 2)
gemm_mma(const __half* __restrict__ A, const __half* __restrict__ B,
         float* __restrict__ C, int N)
{
    extern __shared__ __align__(16) char smem[];
    const uint32_t sb = smem_u32(smem);
    const int tid  = threadIdx.x;
    const int lane = tid & 31;
    const int warp = tid >> 5;
    const int bm = blockIdx.y * 128;
    const int bn = blockIdx.x * 128;
    const int wm = warp & 1;
    const int wn = warp >> 1;

    const __half* asp[4]; uint32_t adf[4];
    const __half* bsp[4]; uint32_t bdf[4];
#pragma unroll
    for (int h = 0; h < 4; h++) {
        int idx = tid + h * 256;
        int row = idx >> 3, seg = idx & 7;
        asp[h] = A + (size_t)(bm + row) * KK + seg * 8;
        bsp[h] = B + (size_t)(bn + row) * KK + seg * 8;
        adf[h] = (uint32_t)(row * (LDT*2) + seg * 16);
        bdf[h] = adf[h] + TILE_BYTES;
    }

#pragma unroll
    for (int s = 0; s < PS - 1; s++) {
        uint32_t st = sb + s * STAGE_BYTES;
#pragma unroll
        for (int h = 0; h < 4; h++) {
            cp16(st + adf[h], asp[h] + s * KC);
            cp16(st + bdf[h], bsp[h] + s * KC);
        }
        cp_commit();
    }

    float acc[4][4][4];
#pragma unroll
    for (int mi = 0; mi < 4; mi++)
#pragma unroll
        for (int ni = 0; ni < 4; ni++)
#pragma unroll
            for (int r = 0; r < 4; r++) acc[mi][ni][r] = 0.f;

    const uint32_t a_row = (uint32_t)(wm * 64 + (lane & 15));
    const uint32_t a_colb = (uint32_t)((lane >> 4) * 16);
    const uint32_t b_row = (uint32_t)(wn * 32 + (lane & 7));
    const uint32_t b_colb = (uint32_t)(((lane >> 3) & 1) * 16);

    for (int i = 0; i < NC; i++) {
        cp_wait<PS - 2>();
        __syncthreads();

        int nc = i + PS - 1;
        if (nc < NC) {
            uint32_t st = sb + (nc % PS) * STAGE_BYTES;
#pragma unroll
            for (int h = 0; h < 4; h++) {
                cp16(st + adf[h], asp[h] + nc * KC);
                cp16(st + bdf[h], bsp[h] + nc * KC);
            }
        }
        cp_commit();

        uint32_t st = sb + (i % PS) * STAGE_BYTES;
#pragma unroll
        for (int ks = 0; ks < 4; ks++) {
            uint32_t a[4][4], b[4][2];
#pragma unroll
            for (int mi = 0; mi < 4; mi++) {
                uint32_t addr = st + (a_row + mi * 16) * (LDT*2) + ks * 32 + a_colb;
                ldsm_x4(a[mi][0], a[mi][1], a[mi][2], a[mi][3], addr);
            }
#pragma unroll
            for (int ni = 0; ni < 4; ni++) {
                uint32_t addr = st + TILE_BYTES + (b_row + ni * 8) * (LDT*2)
                              + ks * 32 + b_colb;
                ldsm_x2(b[ni][0], b[ni][1], addr);
            }
#pragma unroll
            for (int mi = 0; mi < 4; mi++)
#pragma unroll
                for (int ni = 0; ni < 4; ni++)
                    mma16816(acc[mi][ni], a[mi], b[ni]);
        }
    }

    const int g = lane >> 2, t = lane & 3;
#pragma unroll
    for (int mi = 0; mi < 4; mi++) {
        int m0 = bm + wm * 64 + mi * 16 + g;
#pragma unroll
        for (int ni = 0; ni < 4; ni++) {
            int n0 = bn + wn * 32 + ni * 8 + 2 * t;
            *(float2*)&C[(size_t)m0 * N + n0] =
                make_float2(acc[mi][ni][0], acc[mi][ni][1]);
            *(float2*)&C[(size_t)(m0 + 8) * N + n0] =
                make_float2(acc[mi][ni][2], acc[mi][ni][3]);
        }
    }
}

// ---------------------------------------------------------------------------
// Sliding-window attention, fully on HMMA, 2 CTAs/SM:
//   QK^T: Q,K plain fp16 (K-dim 64), softmax on fragments,
//   PV:   P fp16 x V fp16 via ldmatrix.trans.
// ---------------------------------------------------------------------------
__global__ void __launch_bounds__(256, 2)
attn_kernel(const float* __restrict__ qkv, const int* __restrict__ amask,
            const float* __restrict__ tab, __half* __restrict__ attnx)
{
    extern __shared__ __align__(16) char sm[];
    __half* Qh   = (__half*)(sm + QH_OFF);    // [64][72]  (aliases Ph)
    __half* Ph   = (__half*)(sm + PH_OFF);    // [64][200] (aliases Qh)
    __half* Kh   = (__half*)(sm + KH_OFF);    // [192][72]
    __half* Vhi  = (__half*)(sm + VHI_OFF);   // [192][72]
    float*  pmax = (float*)(sm + PMAX_OFF);   // [4][64]
    float*  psum = (float*)(sm + PSUM_OFF);   // [4][64]
    int*    Ms   = (int*)(sm + MS_OFF);       // [192]

    const int tid = threadIdx.x;
    const int qb = blockIdx.x, h = blockIdx.y, b = blockIdx.z;
    const int q0 = qb * 64;
    const int ks = max(0, q0 - WIN);
    const int ke = min(TT, q0 + 64 + WIN);
    const int klen = ke - ks;
    const float* qbase = qkv + (size_t)b * TT * TD3;

    // ---- Q: load + rope -> fp16, row-major [q][d] (2 items/thread) ----
#pragma unroll
    for (int it = 0; it < 2; it++) {
        int item = tid + it * 256;
        int row = item & 63, j4 = item >> 6;
        int t = q0 + row;
        const float* src = qbase + (size_t)t * TD3 + h * HD;
        float4 x0 = *(const float4*)(src + j4 * 4);
        float4 x1 = *(const float4*)(src + j4 * 4 + 32);
        const float4* tb = (const float4*)(tab + (size_t)t * 64 + j4 * 8);
        float4 t0 = tb[0], t1 = tb[1];
        float o[8];
        o[0]=x0.x*t0.x - x1.x*t0.y;  o[1]=x0.x*t0.y + x1.x*t0.x;
        o[2]=x0.y*t0.z - x1.y*t0.w;  o[3]=x0.y*t0.w + x1.y*t0.z;
        o[4]=x0.z*t1.x - x1.z*t1.y;  o[5]=x0.z*t1.y + x1.z*t1.x;
        o[6]=x0.w*t1.z - x1.w*t1.w;  o[7]=x0.w*t1.w + x1.w*t1.z;
        uint4 ph = make_uint4(
            packh2(__float2half_rn(o[0]),__float2half_rn(o[1])),
            packh2(__float2half_rn(o[2]),__float2half_rn(o[3])),
            packh2(__float2half_rn(o[4]),__float2half_rn(o[5])),
            packh2(__float2half_rn(o[6]),__float2half_rn(o[7])));
        *(uint4*)(Qh + row * 72 + j4 * 8) = ph;
    }
    // ---- K: load + rope -> fp16 row-major [token][d] ----
#pragma unroll
    for (int it = 0; it < 6; it++) {
        int item = tid + it * 256;
        int kk = item % 192, j4 = item / 192;
        if (kk < klen) {
            int t = ks + kk;
            const float* src = qbase + (size_t)t * TD3 + DD + h * HD;
            float4 x0 = *(const float4*)(src + j4 * 4);
            float4 x1 = *(const float4*)(src + j4 * 4 + 32);
            const float4* tb = (const float4*)(tab + (size_t)t * 64 + j4 * 8);
            float4 t0 = tb[0], t1 = tb[1];
            float o[8];
            o[0]=x0.x*t0.x - x1.x*t0.y;  o[1]=x0.x*t0.y + x1.x*t0.x;
            o[2]=x0.y*t0.z - x1.y*t0.w;  o[3]=x0.y*t0.w + x1.y*t0.z;
            o[4]=x0.z*t1.x - x1.z*t1.y;  o[5]=x0.z*t1.y + x1.z*t1.x;
            o[6]=x0.w*t1.z - x1.w*t1.w;  o[7]=x0.w*t1.w + x1.w*t1.z;
            uint4 ph = make_uint4(
                packh2(__float2half_rn(o[0]),__float2half_rn(o[1])),
                packh2(__float2half_rn(o[2]),__float2half_rn(o[3])),
                packh2(__float2half_rn(o[4]),__float2half_rn(o[5])),
                packh2(__float2half_rn(o[6]),__float2half_rn(o[7])));
            *(uint4*)(Kh + kk * 72 + j4 * 8) = ph;
        }
    }
    // ---- V: load -> fp16 (zero-fill beyond klen: NaN guard) ----
#pragma unroll
    for (int it = 0; it < 12; it++) {
        int idx = tid + it * 256;
        int kk = idx >> 4, d4 = idx & 15;
        uint2 vh = make_uint2(0u, 0u);
        if (kk < klen) {
            float4 v = *(const float4*)(qbase + (size_t)(ks+kk)*TD3 + 2*DD + h*HD + d4*4);
            vh = make_uint2(packh2(__float2half_rn(v.x), __float2half_rn(v.y)),
                            packh2(__float2half_rn(v.z), __float2half_rn(v.w)));
        }
        *(uint2*)(Vhi + kk*72 + d4*4) = vh;
    }
    if (tid < 192) Ms[tid] = (tid < klen) ? amask[b*TT + ks + tid] : 0;
    __syncthreads();

    // ---- QK^T on HMMA: warp tile 32(q) x 48(k), K-dim 64 ----
    const int lane = tid & 31;
    const int warp = tid >> 5;
    const int wm = warp & 1;       // q half
    const int wn = warp >> 1;      // k quarter (48 cols)
    const int g = lane >> 2, t = lane & 3;
    const uint32_t qh_base = smem_u32(Qh);
    const uint32_t kh_base = smem_u32(Kh);

    float c[2][6][4];
#pragma unroll
    for (int mi = 0; mi < 2; mi++)
#pragma unroll
        for (int ni = 0; ni < 6; ni++)
#pragma unroll
            for (int r = 0; r < 4; r++) c[mi][ni][r] = 0.f;

    const uint32_t a_row = (uint32_t)(wm * 32 + (lane & 15));
    const uint32_t a_colb = (uint32_t)((lane >> 4) * 16);
    const uint32_t b_row = (uint32_t)(wn * 48 + (lane & 7));
    const uint32_t b_colb = (uint32_t)(((lane >> 3) & 1) * 16);

#pragma unroll
    for (int kstep = 0; kstep < 4; kstep++) {
        uint32_t a[2][4];
#pragma unroll
        for (int mi = 0; mi < 2; mi++)
            ldsm_x4(a[mi][0], a[mi][1], a[mi][2], a[mi][3],
                    qh_base + (a_row + mi * 16) * 144 + kstep * 32 + a_colb);
        uint32_t bf[6][2];
#pragma unroll
        for (int ni = 0; ni < 6; ni++)
            ldsm_x2(bf[ni][0], bf[ni][1],
                    kh_base + (b_row + ni * 8) * 144 + kstep * 32 + b_colb);
#pragma unroll
        for (int mi = 0; mi < 2; mi++)
#pragma unroll
            for (int ni = 0; ni < 6; ni++)
                mma16816(c[mi][ni], a[mi], bf[ni]);
    }

    // ---- mask + row max ----
    const float scale = 0.125f;
    float mx[2][2] = { {-1e30f,-1e30f}, {-1e30f,-1e30f} };
#pragma unroll
    for (int mi = 0; mi < 2; mi++)
#pragma unroll
        for (int hh = 0; hh < 2; hh++) {
            int qg = q0 + wm*32 + mi*16 + g + hh*8;
#pragma unroll
            for (int ni = 0; ni < 6; ni++)
#pragma unroll
                for (int cc = 0; cc < 2; cc++) {
                    int kk = wn*48 + ni*8 + 2*t + cc;
                    int kg = ks + kk;
                    bool ok = (Ms[kk] != 0) && (abs(qg - kg) <= WIN);
                    float v = ok ? c[mi][ni][hh*2+cc] * scale : -1e30f;
                    c[mi][ni][hh*2+cc] = v;
                    mx[mi][hh] = fmaxf(mx[mi][hh], v);
                }
        }
#pragma unroll
    for (int mi = 0; mi < 2; mi++)
#pragma unroll
        for (int hh = 0; hh < 2; hh++) {
            float m = mx[mi][hh];
            m = fmaxf(m, __shfl_xor_sync(0xffffffffu, m, 1));
            m = fmaxf(m, __shfl_xor_sync(0xffffffffu, m, 2));
            mx[mi][hh] = m;
        }
    if (t == 0) {
#pragma unroll
        for (int mi = 0; mi < 2; mi++)
#pragma unroll
            for (int hh = 0; hh < 2; hh++)
                pmax[wn*64 + wm*32 + mi*16 + g + hh*8] = mx[mi][hh];
    }
    // Barrier publishes pmax AND retires all Qh reads -> Ph may overwrite.
    __syncthreads();

    // ---- exp + row sum, write Ph (fp16, aliases Qh) ----
    float sum[2][2] = { {0.f,0.f}, {0.f,0.f} };
#pragma unroll
    for (int mi = 0; mi < 2; mi++)
#pragma unroll
        for (int hh = 0; hh < 2; hh++) {
            int row = wm*32 + mi*16 + g + hh*8;
            float gm = fmaxf(fmaxf(pmax[row], pmax[64+row]),
                             fmaxf(pmax[128+row], pmax[192+row]));
#pragma unroll
            for (int ni = 0; ni < 6; ni++) {
                float e0 = __expf(c[mi][ni][hh*2+0] - gm);
                float e1 = __expf(c[mi][ni][hh*2+1] - gm);
                sum[mi][hh] += e0 + e1;
                *(uint32_t*)(Ph + row*200 + wn*48 + ni*8 + 2*t) =
                    packh2(__float2half_rn(e0), __float2half_rn(e1));
            }
        }
#pragma unroll
    for (int mi = 0; mi < 2; mi++)
#pragma unroll
        for (int hh = 0; hh < 2; hh++) {
            float s = sum[mi][hh];
            s += __shfl_xor_sync(0xffffffffu, s, 1);
            s += __shfl_xor_sync(0xffffffffu, s, 2);
            sum[mi][hh] = s;
        }
    if (t == 0) {
#pragma unroll
        for (int mi = 0; mi < 2; mi++)
#pragma unroll
            for (int hh = 0; hh < 2; hh++)
                psum[wn*64 + wm*32 + mi*16 + g + hh*8] = sum[mi][hh];
    }
    __syncthreads();

    // ---- PV on HMMA: warp tile 32(q) x 16(d), K-dim 192 ----
    const int wm2 = warp & 1;      // q half
    const int wn2 = warp >> 1;     // d quarter (16 cols)
    const uint32_t ph_base  = smem_u32(Ph);
    const uint32_t vhi_base = smem_u32(Vhi);

    float o[2][2][4];
#pragma unroll
    for (int mi = 0; mi < 2; mi++)
#pragma unroll
        for (int ni = 0; ni < 2; ni++)
#pragma unroll
            for (int r = 0; r < 4; r++) o[mi][ni][r] = 0.f;

    const uint32_t pa_row  = (uint32_t)(wm2 * 32 + (lane & 15));
    const uint32_t pa_colb = (uint32_t)((lane >> 4) * 16);
    const uint32_t v_lane  = (uint32_t)(lane & 15);          // k row within 16

#pragma unroll
    for (int ks2 = 0; ks2 < 12; ks2++) {
        uint32_t a[2][4];
#pragma unroll
        for (int mi = 0; mi < 2; mi++)
            ldsm_x4(a[mi][0], a[mi][1], a[mi][2], a[mi][3],
                    ph_base + (pa_row + mi * 16) * 400 + ks2 * 32 + pa_colb);
        uint32_t bh[2][2];
#pragma unroll
        for (int ni = 0; ni < 2; ni++) {
            uint32_t off = (ks2 * 16 + v_lane) * 144 + (wn2 * 16 + ni * 8) * 2;
            ldsm_x2t(bh[ni][0], bh[ni][1], vhi_base + off);
        }
#pragma unroll
        for (int mi = 0; mi < 2; mi++)
#pragma unroll
            for (int ni = 0; ni < 2; ni++)
                mma16816(o[mi][ni], a[mi], bh[ni]);
    }

    // ---- epilogue: normalize + write fp16 operand for Wo GEMM ----
#pragma unroll
    for (int mi = 0; mi < 2; mi++)
#pragma unroll
        for (int hh = 0; hh < 2; hh++) {
            int qq = wm2*32 + mi*16 + g + hh*8;
            float tot = psum[qq] + psum[64+qq] + psum[128+qq] + psum[192+qq];
            float r = 1.f / fmaxf(tot, 1e-30f);
#pragma unroll
            for (int ni = 0; ni < 2; ni++) {
                int d = wn2*16 + ni*8 + 2*t;
                uint32_t pair = packh2(__float2half_rn(o[mi][ni][hh*2+0] * r),
                                       __float2half_rn(o[mi][ni][hh*2+1] * r));
                *(uint32_t*)(attnx + (size_t)(b*TT + q0 + qq) * KK + h*HD + d) = pair;
            }
        }
}

// ---------------------------------------------------------------------------
extern "C" void kernel_launch(void* const* d_in, const int* in_sizes, int n_in,
                              void* d_out, int out_size)
{
    const float* hs   = (const float*)d_in[0];
    const int*   am   = (const int*)d_in[1];
    const float* Wqkv = (const float*)d_in[2];
    const float* Wo   = (const float*)d_in[3];
    float* out = (float*)d_out;

    void* p;
    cudaGetSymbolAddress(&p, g_qkv);   float*  qkv   = (float*)p;
    cudaGetSymbolAddress(&p, g_ah);    __half* ah    = (__half*)p;
    cudaGetSymbolAddress(&p, g_attnx); __half* attnx = (__half*)p;
    cudaGetSymbolAddress(&p, g_wqkvh); __half* wqkvh = (__half*)p;
    cudaGetSymbolAddress(&p, g_woh);   __half* woh   = (__half*)p;
    cudaGetSymbolAddress(&p, g_tab);   float*  tab   = (float*)p;

    cudaFuncSetAttribute(attn_kernel,
                         cudaFuncAttributeMaxDynamicSharedMemorySize,
                         ATTN_SMEM_BYTES);
    cudaFuncSetAttribute(gemm_mma,
                         cudaFuncAttributeMaxDynamicSharedMemorySize,
                         GEMM_SMEM);

    const int M = BB * TT;                 // 8192

    // 1) fp32 -> fp16: weights + hidden states
    conv_all<<<((TD3*DD + DD*DD + M*DD)/4 + 255)/256, 256>>>(
        Wqkv, Wo, hs, wqkvh, woh, ah);

    // 2) rope table
    tab_kernel<<<(TT*32)/256, 256>>>(tab);

    // 3) QKV projection
    gemm_mma<<<dim3(TD3/128, M/128), 256, GEMM_SMEM>>>(ah, wqkvh, qkv, TD3);

    // 4) attention (HMMA scores + HMMA PV, plain fp16 Q/K/V)
    dim3 ga(TT/64, NH, BB);
    attn_kernel<<<ga, 256, ATTN_SMEM_BYTES>>>(qkv, am, tab, attnx);

    // 5) output projection
    gemm_mma<<<dim3(DD/128, M/128), 256, GEMM_SMEM>>>(attnx, woh, out, DD);
}

// round 13
// speedup vs baseline: 6.8672x; 1.0147x over previous
#include <cuda_runtime.h>
#include <cuda_fp16.h>
#include <math.h>
#include <stdint.h>

#define BB 4
#define TT 2048
#define DD 768
#define NH 12
#define HD 64
#define WIN 64
#define TD3 (3*DD)
#define KK 768             // GEMM K (plain fp16 both operands)
#define KC 64              // k per pipeline chunk
#define NC (KK/KC)         // 12 chunks
#define PS 3               // pipeline stages
#define LDT 72             // padded smem row (fp16 elems) -> 144 bytes
#define TILE_BYTES (128*LDT*2)          // 18432 per operand tile
#define STAGE_BYTES (2*TILE_BYTES)      // 36864
#define GEMM_SMEM (PS*STAGE_BYTES)      // 110592

// attention smem layout (bytes).  Qh and Ph ALIAS (same region).
#define QH_OFF   0                       // Qh fp16 [64][72]  9216B (alias w/ Ph)
#define PH_OFF   0                       // Ph fp16 [64][200] 25600B
#define KH_OFF   25600                   // Kh fp16 [192][72] 27648B
#define VHI_OFF  53248                   // Vhi fp16 [192][72] 27648B
#define PMAX_OFF 80896                   // fp32 [4][64] 1024B
#define PSUM_OFF 81920                   // fp32 [4][64] 1024B
#define MS_OFF   82944                   // int [192] 768B
#define ATTN_SMEM_BYTES 83712

// ---------------- scratch (device globals: allocation-free rule) -----------
__device__ __half g_qkvh[(size_t)BB*TT*TD3];         // [B,T,3D] fp16 (pre-rope)
__device__ __half g_ah  [(size_t)BB*TT*KK];          // hidden fp16
__device__ __half g_attnx[(size_t)BB*TT*KK];         // attn out fp16
__device__ __half g_wqkvh[(size_t)TD3*KK];           // Wqkv fp16
__device__ __half g_woh [(size_t)DD*KK];             // Wo fp16
__device__ float  g_tab [(size_t)TT*64];             // rope (cos,sin) pairs [t][j]

typedef unsigned long long u64;

// ---------------- PTX helpers (baseline ISA only) ---------------------------
__device__ __forceinline__ uint32_t smem_u32(const void* p){
    uint32_t a;
    asm("{ .reg .u64 t; cvta.to.shared.u64 t, %1; cvt.u32.u64 %0, t; }"
        : "=r"(a) : "l"(p));
    return a;
}
__device__ __forceinline__ void cp16(uint32_t d, const void* s){
    asm volatile("cp.async.cg.shared.global [%0], [%1], 16;"
                 :: "r"(d), "l"(s) : "memory");
}
__device__ __forceinline__ void cp_commit(){
    asm volatile("cp.async.commit_group;" ::: "memory");
}
template<int N>
__device__ __forceinline__ void cp_wait(){
    asm volatile("cp.async.wait_group %0;" :: "n"(N) : "memory");
}
__device__ __forceinline__ void ldsm_x4(uint32_t &r0,uint32_t &r1,uint32_t &r2,uint32_t &r3,
                                        uint32_t addr){
    asm volatile("ldmatrix.sync.aligned.m8n8.x4.shared.b16 {%0,%1,%2,%3}, [%4];"
                 : "=r"(r0),"=r"(r1),"=r"(r2),"=r"(r3) : "r"(addr));
}
__device__ __forceinline__ void ldsm_x2(uint32_t &r0,uint32_t &r1, uint32_t addr){
    asm volatile("ldmatrix.sync.aligned.m8n8.x2.shared.b16 {%0,%1}, [%2];"
                 : "=r"(r0),"=r"(r1) : "r"(addr));
}
__device__ __forceinline__ void ldsm_x2t(uint32_t &r0,uint32_t &r1, uint32_t addr){
    asm volatile("ldmatrix.sync.aligned.m8n8.x2.trans.shared.b16 {%0,%1}, [%2];"
                 : "=r"(r0),"=r"(r1) : "r"(addr));
}
__device__ __forceinline__ void mma16816(float* d, const uint32_t* a, const uint32_t* b){
    asm volatile("mma.sync.aligned.m16n8k16.row.col.f32.f16.f16.f32 "
        "{%0,%1,%2,%3}, {%4,%5,%6,%7}, {%8,%9}, {%0,%1,%2,%3};"
        : "+f"(d[0]),"+f"(d[1]),"+f"(d[2]),"+f"(d[3])
        : "r"(a[0]),"r"(a[1]),"r"(a[2]),"r"(a[3]), "r"(b[0]),"r"(b[1]));
}
__device__ __forceinline__ uint32_t packh2(__half a, __half b){
    return (uint32_t)__half_as_ushort(a) | ((uint32_t)__half_as_ushort(b) << 16);
}

// ---------------------------------------------------------------------------
// fp32 -> fp16 conversion (weights + hidden states).
// ---------------------------------------------------------------------------
__global__ void conv_all(const float* __restrict__ wqkv, const float* __restrict__ wo,
                         const float* __restrict__ hs,
                         __half* __restrict__ wqkvh, __half* __restrict__ woh,
                         __half* __restrict__ ah)
{
    const int n1 = TD3*DD/4;
    const int n2 = DD*DD/4;
    const int n3 = BB*TT*DD/4;
    int idx = blockIdx.x * blockDim.x + threadIdx.x;
    if (idx >= n1 + n2 + n3) return;
    const float* src; __half* dst; int i;
    if (idx < n1)            { src = wqkv; dst = wqkvh; i = idx; }
    else if (idx < n1 + n2)  { src = wo;   dst = woh;   i = idx - n1; }
    else                     { src = hs;   dst = ah;    i = idx - n1 - n2; }
    float4 v = *(const float4*)(src + (size_t)i*4);
    uint2 o = make_uint2(packh2(__float2half_rn(v.x), __float2half_rn(v.y)),
                         packh2(__float2half_rn(v.z), __float2half_rn(v.w)));
    *(uint2*)(dst + (size_t)i*4) = o;
}

// ---------------------------------------------------------------------------
// RoPE table: g_tab[t*64 + 2j] = cos(t * 10000^(-j/32)), [.. +1] = sin.
// ---------------------------------------------------------------------------
__global__ void tab_kernel(float* __restrict__ tab)
{
    int idx = blockIdx.x * blockDim.x + threadIdx.x;   // TT*32
    int t = idx >> 5, j = idx & 31;
    const float c0 = 0.41524101186092029f;             // log2(10000)/32
    float inv = exp2f(-c0 * (float)j);
    float sn, cs;
    sincosf((float)t * inv, &sn, &cs);
    tab[t*64 + 2*j]     = cs;
    tab[t*64 + 2*j + 1] = sn;
}

// ---------------------------------------------------------------------------
// HMMA GEMM: C[m,n] = sum_{k<768} A[m,k] * B[n,k]   (fp16 -> fp32 or fp16)
// Templated epilogue: HOUT=true stores __half C, else float C.
// ---------------------------------------------------------------------------
template<bool HOUT>
__global__ void __launch_bounds__(256, 2)
gemm_mma(const __half* __restrict__ A, const __half* __restrict__ B,
         void* __restrict__ Cv, int N)
{
    extern __shared__ __align__(16) char smem[];
    const uint32_t sb = smem_u32(smem);
    const int tid  = threadIdx.x;
    const int lane = tid & 31;
    const int warp = tid >> 5;
    const int bm = blockIdx.y * 128;
    const int bn = blockIdx.x * 128;
    const int wm = warp & 1;
    const int wn = warp >> 1;

    const __half* asp[4]; uint32_t adf[4];
    const __half* bsp[4]; uint32_t bdf[4];
#pragma unroll
    for (int h = 0; h < 4; h++) {
        int idx = tid + h * 256;
        int row = idx >> 3, seg = idx & 7;
        asp[h] = A + (size_t)(bm + row) * KK + seg * 8;
        bsp[h] = B + (size_t)(bn + row) * KK + seg * 8;
        adf[h] = (uint32_t)(row * (LDT*2) + seg * 16);
        bdf[h] = adf[h] + TILE_BYTES;
    }

#pragma unroll
    for (int s = 0; s < PS - 1; s++) {
        uint32_t st = sb + s * STAGE_BYTES;
#pragma unroll
        for (int h = 0; h < 4; h++) {
            cp16(st + adf[h], asp[h] + s * KC);
            cp16(st + bdf[h], bsp[h] + s * KC);
        }
        cp_commit();
    }

    float acc[4][4][4];
#pragma unroll
    for (int mi = 0; mi < 4; mi++)
#pragma unroll
        for (int ni = 0; ni < 4; ni++)
#pragma unroll
            for (int r = 0; r < 4; r++) acc[mi][ni][r] = 0.f;

    const uint32_t a_row = (uint32_t)(wm * 64 + (lane & 15));
    const uint32_t a_colb = (uint32_t)((lane >> 4) * 16);
    const uint32_t b_row = (uint32_t)(wn * 32 + (lane & 7));
    const uint32_t b_colb = (uint32_t)(((lane >> 3) & 1) * 16);

    for (int i = 0; i < NC; i++) {
        cp_wait<PS - 2>();
        __syncthreads();

        int nc = i + PS - 1;
        if (nc < NC) {
            uint32_t st = sb + (nc % PS) * STAGE_BYTES;
#pragma unroll
            for (int h = 0; h < 4; h++) {
                cp16(st + adf[h], asp[h] + nc * KC);
                cp16(st + bdf[h], bsp[h] + nc * KC);
            }
        }
        cp_commit();

        uint32_t st = sb + (i % PS) * STAGE_BYTES;
#pragma unroll
        for (int ks = 0; ks < 4; ks++) {
            uint32_t a[4][4], b[4][2];
#pragma unroll
            for (int mi = 0; mi < 4; mi++) {
                uint32_t addr = st + (a_row + mi * 16) * (LDT*2) + ks * 32 + a_colb;
                ldsm_x4(a[mi][0], a[mi][1], a[mi][2], a[mi][3], addr);
            }
#pragma unroll
            for (int ni = 0; ni < 4; ni++) {
                uint32_t addr = st + TILE_BYTES + (b_row + ni * 8) * (LDT*2)
                              + ks * 32 + b_colb;
                ldsm_x2(b[ni][0], b[ni][1], addr);
            }
#pragma unroll
            for (int mi = 0; mi < 4; mi++)
#pragma unroll
                for (int ni = 0; ni < 4; ni++)
                    mma16816(acc[mi][ni], a[mi], b[ni]);
        }
    }

    const int g = lane >> 2, t = lane & 3;
#pragma unroll
    for (int mi = 0; mi < 4; mi++) {
        int m0 = bm + wm * 64 + mi * 16 + g;
#pragma unroll
        for (int ni = 0; ni < 4; ni++) {
            int n0 = bn + wn * 32 + ni * 8 + 2 * t;
            if (HOUT) {
                __half* C = (__half*)Cv;
                *(uint32_t*)&C[(size_t)m0 * N + n0] =
                    packh2(__float2half_rn(acc[mi][ni][0]),
                           __float2half_rn(acc[mi][ni][1]));
                *(uint32_t*)&C[(size_t)(m0 + 8) * N + n0] =
                    packh2(__float2half_rn(acc[mi][ni][2]),
                           __float2half_rn(acc[mi][ni][3]));
            } else {
                float* C = (float*)Cv;
                *(float2*)&C[(size_t)m0 * N + n0] =
                    make_float2(acc[mi][ni][0], acc[mi][ni][1]);
                *(float2*)&C[(size_t)(m0 + 8) * N + n0] =
                    make_float2(acc[mi][ni][2], acc[mi][ni][3]);
            }
        }
    }
}

// ---------------------------------------------------------------------------
// Sliding-window attention, fully on HMMA, 2 CTAs/SM, fp16 qkv input:
//   Q/K: fp16 loads + fp32 rope -> fp16 smem,
//   V:   pure cp.async global->smem copy (no register round trip),
//   QK^T + softmax-on-fragments + PV all as before.
// ---------------------------------------------------------------------------
__global__ void __launch_bounds__(256, 2)
attn_kernel(const __half* __restrict__ qkvh, const int* __restrict__ amask,
            const float* __restrict__ tab, __half* __restrict__ attnx)
{
    extern __shared__ __align__(16) char sm[];
    __half* Qh   = (__half*)(sm + QH_OFF);    // [64][72]  (aliases Ph)
    __half* Ph   = (__half*)(sm + PH_OFF);    // [64][200] (aliases Qh)
    __half* Kh   = (__half*)(sm + KH_OFF);    // [192][72]
    __half* Vhi  = (__half*)(sm + VHI_OFF);   // [192][72]
    float*  pmax = (float*)(sm + PMAX_OFF);   // [4][64]
    float*  psum = (float*)(sm + PSUM_OFF);   // [4][64]
    int*    Ms   = (int*)(sm + MS_OFF);       // [192]

    const int tid = threadIdx.x;
    const int qb = blockIdx.x, h = blockIdx.y, b = blockIdx.z;
    const int q0 = qb * 64;
    const int ks = max(0, q0 - WIN);
    const int ke = min(TT, q0 + 64 + WIN);
    const int klen = ke - ks;
    const __half* qbase = qkvh + (size_t)b * TT * TD3;
    const uint32_t vhi_smem = smem_u32(Vhi);

    // ---- V: cp.async copy (zero-fill beyond klen) ----
#pragma unroll
    for (int it = 0; it < 6; it++) {
        int idx = tid + it * 256;
        int kk = idx >> 3, seg = idx & 7;
        if (kk < klen) {
            cp16(vhi_smem + kk * 144 + seg * 16,
                 qbase + (size_t)(ks + kk) * TD3 + 2*DD + h*HD + seg * 8);
        } else {
            *(uint4*)(Vhi + kk*72 + seg*8) = make_uint4(0u,0u,0u,0u);
        }
    }
    cp_commit();

    // ---- Q: fp16 load + fp32 rope -> fp16, row-major [q][d] ----
#pragma unroll
    for (int it = 0; it < 2; it++) {
        int item = tid + it * 256;
        int row = item & 63, j4 = item >> 6;
        int t = q0 + row;
        const __half* src = qbase + (size_t)t * TD3 + h * HD;
        uint2 u0 = *(const uint2*)(src + j4 * 4);
        uint2 u1 = *(const uint2*)(src + j4 * 4 + 32);
        float2 f0 = __half22float2(*(__half2*)&u0.x);
        float2 f1 = __half22float2(*(__half2*)&u0.y);
        float2 f2 = __half22float2(*(__half2*)&u1.x);
        float2 f3 = __half22float2(*(__half2*)&u1.y);
        const float4* tb = (const float4*)(tab + (size_t)t * 64 + j4 * 8);
        float4 t0 = tb[0], t1 = tb[1];
        float o[8];
        o[0]=f0.x*t0.x - f2.x*t0.y;  o[1]=f0.x*t0.y + f2.x*t0.x;
        o[2]=f0.y*t0.z - f2.y*t0.w;  o[3]=f0.y*t0.w + f2.y*t0.z;
        o[4]=f1.x*t1.x - f3.x*t1.y;  o[5]=f1.x*t1.y + f3.x*t1.x;
        o[6]=f1.y*t1.z - f3.y*t1.w;  o[7]=f1.y*t1.w + f3.y*t1.z;
        uint4 ph = make_uint4(
            packh2(__float2half_rn(o[0]),__float2half_rn(o[1])),
            packh2(__float2half_rn(o[2]),__float2half_rn(o[3])),
            packh2(__float2half_rn(o[4]),__float2half_rn(o[5])),
            packh2(__float2half_rn(o[6]),__float2half_rn(o[7])));
        *(uint4*)(Qh + row * 72 + j4 * 8) = ph;
    }
    // ---- K: fp16 load + fp32 rope -> fp16 row-major [token][d] ----
#pragma unroll
    for (int it = 0; it < 6; it++) {
        int item = tid + it * 256;
        int kk = item % 192, j4 = item / 192;
        if (kk < klen) {
            int t = ks + kk;
            const __half* src = qbase + (size_t)t * TD3 + DD + h * HD;
            uint2 u0 = *(const uint2*)(src + j4 * 4);
            uint2 u1 = *(const uint2*)(src + j4 * 4 + 32);
            float2 f0 = __half22float2(*(__half2*)&u0.x);
            float2 f1 = __half22float2(*(__half2*)&u0.y);
            float2 f2 = __half22float2(*(__half2*)&u1.x);
            float2 f3 = __half22float2(*(__half2*)&u1.y);
            const float4* tb = (const float4*)(tab + (size_t)t * 64 + j4 * 8);
            float4 t0 = tb[0], t1 = tb[1];
            float o[8];
            o[0]=f0.x*t0.x - f2.x*t0.y;  o[1]=f0.x*t0.y + f2.x*t0.x;
            o[2]=f0.y*t0.z - f2.y*t0.w;  o[3]=f0.y*t0.w + f2.y*t0.z;
            o[4]=f1.x*t1.x - f3.x*t1.y;  o[5]=f1.x*t1.y + f3.x*t1.x;
            o[6]=f1.y*t1.z - f3.y*t1.w;  o[7]=f1.y*t1.w + f3.y*t1.z;
            uint4 ph = make_uint4(
                packh2(__float2half_rn(o[0]),__float2half_rn(o[1])),
                packh2(__float2half_rn(o[2]),__float2half_rn(o[3])),
                packh2(__float2half_rn(o[4]),__float2half_rn(o[5])),
                packh2(__float2half_rn(o[6]),__float2half_rn(o[7])));
            *(uint4*)(Kh + kk * 72 + j4 * 8) = ph;
        }
    }
    if (tid < 192) Ms[tid] = (tid < klen) ? amask[b*TT + ks + tid] : 0;
    cp_wait<0>();
    __syncthreads();

    // ---- QK^T on HMMA: warp tile 32(q) x 48(k), K-dim 64 ----
    const int lane = tid & 31;
    const int warp = tid >> 5;
    const int wm = warp & 1;       // q half
    const int wn = warp >> 1;      // k quarter (48 cols)
    const int g = lane >> 2, t = lane & 3;
    const uint32_t qh_base = smem_u32(Qh);
    const uint32_t kh_base = smem_u32(Kh);

    float c[2][6][4];
#pragma unroll
    for (int mi = 0; mi < 2; mi++)
#pragma unroll
        for (int ni = 0; ni < 6; ni++)
#pragma unroll
            for (int r = 0; r < 4; r++) c[mi][ni][r] = 0.f;

    const uint32_t a_row = (uint32_t)(wm * 32 + (lane & 15));
    const uint32_t a_colb = (uint32_t)((lane >> 4) * 16);
    const uint32_t b_row = (uint32_t)(wn * 48 + (lane & 7));
    const uint32_t b_colb = (uint32_t)(((lane >> 3) & 1) * 16);

#pragma unroll
    for (int kstep = 0; kstep < 4; kstep++) {
        uint32_t a[2][4];
#pragma unroll
        for (int mi = 0; mi < 2; mi++)
            ldsm_x4(a[mi][0], a[mi][1], a[mi][2], a[mi][3],
                    qh_base + (a_row + mi * 16) * 144 + kstep * 32 + a_colb);
        uint32_t bf[6][2];
#pragma unroll
        for (int ni = 0; ni < 6; ni++)
            ldsm_x2(bf[ni][0], bf[ni][1],
                    kh_base + (b_row + ni * 8) * 144 + kstep * 32 + b_colb);
#pragma unroll
        for (int mi = 0; mi < 2; mi++)
#pragma unroll
            for (int ni = 0; ni < 6; ni++)
                mma16816(c[mi][ni], a[mi], bf[ni]);
    }

    // ---- mask + row max ----
    const float scale = 0.125f;
    float mx[2][2] = { {-1e30f,-1e30f}, {-1e30f,-1e30f} };
#pragma unroll
    for (int mi = 0; mi < 2; mi++)
#pragma unroll
        for (int hh = 0; hh < 2; hh++) {
            int qg = q0 + wm*32 + mi*16 + g + hh*8;
#pragma unroll
            for (int ni = 0; ni < 6; ni++)
#pragma unroll
                for (int cc = 0; cc < 2; cc++) {
                    int kk = wn*48 + ni*8 + 2*t + cc;
                    int kg = ks + kk;
                    bool ok = (Ms[kk] != 0) && (abs(qg - kg) <= WIN);
                    float v = ok ? c[mi][ni][hh*2+cc] * scale : -1e30f;
                    c[mi][ni][hh*2+cc] = v;
                    mx[mi][hh] = fmaxf(mx[mi][hh], v);
                }
        }
#pragma unroll
    for (int mi = 0; mi < 2; mi++)
#pragma unroll
        for (int hh = 0; hh < 2; hh++) {
            float m = mx[mi][hh];
            m = fmaxf(m, __shfl_xor_sync(0xffffffffu, m, 1));
            m = fmaxf(m, __shfl_xor_sync(0xffffffffu, m, 2));
            mx[mi][hh] = m;
        }
    if (t == 0) {
#pragma unroll
        for (int mi = 0; mi < 2; mi++)
#pragma unroll
            for (int hh = 0; hh < 2; hh++)
                pmax[wn*64 + wm*32 + mi*16 + g + hh*8] = mx[mi][hh];
    }
    // Barrier publishes pmax AND retires all Qh reads -> Ph may overwrite.
    __syncthreads();

    // ---- exp + row sum, write Ph (fp16, aliases Qh) ----
    float sum[2][2] = { {0.f,0.f}, {0.f,0.f} };
#pragma unroll
    for (int mi = 0; mi < 2; mi++)
#pragma unroll
        for (int hh = 0; hh < 2; hh++) {
            int row = wm*32 + mi*16 + g + hh*8;
            float gm = fmaxf(fmaxf(pmax[row], pmax[64+row]),
                             fmaxf(pmax[128+row], pmax[192+row]));
#pragma unroll
            for (int ni = 0; ni < 6; ni++) {
                float e0 = __expf(c[mi][ni][hh*2+0] - gm);
                float e1 = __expf(c[mi][ni][hh*2+1] - gm);
                sum[mi][hh] += e0 + e1;
                *(uint32_t*)(Ph + row*200 + wn*48 + ni*8 + 2*t) =
                    packh2(__float2half_rn(e0), __float2half_rn(e1));
            }
        }
#pragma unroll
    for (int mi = 0; mi < 2; mi++)
#pragma unroll
        for (int hh = 0; hh < 2; hh++) {
            float s = sum[mi][hh];
            s += __shfl_xor_sync(0xffffffffu, s, 1);
            s += __shfl_xor_sync(0xffffffffu, s, 2);
            sum[mi][hh] = s;
        }
    if (t == 0) {
#pragma unroll
        for (int mi = 0; mi < 2; mi++)
#pragma unroll
            for (int hh = 0; hh < 2; hh++)
                psum[wn*64 + wm*32 + mi*16 + g + hh*8] = sum[mi][hh];
    }
    __syncthreads();

    // ---- PV on HMMA: warp tile 32(q) x 16(d), K-dim 192 ----
    const int wm2 = warp & 1;      // q half
    const int wn2 = warp >> 1;     // d quarter (16 cols)
    const uint32_t ph_base  = smem_u32(Ph);

    float o[2][2][4];
#pragma unroll
    for (int mi = 0; mi < 2; mi++)
#pragma unroll
        for (int ni = 0; ni < 2; ni++)
#pragma unroll
            for (int r = 0; r < 4; r++) o[mi][ni][r] = 0.f;

    const uint32_t pa_row  = (uint32_t)(wm2 * 32 + (lane & 15));
    const uint32_t pa_colb = (uint32_t)((lane >> 4) * 16);
    const uint32_t v_lane  = (uint32_t)(lane & 15);          // k row within 16

#pragma unroll
    for (int ks2 = 0; ks2 < 12; ks2++) {
        uint32_t a[2][4];
#pragma unroll
        for (int mi = 0; mi < 2; mi++)
            ldsm_x4(a[mi][0], a[mi][1], a[mi][2], a[mi][3],
                    ph_base + (pa_row + mi * 16) * 400 + ks2 * 32 + pa_colb);
        uint32_t bh[2][2];
#pragma unroll
        for (int ni = 0; ni < 2; ni++) {
            uint32_t off = (ks2 * 16 + v_lane) * 144 + (wn2 * 16 + ni * 8) * 2;
            ldsm_x2t(bh[ni][0], bh[ni][1], vhi_smem + off);
        }
#pragma unroll
        for (int mi = 0; mi < 2; mi++)
#pragma unroll
            for (int ni = 0; ni < 2; ni++)
                mma16816(o[mi][ni], a[mi], bh[ni]);
    }

    // ---- epilogue: normalize + write fp16 operand for Wo GEMM ----
#pragma unroll
    for (int mi = 0; mi < 2; mi++)
#pragma unroll
        for (int hh = 0; hh < 2; hh++) {
            int qq = wm2*32 + mi*16 + g + hh*8;
            float tot = psum[qq] + psum[64+qq] + psum[128+qq] + psum[192+qq];
            float r = 1.f / fmaxf(tot, 1e-30f);
#pragma unroll
            for (int ni = 0; ni < 2; ni++) {
                int d = wn2*16 + ni*8 + 2*t;
                uint32_t pair = packh2(__float2half_rn(o[mi][ni][hh*2+0] * r),
                                       __float2half_rn(o[mi][ni][hh*2+1] * r));
                *(uint32_t*)(attnx + (size_t)(b*TT + q0 + qq) * KK + h*HD + d) = pair;
            }
        }
}

// ---------------------------------------------------------------------------
extern "C" void kernel_launch(void* const* d_in, const int* in_sizes, int n_in,
                              void* d_out, int out_size)
{
    const float* hs   = (const float*)d_in[0];
    const int*   am   = (const int*)d_in[1];
    const float* Wqkv = (const float*)d_in[2];
    const float* Wo   = (const float*)d_in[3];
    float* out = (float*)d_out;

    void* p;
    cudaGetSymbolAddress(&p, g_qkvh);  __half* qkvh  = (__half*)p;
    cudaGetSymbolAddress(&p, g_ah);    __half* ah    = (__half*)p;
    cudaGetSymbolAddress(&p, g_attnx); __half* attnx = (__half*)p;
    cudaGetSymbolAddress(&p, g_wqkvh); __half* wqkvh = (__half*)p;
    cudaGetSymbolAddress(&p, g_woh);   __half* woh   = (__half*)p;
    cudaGetSymbolAddress(&p, g_tab);   float*  tab   = (float*)p;

    cudaFuncSetAttribute(attn_kernel,
                         cudaFuncAttributeMaxDynamicSharedMemorySize,
                         ATTN_SMEM_BYTES);
    cudaFuncSetAttribute(gemm_mma<true>,
                         cudaFuncAttributeMaxDynamicSharedMemorySize,
                         GEMM_SMEM);
    cudaFuncSetAttribute(gemm_mma<false>,
                         cudaFuncAttributeMaxDynamicSharedMemorySize,
                         GEMM_SMEM);

    const int M = BB * TT;                 // 8192

    // 1) fp32 -> fp16: weights + hidden states
    conv_all<<<((TD3*DD + DD*DD + M*DD)/4 + 255)/256, 256>>>(
        Wqkv, Wo, hs, wqkvh, woh, ah);

    // 2) rope table
    tab_kernel<<<(TT*32)/256, 256>>>(tab);

    // 3) QKV projection (fp16 output)
    gemm_mma<true><<<dim3(TD3/128, M/128), 256, GEMM_SMEM>>>(ah, wqkvh, qkvh, TD3);

    // 4) attention (fp16 qkv; HMMA scores + HMMA PV; cp.async V)
    dim3 ga(TT/64, NH, BB);
    attn_kernel<<<ga, 256, ATTN_SMEM_BYTES>>>(qkvh, am, tab, attnx);

    // 5) output projection (fp32 output)
    gemm_mma<false><<<dim3(DD/128, M/128), 256, GEMM_SMEM>>>(attnx, woh, out, DD);
}